// round 3
// baseline (speedup 1.0000x reference)
#include <cuda_runtime.h>
#include <cuda_bf16.h>
#include <math.h>

#define B_SZ 2
#define S_SZ 2048
#define D_SZ 2048
#define F_SZ 8192
#define H_SZ 16
#define HD   128
#define MROWS (B_SZ * S_SZ)   // 4096

// ---------------- scratch (device globals; no allocation) ----------------
__device__ float g_xn  [MROWS * D_SZ];
__device__ float g_q   [MROWS * D_SZ];
__device__ float g_k   [MROWS * D_SZ];
__device__ float g_v   [MROWS * D_SZ];
__device__ float g_attn[MROWS * D_SZ];
__device__ float g_h   [MROWS * D_SZ];
__device__ float g_mlp [MROWS * F_SZ];

// ---------------- hypersphere norm: out = x/(||x||+eps)*sqrt(D)*g ----------------
__global__ void hnorm_kernel(const float* __restrict__ x, const float* __restrict__ g,
                             float* __restrict__ out) {
    const int row = blockIdx.x;
    const float* xr = x + (size_t)row * D_SZ;
    float ss = 0.f;
    for (int i = threadIdx.x; i < D_SZ; i += blockDim.x) {
        float v = xr[i];
        ss += v * v;
    }
    __shared__ float red[32];
    #pragma unroll
    for (int o = 16; o; o >>= 1) ss += __shfl_xor_sync(0xffffffffu, ss, o);
    if ((threadIdx.x & 31) == 0) red[threadIdx.x >> 5] = ss;
    __syncthreads();
    if (threadIdx.x < 32) {
        float v = (threadIdx.x < (blockDim.x >> 5)) ? red[threadIdx.x] : 0.f;
        #pragma unroll
        for (int o = 16; o; o >>= 1) v += __shfl_xor_sync(0xffffffffu, v, o);
        if (threadIdx.x == 0) red[0] = v;
    }
    __syncthreads();
    const float n = sqrtf(red[0]);
    const float scale = 45.254833995939045f / (n + 1e-6f);  // sqrt(2048)
    float* orow = out + (size_t)row * D_SZ;
    for (int i = threadIdx.x; i < D_SZ; i += blockDim.x)
        orow[i] = xr[i] * scale * g[i];
}

// ---------------- QK-norm: unit-normalize each 128-dim head vector ----------------
__global__ void qknorm_kernel(float* __restrict__ q) {
    const int vec = blockIdx.x * (blockDim.x >> 5) + (threadIdx.x >> 5);
    const int lane = threadIdx.x & 31;
    float* p = q + (size_t)vec * HD;  // [row][h*128+d] contiguous per (row,h)
    float4 v = ((float4*)p)[lane];
    float ss = v.x * v.x + v.y * v.y + v.z * v.z + v.w * v.w;
    #pragma unroll
    for (int o = 16; o; o >>= 1) ss += __shfl_xor_sync(0xffffffffu, ss, o);
    const float s = 1.f / (sqrtf(ss) + 1e-6f);
    v.x *= s; v.y *= s; v.z *= s; v.w *= s;
    ((float4*)p)[lane] = v;
}

// ---------------- GEMM: C[M,N] = A[M,K] @ W[N,K]^T (+epilogue) ----------------
// EPI: 0=none, 1=exact GELU, 2=residual add (C = R + A@W^T)
__device__ __forceinline__ float gelu_exact(float x) {
    return 0.5f * x * (1.f + erff(x * 0.7071067811865476f));
}

template <int EPI>
__global__ void __launch_bounds__(256, 2)
gemm_tn(const float* __restrict__ A, const float* __restrict__ W,
        const float* __restrict__ R, float* __restrict__ C,
        int M, int N, int K) {
    __shared__ float As[16][132];
    __shared__ float Bs[16][132];

    const int bm = blockIdx.y * 128;
    const int bn = blockIdx.x * 128;
    const int tid = threadIdx.x;
    const int tx = tid & 15, ty = tid >> 4;

    const float* Ab = A + (size_t)bm * K;
    const float* Wb = W + (size_t)bn * K;

    const int lrow = tid >> 2;          // 0..63
    const int lk   = (tid & 3) << 2;    // 0,4,8,12

    float acc[8][8];
    #pragma unroll
    for (int i = 0; i < 8; i++)
        #pragma unroll
        for (int j = 0; j < 8; j++) acc[i][j] = 0.f;

    for (int k0 = 0; k0 < K; k0 += 16) {
        #pragma unroll
        for (int hh = 0; hh < 2; hh++) {
            const int r = lrow + hh * 64;
            float4 a = *(const float4*)(Ab + (size_t)r * K + k0 + lk);
            As[lk + 0][r] = a.x; As[lk + 1][r] = a.y;
            As[lk + 2][r] = a.z; As[lk + 3][r] = a.w;
            float4 b = *(const float4*)(Wb + (size_t)r * K + k0 + lk);
            Bs[lk + 0][r] = b.x; Bs[lk + 1][r] = b.y;
            Bs[lk + 2][r] = b.z; Bs[lk + 3][r] = b.w;
        }
        __syncthreads();
        #pragma unroll
        for (int kk = 0; kk < 16; kk++) {
            float a[8], b[8];
            *(float4*)(a + 0) = *(float4*)&As[kk][ty * 8 + 0];
            *(float4*)(a + 4) = *(float4*)&As[kk][ty * 8 + 4];
            *(float4*)(b + 0) = *(float4*)&Bs[kk][tx * 8 + 0];
            *(float4*)(b + 4) = *(float4*)&Bs[kk][tx * 8 + 4];
            #pragma unroll
            for (int i = 0; i < 8; i++)
                #pragma unroll
                for (int j = 0; j < 8; j++)
                    acc[i][j] = fmaf(a[i], b[j], acc[i][j]);
        }
        __syncthreads();
    }

    #pragma unroll
    for (int i = 0; i < 8; i++) {
        const int row = bm + ty * 8 + i;
        float* crow = C + (size_t)row * N + bn + tx * 8;
        const float* rrow = (EPI == 2) ? (R + (size_t)row * N + bn + tx * 8) : nullptr;
        float v[8];
        #pragma unroll
        for (int j = 0; j < 8; j++) {
            float t = acc[i][j];
            if (EPI == 2) t += rrow[j];
            if (EPI == 1) t = gelu_exact(t);
            v[j] = t;
        }
        *(float4*)(crow + 0) = *(float4*)(v + 0);
        *(float4*)(crow + 4) = *(float4*)(v + 4);
    }
}

// ---------------- Flash attention (fp32, causal, online softmax) ----------------
// grid: x = q-tile (S/64 = 32), y = b*H+h (32). 256 threads.
// Row stride 132 floats = 528 bytes (16B-aligned so float4 smem ops are legal).
#define QKV_LD 132
#define S_LD   68
#define FLASH_SMEM ((3 * 64 * QKV_LD + 64 * S_LD + 128) * 4)

__global__ void __launch_bounds__(256, 1)
flash_kernel(const float* __restrict__ Q, const float* __restrict__ K,
             const float* __restrict__ V, const float* __restrict__ scale_p,
             float* __restrict__ O) {
    extern __shared__ float sm[];
    float (*sQ)[QKV_LD] = (float(*)[QKV_LD])sm;
    float (*sK)[QKV_LD] = (float(*)[QKV_LD])(sm + 64 * QKV_LD);
    float (*sV)[QKV_LD] = (float(*)[QKV_LD])(sm + 2 * 64 * QKV_LD);
    float (*sS)[S_LD]   = (float(*)[S_LD]) (sm + 3 * 64 * QKV_LD);
    float* sAlpha = sm + 3 * 64 * QKV_LD + 64 * S_LD;
    float* sLinv  = sAlpha + 64;

    const int qt = blockIdx.x;
    const int bh = blockIdx.y;
    const int b = bh >> 4, h = bh & 15;
    const float scale = *scale_p;
    const int tid = threadIdx.x;
    const int tx = tid & 15, ty = tid >> 4;

    const size_t base = (size_t)b * S_SZ * D_SZ + (size_t)h * HD;
    const float* Qb = Q + base;
    const float* Kb = K + base;
    const float* Vb = V + base;

    // load Q tile (rows qt*64 .. +63)
    {
        const int c4 = tid & 31;       // float4 col index (32 per row)
        const int r0 = tid >> 5;       // 0..7
        #pragma unroll
        for (int i = 0; i < 8; i++) {
            const int r = r0 + i * 8;
            float4 t = *(const float4*)(Qb + (size_t)(qt * 64 + r) * D_SZ + c4 * 4);
            *(float4*)&sQ[r][c4 * 4] = t;
        }
    }

    float o[4][8];
    #pragma unroll
    for (int i = 0; i < 4; i++)
        #pragma unroll
        for (int j = 0; j < 8; j++) o[i][j] = 0.f;

    float m_run = -INFINITY, l_run = 0.f;  // valid in row-owner threads (tid < 64)

    for (int kt = 0; kt <= qt; kt++) {
        __syncthreads();  // prior iteration done with sK/sV/sS
        {
            const int c4 = tid & 31;
            const int r0 = tid >> 5;
            #pragma unroll
            for (int i = 0; i < 8; i++) {
                const int r = r0 + i * 8;
                float4 tk = *(const float4*)(Kb + (size_t)(kt * 64 + r) * D_SZ + c4 * 4);
                *(float4*)&sK[r][c4 * 4] = tk;
                float4 tv = *(const float4*)(Vb + (size_t)(kt * 64 + r) * D_SZ + c4 * 4);
                *(float4*)&sV[r][c4 * 4] = tv;
            }
        }
        __syncthreads();

        // S = Q @ K^T (4x4 micro-tile per thread)
        float acc[4][4];
        #pragma unroll
        for (int i = 0; i < 4; i++)
            #pragma unroll
            for (int j = 0; j < 4; j++) acc[i][j] = 0.f;

        for (int d = 0; d < HD; d += 4) {
            float4 a[4], bq[4];
            #pragma unroll
            for (int i = 0; i < 4; i++) a[i]  = *(float4*)&sQ[ty * 4 + i][d];
            #pragma unroll
            for (int j = 0; j < 4; j++) bq[j] = *(float4*)&sK[tx * 4 + j][d];
            #pragma unroll
            for (int i = 0; i < 4; i++)
                #pragma unroll
                for (int j = 0; j < 4; j++) {
                    acc[i][j] = fmaf(a[i].x, bq[j].x, acc[i][j]);
                    acc[i][j] = fmaf(a[i].y, bq[j].y, acc[i][j]);
                    acc[i][j] = fmaf(a[i].z, bq[j].z, acc[i][j]);
                    acc[i][j] = fmaf(a[i].w, bq[j].w, acc[i][j]);
                }
        }

        const int qbase = qt * 64, kbase = kt * 64;
        #pragma unroll
        for (int i = 0; i < 4; i++)
            #pragma unroll
            for (int j = 0; j < 4; j++) {
                float s = acc[i][j] * scale;
                if (kbase + tx * 4 + j > qbase + ty * 4 + i) s = -INFINITY;
                sS[ty * 4 + i][tx * 4 + j] = s;
            }
        __syncthreads();

        // online softmax update (row owners)
        if (tid < 64) {
            const int r = tid;
            float mt = -INFINITY;
            #pragma unroll 8
            for (int c = 0; c < 64; c++) mt = fmaxf(mt, sS[r][c]);
            const float mnew = fmaxf(m_run, mt);
            const float alpha = (m_run == -INFINITY) ? 0.f : __expf(m_run - mnew);
            float sum = 0.f;
            #pragma unroll 8
            for (int c = 0; c < 64; c++) {
                float p = __expf(sS[r][c] - mnew);
                sS[r][c] = p;
                sum += p;
            }
            l_run = l_run * alpha + sum;
            m_run = mnew;
            sAlpha[r] = alpha;
        }
        __syncthreads();

        // rescale existing O and accumulate P @ V
        float al[4];
        #pragma unroll
        for (int i = 0; i < 4; i++) al[i] = sAlpha[ty * 4 + i];
        #pragma unroll
        for (int i = 0; i < 4; i++)
            #pragma unroll
            for (int j = 0; j < 8; j++) o[i][j] *= al[i];

        for (int kk = 0; kk < 64; kk++) {
            float p[4];
            #pragma unroll
            for (int i = 0; i < 4; i++) p[i] = sS[ty * 4 + i][kk];
            float vv[8];
            *(float4*)(vv + 0) = *(float4*)&sV[kk][tx * 8 + 0];
            *(float4*)(vv + 4) = *(float4*)&sV[kk][tx * 8 + 4];
            #pragma unroll
            for (int i = 0; i < 4; i++)
                #pragma unroll
                for (int j = 0; j < 8; j++)
                    o[i][j] = fmaf(p[i], vv[j], o[i][j]);
        }
    }

    if (tid < 64) sLinv[tid] = 1.f / l_run;
    __syncthreads();

    float li[4];
    #pragma unroll
    for (int i = 0; i < 4; i++) li[i] = sLinv[ty * 4 + i];
    #pragma unroll
    for (int i = 0; i < 4; i++) {
        const int srow = qt * 64 + ty * 4 + i;
        float* orow = O + (size_t)(b * S_SZ + srow) * D_SZ + h * HD + tx * 8;
        float v[8];
        #pragma unroll
        for (int j = 0; j < 8; j++) v[j] = o[i][j] * li[i];
        *(float4*)(orow + 0) = *(float4*)(v + 0);
        *(float4*)(orow + 4) = *(float4*)(v + 4);
    }
}

// ---------------- driver ----------------
extern "C" void kernel_launch(void* const* d_in, const int* in_sizes, int n_in,
                              void* d_out, int out_size) {
    const float* hs    = (const float*)d_in[0];
    const float* Wq    = (const float*)d_in[1];
    const float* Wk    = (const float*)d_in[2];
    const float* Wv    = (const float*)d_in[3];
    const float* Wo    = (const float*)d_in[4];
    const float* Win   = (const float*)d_in[5];
    const float* Wout  = (const float*)d_in[6];
    const float* qkf   = (const float*)d_in[7];
    const float* gattn = (const float*)d_in[8];
    const float* gmlp  = (const float*)d_in[9];
    float* out = (float*)d_out;

    float *xn, *q, *k, *v, *attn, *h, *mlp;
    cudaGetSymbolAddress((void**)&xn,   g_xn);
    cudaGetSymbolAddress((void**)&q,    g_q);
    cudaGetSymbolAddress((void**)&k,    g_k);
    cudaGetSymbolAddress((void**)&v,    g_v);
    cudaGetSymbolAddress((void**)&attn, g_attn);
    cudaGetSymbolAddress((void**)&h,    g_h);
    cudaGetSymbolAddress((void**)&mlp,  g_mlp);

    cudaFuncSetAttribute(flash_kernel, cudaFuncAttributeMaxDynamicSharedMemorySize,
                         FLASH_SMEM);

    // 1) pre-attn hypersphere norm
    hnorm_kernel<<<MROWS, 256>>>(hs, gattn, xn);

    // 2) QKV projections
    dim3 gqkv(D_SZ / 128, MROWS / 128);
    gemm_tn<0><<<gqkv, 256>>>(xn, Wq, nullptr, q, MROWS, D_SZ, D_SZ);
    gemm_tn<0><<<gqkv, 256>>>(xn, Wk, nullptr, k, MROWS, D_SZ, D_SZ);
    gemm_tn<0><<<gqkv, 256>>>(xn, Wv, nullptr, v, MROWS, D_SZ, D_SZ);

    // 3) QK-norm (unit-normalize per head vector)
    const int nvec = MROWS * H_SZ;                 // 65536
    qknorm_kernel<<<nvec / 8, 256>>>(q);
    qknorm_kernel<<<nvec / 8, 256>>>(k);

    // 4) causal attention
    flash_kernel<<<dim3(S_SZ / 64, B_SZ * H_SZ), 256, FLASH_SMEM>>>(q, k, v, qkf, attn);

    // 5) output projection + residual: h = hs + attn @ Wo^T
    gemm_tn<2><<<gqkv, 256>>>(attn, Wo, hs, h, MROWS, D_SZ, D_SZ);

    // 6) pre-MLP hypersphere norm
    hnorm_kernel<<<MROWS, 256>>>(h, gmlp, xn);

    // 7) MLP in + exact GELU
    gemm_tn<1><<<dim3(F_SZ / 128, MROWS / 128), 256>>>(xn, Win, nullptr, mlp,
                                                       MROWS, F_SZ, D_SZ);

    // 8) MLP out + residual -> d_out
    gemm_tn<2><<<gqkv, 256>>>(mlp, Wout, h, out, MROWS, D_SZ, F_SZ);
}

// round 5
// speedup vs baseline: 1.6792x; 1.6792x over previous
#include <cuda_runtime.h>
#include <cuda_bf16.h>
#include <math.h>
#include <stdint.h>

#define B_SZ 2
#define S_SZ 2048
#define D_SZ 2048
#define F_SZ 8192
#define H_SZ 16
#define HD   128
#define MROWS (B_SZ * S_SZ)   // 4096

// ---------------- scratch (device globals; no allocation) ----------------
__device__ float g_xn  [MROWS * D_SZ];
__device__ float g_q   [MROWS * D_SZ];
__device__ float g_k   [MROWS * D_SZ];
__device__ float g_v   [MROWS * D_SZ];
__device__ float g_attn[MROWS * D_SZ];
__device__ float g_h   [MROWS * D_SZ];
__device__ float g_mlp [MROWS * F_SZ];

// ==================== helpers ====================
__device__ __forceinline__ uint32_t f2tf32(float x) {
    uint32_t r;
    asm("cvt.rna.tf32.f32 %0, %1;" : "=r"(r) : "f"(x));
    return r;
}
__device__ __forceinline__ void mma_tf32(float* d, const uint32_t* a, const uint32_t* b) {
    asm volatile(
        "mma.sync.aligned.m16n8k8.row.col.f32.tf32.tf32.f32 "
        "{%0,%1,%2,%3}, {%4,%5,%6,%7}, {%8,%9}, {%0,%1,%2,%3};"
        : "+f"(d[0]), "+f"(d[1]), "+f"(d[2]), "+f"(d[3])
        : "r"(a[0]), "r"(a[1]), "r"(a[2]), "r"(a[3]), "r"(b[0]), "r"(b[1]));
}
__device__ __forceinline__ float gelu_exact(float x) {
    return 0.5f * x * (1.f + erff(x * 0.7071067811865476f));
}

// ==================== tf32 mma.sync GEMM ====================
// C[M,N] = A[M,K] @ W[N,K]^T (+epilogue).
// CTA tile 128x128, BK=32, 256 threads = 8 warps (2 m x 4 n), warp tile 64x32.
// Smem holds tiles pre-permuted into m16n8k8 fragment order:
//   Afrag[s(4)][m_atom(8)][lane(32)][reg(4)]  (4096 floats)
//   Bfrag[s(4)][n_atom(16)][lane(32)][reg(2)] (4096 floats)
// Double buffered: stage stride 8192 floats (32KB). Total 64KB dynamic smem.
#define GBM 128
#define GBN 128
#define GBK 32
#define STG_FLOATS 8192
#define GEMM_SMEM (2 * STG_FLOATS * 4)

// EPI: 0=none, 1=exact GELU, 2=residual add
template <int EPI>
__global__ void __launch_bounds__(256, 1)
gemm_mma(const float* __restrict__ A, const float* __restrict__ W,
         const float* __restrict__ R, float* __restrict__ C, int N, int K) {
    extern __shared__ float sm[];
    const int tid = threadIdx.x;
    const int lane = tid & 31;
    const int wid = tid >> 5;
    const int wm = wid >> 2;          // 0..1
    const int wn = wid & 3;           // 0..3
    const int bm = blockIdx.x * GBM;
    const int bn = blockIdx.y * GBN;

    const int r0 = tid >> 3;          // 0..31 (row group for gmem loads)
    const int c4 = tid & 7;           // float4 col within 32-wide K slice
    const int s_idx = c4 >> 1;        // k8 sub-tile 0..3
    const int creg = c4 & 1;          // high half of k8 (cols 4..7)

    float acc[4][4][4];
    #pragma unroll
    for (int i = 0; i < 4; i++)
        #pragma unroll
        for (int j = 0; j < 4; j++)
            #pragma unroll
            for (int r = 0; r < 4; r++) acc[i][j][r] = 0.f;

    float4 ra[4], rb[4];
    const int NT = K / GBK;

    // ---- load tile 0 ----
    #pragma unroll
    for (int i = 0; i < 4; i++) {
        ra[i] = *(const float4*)(A + (size_t)(bm + r0 + 32 * i) * K + c4 * 4);
        rb[i] = *(const float4*)(W + (size_t)(bn + r0 + 32 * i) * K + c4 * 4);
    }
    // ---- store tile 0 into stage 0 (fragment order) ----
    {
        float* smA = sm;
        float* smB = sm + 4096;
        #pragma unroll
        for (int i = 0; i < 4; i++) {
            const int r = r0 + 32 * i;
            const int ma = r >> 4, rr = r & 15;
            float* da = smA + (((s_idx * 8 + ma) * 32 + (rr & 7) * 4) << 2) + ((rr >> 3) + 2 * creg);
            da[0]  = __uint_as_float(f2tf32(ra[i].x));
            da[4]  = __uint_as_float(f2tf32(ra[i].y));
            da[8]  = __uint_as_float(f2tf32(ra[i].z));
            da[12] = __uint_as_float(f2tf32(ra[i].w));
            const int na = r >> 3, nn = r & 7;
            float* db = smB + (((s_idx * 16 + na) * 32 + nn * 4) << 1) + creg;
            db[0] = __uint_as_float(f2tf32(rb[i].x));
            db[2] = __uint_as_float(f2tf32(rb[i].y));
            db[4] = __uint_as_float(f2tf32(rb[i].z));
            db[6] = __uint_as_float(f2tf32(rb[i].w));
        }
    }
    __syncthreads();

    for (int kt = 0; kt < NT; kt++) {
        const int cur = kt & 1;
        // prefetch next tile into regs
        if (kt + 1 < NT) {
            const int ko = (kt + 1) * GBK;
            #pragma unroll
            for (int i = 0; i < 4; i++) {
                ra[i] = *(const float4*)(A + (size_t)(bm + r0 + 32 * i) * K + ko + c4 * 4);
                rb[i] = *(const float4*)(W + (size_t)(bn + r0 + 32 * i) * K + ko + c4 * 4);
            }
        }
        // compute current stage
        {
            const float* smA = sm + cur * STG_FLOATS;
            const float* smB = smA + 4096;
            #pragma unroll
            for (int s = 0; s < 4; s++) {
                uint32_t af[4][4];
                #pragma unroll
                for (int i = 0; i < 4; i++)
                    *(uint4*)af[i] = *(const uint4*)(smA + (((s * 8 + wm * 4 + i) * 32 + lane) << 2));
                uint32_t bf[4][2];
                #pragma unroll
                for (int j = 0; j < 4; j++)
                    *(uint2*)bf[j] = *(const uint2*)(smB + (((s * 16 + wn * 4 + j) * 32 + lane) << 1));
                #pragma unroll
                for (int i = 0; i < 4; i++)
                    #pragma unroll
                    for (int j = 0; j < 4; j++)
                        mma_tf32(acc[i][j], af[i], bf[j]);
            }
        }
        // store next stage
        if (kt + 1 < NT) {
            float* smA = sm + ((kt + 1) & 1) * STG_FLOATS;
            float* smB = smA + 4096;
            #pragma unroll
            for (int i = 0; i < 4; i++) {
                const int r = r0 + 32 * i;
                const int ma = r >> 4, rr = r & 15;
                float* da = smA + (((s_idx * 8 + ma) * 32 + (rr & 7) * 4) << 2) + ((rr >> 3) + 2 * creg);
                da[0]  = __uint_as_float(f2tf32(ra[i].x));
                da[4]  = __uint_as_float(f2tf32(ra[i].y));
                da[8]  = __uint_as_float(f2tf32(ra[i].z));
                da[12] = __uint_as_float(f2tf32(ra[i].w));
                const int na = r >> 3, nn = r & 7;
                float* db = smB + (((s_idx * 16 + na) * 32 + nn * 4) << 1) + creg;
                db[0] = __uint_as_float(f2tf32(rb[i].x));
                db[2] = __uint_as_float(f2tf32(rb[i].y));
                db[4] = __uint_as_float(f2tf32(rb[i].z));
                db[6] = __uint_as_float(f2tf32(rb[i].w));
            }
            __syncthreads();
        }
    }

    // ---- epilogue ----
    const int gid = lane >> 2, tig = lane & 3;
    #pragma unroll
    for (int i = 0; i < 4; i++) {
        #pragma unroll
        for (int j = 0; j < 4; j++) {
            const int row0 = bm + wm * 64 + i * 16 + gid;
            const int col  = bn + wn * 32 + j * 8 + tig * 2;
            float2 v0 = {acc[i][j][0], acc[i][j][1]};
            float2 v1 = {acc[i][j][2], acc[i][j][3]};
            if (EPI == 2) {
                float2 q0 = *(const float2*)(R + (size_t)row0 * N + col);
                float2 q1 = *(const float2*)(R + (size_t)(row0 + 8) * N + col);
                v0.x += q0.x; v0.y += q0.y;
                v1.x += q1.x; v1.y += q1.y;
            }
            if (EPI == 1) {
                v0.x = gelu_exact(v0.x); v0.y = gelu_exact(v0.y);
                v1.x = gelu_exact(v1.x); v1.y = gelu_exact(v1.y);
            }
            *(float2*)(C + (size_t)row0 * N + col) = v0;
            *(float2*)(C + (size_t)(row0 + 8) * N + col) = v1;
        }
    }
}

// ---------------- hypersphere norm ----------------
__global__ void hnorm_kernel(const float* __restrict__ x, const float* __restrict__ g,
                             float* __restrict__ out) {
    const int row = blockIdx.x;
    const float* xr = x + (size_t)row * D_SZ;
    float ss = 0.f;
    for (int i = threadIdx.x; i < D_SZ; i += blockDim.x) {
        float v = xr[i];
        ss += v * v;
    }
    __shared__ float red[32];
    #pragma unroll
    for (int o = 16; o; o >>= 1) ss += __shfl_xor_sync(0xffffffffu, ss, o);
    if ((threadIdx.x & 31) == 0) red[threadIdx.x >> 5] = ss;
    __syncthreads();
    if (threadIdx.x < 32) {
        float v = (threadIdx.x < (blockDim.x >> 5)) ? red[threadIdx.x] : 0.f;
        #pragma unroll
        for (int o = 16; o; o >>= 1) v += __shfl_xor_sync(0xffffffffu, v, o);
        if (threadIdx.x == 0) red[0] = v;
    }
    __syncthreads();
    const float n = sqrtf(red[0]);
    const float scale = 45.254833995939045f / (n + 1e-6f);
    float* orow = out + (size_t)row * D_SZ;
    for (int i = threadIdx.x; i < D_SZ; i += blockDim.x)
        orow[i] = xr[i] * scale * g[i];
}

// ---------------- QK-norm ----------------
__global__ void qknorm_kernel(float* __restrict__ q) {
    const int vec = blockIdx.x * (blockDim.x >> 5) + (threadIdx.x >> 5);
    const int lane = threadIdx.x & 31;
    float* p = q + (size_t)vec * HD;
    float4 v = ((float4*)p)[lane];
    float ss = v.x * v.x + v.y * v.y + v.z * v.z + v.w * v.w;
    #pragma unroll
    for (int o = 16; o; o >>= 1) ss += __shfl_xor_sync(0xffffffffu, ss, o);
    const float s = 1.f / (sqrtf(ss) + 1e-6f);
    v.x *= s; v.y *= s; v.z *= s; v.w *= s;
    ((float4*)p)[lane] = v;
}

// ---------------- Flash attention (fp32, causal, online softmax) ----------------
#define QKV_LD 132
#define S_LD   68
#define FLASH_SMEM ((3 * 64 * QKV_LD + 64 * S_LD + 128) * 4)

__global__ void __launch_bounds__(256, 1)
flash_kernel(const float* __restrict__ Q, const float* __restrict__ K,
             const float* __restrict__ V, const float* __restrict__ scale_p,
             float* __restrict__ O) {
    extern __shared__ float smf[];
    float (*sQ)[QKV_LD] = (float(*)[QKV_LD])smf;
    float (*sK)[QKV_LD] = (float(*)[QKV_LD])(smf + 64 * QKV_LD);
    float (*sV)[QKV_LD] = (float(*)[QKV_LD])(smf + 2 * 64 * QKV_LD);
    float (*sS)[S_LD]   = (float(*)[S_LD]) (smf + 3 * 64 * QKV_LD);
    float* sAlpha = smf + 3 * 64 * QKV_LD + 64 * S_LD;
    float* sLinv  = sAlpha + 64;

    const int qt = blockIdx.x;
    const int bh = blockIdx.y;
    const int b = bh >> 4, h = bh & 15;
    const float scale = *scale_p;
    const int tid = threadIdx.x;
    const int tx = tid & 15, ty = tid >> 4;

    const size_t base = (size_t)b * S_SZ * D_SZ + (size_t)h * HD;
    const float* Qb = Q + base;
    const float* Kb = K + base;
    const float* Vb = V + base;

    {
        const int c4 = tid & 31;
        const int r0 = tid >> 5;
        #pragma unroll
        for (int i = 0; i < 8; i++) {
            const int r = r0 + i * 8;
            float4 t = *(const float4*)(Qb + (size_t)(qt * 64 + r) * D_SZ + c4 * 4);
            *(float4*)&sQ[r][c4 * 4] = t;
        }
    }

    float o[4][8];
    #pragma unroll
    for (int i = 0; i < 4; i++)
        #pragma unroll
        for (int j = 0; j < 8; j++) o[i][j] = 0.f;

    float m_run = -INFINITY, l_run = 0.f;

    for (int kt = 0; kt <= qt; kt++) {
        __syncthreads();
        {
            const int c4 = tid & 31;
            const int r0 = tid >> 5;
            #pragma unroll
            for (int i = 0; i < 8; i++) {
                const int r = r0 + i * 8;
                float4 tk = *(const float4*)(Kb + (size_t)(kt * 64 + r) * D_SZ + c4 * 4);
                *(float4*)&sK[r][c4 * 4] = tk;
                float4 tv = *(const float4*)(Vb + (size_t)(kt * 64 + r) * D_SZ + c4 * 4);
                *(float4*)&sV[r][c4 * 4] = tv;
            }
        }
        __syncthreads();

        float acc[4][4];
        #pragma unroll
        for (int i = 0; i < 4; i++)
            #pragma unroll
            for (int j = 0; j < 4; j++) acc[i][j] = 0.f;

        for (int d = 0; d < HD; d += 4) {
            float4 a[4], bq[4];
            #pragma unroll
            for (int i = 0; i < 4; i++) a[i]  = *(float4*)&sQ[ty * 4 + i][d];
            #pragma unroll
            for (int j = 0; j < 4; j++) bq[j] = *(float4*)&sK[tx * 4 + j][d];
            #pragma unroll
            for (int i = 0; i < 4; i++)
                #pragma unroll
                for (int j = 0; j < 4; j++) {
                    acc[i][j] = fmaf(a[i].x, bq[j].x, acc[i][j]);
                    acc[i][j] = fmaf(a[i].y, bq[j].y, acc[i][j]);
                    acc[i][j] = fmaf(a[i].z, bq[j].z, acc[i][j]);
                    acc[i][j] = fmaf(a[i].w, bq[j].w, acc[i][j]);
                }
        }

        const int qbase = qt * 64, kbase = kt * 64;
        #pragma unroll
        for (int i = 0; i < 4; i++)
            #pragma unroll
            for (int j = 0; j < 4; j++) {
                float s = acc[i][j] * scale;
                if (kbase + tx * 4 + j > qbase + ty * 4 + i) s = -INFINITY;
                sS[ty * 4 + i][tx * 4 + j] = s;
            }
        __syncthreads();

        if (tid < 64) {
            const int r = tid;
            float mt = -INFINITY;
            #pragma unroll 8
            for (int c = 0; c < 64; c++) mt = fmaxf(mt, sS[r][c]);
            const float mnew = fmaxf(m_run, mt);
            const float alpha = (m_run == -INFINITY) ? 0.f : __expf(m_run - mnew);
            float sum = 0.f;
            #pragma unroll 8
            for (int c = 0; c < 64; c++) {
                float p = __expf(sS[r][c] - mnew);
                sS[r][c] = p;
                sum += p;
            }
            l_run = l_run * alpha + sum;
            m_run = mnew;
            sAlpha[r] = alpha;
        }
        __syncthreads();

        float al[4];
        #pragma unroll
        for (int i = 0; i < 4; i++) al[i] = sAlpha[ty * 4 + i];
        #pragma unroll
        for (int i = 0; i < 4; i++)
            #pragma unroll
            for (int j = 0; j < 8; j++) o[i][j] *= al[i];

        for (int kk = 0; kk < 64; kk++) {
            float p[4];
            #pragma unroll
            for (int i = 0; i < 4; i++) p[i] = sS[ty * 4 + i][kk];
            float vv[8];
            *(float4*)(vv + 0) = *(float4*)&sV[kk][tx * 8 + 0];
            *(float4*)(vv + 4) = *(float4*)&sV[kk][tx * 8 + 4];
            #pragma unroll
            for (int i = 0; i < 4; i++)
                #pragma unroll
                for (int j = 0; j < 8; j++)
                    o[i][j] = fmaf(p[i], vv[j], o[i][j]);
        }
    }

    if (tid < 64) sLinv[tid] = 1.f / l_run;
    __syncthreads();

    float li[4];
    #pragma unroll
    for (int i = 0; i < 4; i++) li[i] = sLinv[ty * 4 + i];
    #pragma unroll
    for (int i = 0; i < 4; i++) {
        const int srow = qt * 64 + ty * 4 + i;
        float* orow = O + (size_t)(b * S_SZ + srow) * D_SZ + h * HD + tx * 8;
        float v[8];
        #pragma unroll
        for (int j = 0; j < 8; j++) v[j] = o[i][j] * li[i];
        *(float4*)(orow + 0) = *(float4*)(v + 0);
        *(float4*)(orow + 4) = *(float4*)(v + 4);
    }
}

// ---------------- driver ----------------
extern "C" void kernel_launch(void* const* d_in, const int* in_sizes, int n_in,
                              void* d_out, int out_size) {
    const float* hs    = (const float*)d_in[0];
    const float* Wq    = (const float*)d_in[1];
    const float* Wk    = (const float*)d_in[2];
    const float* Wv    = (const float*)d_in[3];
    const float* Wo    = (const float*)d_in[4];
    const float* Win   = (const float*)d_in[5];
    const float* Wout  = (const float*)d_in[6];
    const float* qkf   = (const float*)d_in[7];
    const float* gattn = (const float*)d_in[8];
    const float* gmlp  = (const float*)d_in[9];
    float* out = (float*)d_out;

    float *xn, *q, *k, *v, *attn, *h, *mlp;
    cudaGetSymbolAddress((void**)&xn,   g_xn);
    cudaGetSymbolAddress((void**)&q,    g_q);
    cudaGetSymbolAddress((void**)&k,    g_k);
    cudaGetSymbolAddress((void**)&v,    g_v);
    cudaGetSymbolAddress((void**)&attn, g_attn);
    cudaGetSymbolAddress((void**)&h,    g_h);
    cudaGetSymbolAddress((void**)&mlp,  g_mlp);

    cudaFuncSetAttribute(flash_kernel, cudaFuncAttributeMaxDynamicSharedMemorySize, FLASH_SMEM);
    cudaFuncSetAttribute(gemm_mma<0>, cudaFuncAttributeMaxDynamicSharedMemorySize, GEMM_SMEM);
    cudaFuncSetAttribute(gemm_mma<1>, cudaFuncAttributeMaxDynamicSharedMemorySize, GEMM_SMEM);
    cudaFuncSetAttribute(gemm_mma<2>, cudaFuncAttributeMaxDynamicSharedMemorySize, GEMM_SMEM);

    // 1) pre-attn hypersphere norm
    hnorm_kernel<<<MROWS, 256>>>(hs, gattn, xn);

    // 2) QKV projections (tf32 mma.sync)
    dim3 gD(MROWS / GBM, D_SZ / GBN);   // (32, 16)
    gemm_mma<0><<<gD, 256, GEMM_SMEM>>>(xn, Wq, nullptr, q, D_SZ, D_SZ);
    gemm_mma<0><<<gD, 256, GEMM_SMEM>>>(xn, Wk, nullptr, k, D_SZ, D_SZ);
    gemm_mma<0><<<gD, 256, GEMM_SMEM>>>(xn, Wv, nullptr, v, D_SZ, D_SZ);

    // 3) QK-norm
    const int nvec = MROWS * H_SZ;
    qknorm_kernel<<<nvec / 8, 256>>>(q);
    qknorm_kernel<<<nvec / 8, 256>>>(k);

    // 4) causal attention
    flash_kernel<<<dim3(S_SZ / 64, B_SZ * H_SZ), 256, FLASH_SMEM>>>(q, k, v, qkf, attn);

    // 5) output projection + residual
    gemm_mma<2><<<gD, 256, GEMM_SMEM>>>(attn, Wo, hs, h, D_SZ, D_SZ);

    // 6) pre-MLP hypersphere norm
    hnorm_kernel<<<MROWS, 256>>>(h, gmlp, xn);

    // 7) MLP in + exact GELU
    dim3 gF(MROWS / GBM, F_SZ / GBN);   // (32, 64)
    gemm_mma<1><<<gF, 256, GEMM_SMEM>>>(xn, Win, nullptr, mlp, F_SZ, D_SZ);

    // 8) MLP out + residual -> d_out
    gemm_mma<2><<<gD, 256, GEMM_SMEM>>>(mlp, Wout, h, out, D_SZ, F_SZ);
}

// round 6
// speedup vs baseline: 2.1085x; 1.2556x over previous
#include <cuda_runtime.h>
#include <cuda_bf16.h>
#include <math.h>
#include <stdint.h>

#define B_SZ 2
#define S_SZ 2048
#define D_SZ 2048
#define F_SZ 8192
#define H_SZ 16
#define HD   128
#define MROWS (B_SZ * S_SZ)   // 4096

// ---------------- scratch (device globals; no allocation) ----------------
__device__ float g_xn  [MROWS * D_SZ];
__device__ float g_q   [MROWS * D_SZ];
__device__ float g_k   [MROWS * D_SZ];
__device__ float g_v   [MROWS * D_SZ];
__device__ float g_attn[MROWS * D_SZ];
__device__ float g_h   [MROWS * D_SZ];
__device__ float g_mlp [MROWS * F_SZ];

// ==================== helpers ====================
__device__ __forceinline__ uint32_t f2tf32(float x) {
    uint32_t r;
    asm("cvt.rna.tf32.f32 %0, %1;" : "=r"(r) : "f"(x));
    return r;
}
__device__ __forceinline__ void mma_tf32(float* d, const uint32_t* a, const uint32_t* b) {
    asm volatile(
        "mma.sync.aligned.m16n8k8.row.col.f32.tf32.tf32.f32 "
        "{%0,%1,%2,%3}, {%4,%5,%6,%7}, {%8,%9}, {%0,%1,%2,%3};"
        : "+f"(d[0]), "+f"(d[1]), "+f"(d[2]), "+f"(d[3])
        : "r"(a[0]), "r"(a[1]), "r"(a[2]), "r"(a[3]), "r"(b[0]), "r"(b[1]));
}
__device__ __forceinline__ float gelu_exact(float x) {
    return 0.5f * x * (1.f + erff(x * 0.7071067811865476f));
}

// ==================== tf32 mma.sync GEMM ====================
// C[M,N] = A[M,K] @ W[N,K]^T (+epilogue).
// CTA tile 128x256, BK=32, 256 threads = 8 warps (2 m x 4 n), warp tile 64x64.
// Smem tiles pre-permuted into m16n8k8 fragment order:
//   Afrag[s(4)][m_atom(8)][lane(32)][reg(4)]  (4096 floats)
//   Bfrag[s(4)][n_atom(32)][lane(32)][reg(2)] (8192 floats)
// Double buffered: stage = 12288 floats (48KB), total 96KB dynamic smem.
#define GBM 128
#define GBN 256
#define GBK 32
#define STG_FLOATS 12288
#define GEMM_SMEM (2 * STG_FLOATS * 4)

// EPI: 0=none, 1=exact GELU, 2=residual add
template <int EPI>
__global__ void __launch_bounds__(256, 1)
gemm_mma(const float* __restrict__ A, const float* __restrict__ W,
         const float* __restrict__ R, float* __restrict__ C, int N, int K) {
    extern __shared__ float sm[];
    const int tid = threadIdx.x;
    const int lane = tid & 31;
    const int wid = tid >> 5;
    const int wm = wid >> 2;          // 0..1 (64 rows each)
    const int wn = wid & 3;           // 0..3 (64 cols each)
    const int bm = blockIdx.x * GBM;
    const int bn = blockIdx.y * GBN;

    const int r0 = tid >> 3;          // 0..31 (row group for gmem loads)
    const int c4 = tid & 7;           // float4 col within 32-wide K slice
    const int s_idx = c4 >> 1;        // k8 sub-tile 0..3
    const int creg = c4 & 1;          // high half of k8 (cols 4..7)

    float acc[4][8][4];
    #pragma unroll
    for (int i = 0; i < 4; i++)
        #pragma unroll
        for (int j = 0; j < 8; j++)
            #pragma unroll
            for (int r = 0; r < 4; r++) acc[i][j][r] = 0.f;

    float4 ra[4], rb[8];
    const int NT = K / GBK;

    // ---- load tile 0 ----
    #pragma unroll
    for (int i = 0; i < 4; i++)
        ra[i] = *(const float4*)(A + (size_t)(bm + r0 + 32 * i) * K + c4 * 4);
    #pragma unroll
    for (int i = 0; i < 8; i++)
        rb[i] = *(const float4*)(W + (size_t)(bn + r0 + 32 * i) * K + c4 * 4);

    // ---- store tile 0 into stage 0 (fragment order) ----
    {
        float* smA = sm;
        float* smB = sm + 4096;
        #pragma unroll
        for (int i = 0; i < 4; i++) {
            const int r = r0 + 32 * i;
            const int ma = r >> 4, rr = r & 15;
            float* da = smA + (((s_idx * 8 + ma) * 32 + (rr & 7) * 4) << 2) + ((rr >> 3) + 2 * creg);
            da[0]  = __uint_as_float(f2tf32(ra[i].x));
            da[4]  = __uint_as_float(f2tf32(ra[i].y));
            da[8]  = __uint_as_float(f2tf32(ra[i].z));
            da[12] = __uint_as_float(f2tf32(ra[i].w));
        }
        #pragma unroll
        for (int i = 0; i < 8; i++) {
            const int r = r0 + 32 * i;
            const int na = r >> 3, nn = r & 7;
            float* db = smB + (((s_idx * 32 + na) * 32 + nn * 4) << 1) + creg;
            db[0] = __uint_as_float(f2tf32(rb[i].x));
            db[2] = __uint_as_float(f2tf32(rb[i].y));
            db[4] = __uint_as_float(f2tf32(rb[i].z));
            db[6] = __uint_as_float(f2tf32(rb[i].w));
        }
    }
    __syncthreads();

    for (int kt = 0; kt < NT; kt++) {
        const int cur = kt & 1;
        // prefetch next tile into regs
        if (kt + 1 < NT) {
            const int ko = (kt + 1) * GBK;
            #pragma unroll
            for (int i = 0; i < 4; i++)
                ra[i] = *(const float4*)(A + (size_t)(bm + r0 + 32 * i) * K + ko + c4 * 4);
            #pragma unroll
            for (int i = 0; i < 8; i++)
                rb[i] = *(const float4*)(W + (size_t)(bn + r0 + 32 * i) * K + ko + c4 * 4);
        }
        // compute current stage
        {
            const float* smA = sm + cur * STG_FLOATS;
            const float* smB = smA + 4096;
            #pragma unroll
            for (int s = 0; s < 4; s++) {
                uint32_t af[4][4];
                #pragma unroll
                for (int i = 0; i < 4; i++)
                    *(uint4*)af[i] = *(const uint4*)(smA + (((s * 8 + wm * 4 + i) * 32 + lane) << 2));
                uint32_t bf[8][2];
                #pragma unroll
                for (int j = 0; j < 8; j++)
                    *(uint2*)bf[j] = *(const uint2*)(smB + (((s * 32 + wn * 8 + j) * 32 + lane) << 1));
                #pragma unroll
                for (int i = 0; i < 4; i++)
                    #pragma unroll
                    for (int j = 0; j < 8; j++)
                        mma_tf32(acc[i][j], af[i], bf[j]);
            }
        }
        // store next stage
        if (kt + 1 < NT) {
            float* smA = sm + ((kt + 1) & 1) * STG_FLOATS;
            float* smB = smA + 4096;
            #pragma unroll
            for (int i = 0; i < 4; i++) {
                const int r = r0 + 32 * i;
                const int ma = r >> 4, rr = r & 15;
                float* da = smA + (((s_idx * 8 + ma) * 32 + (rr & 7) * 4) << 2) + ((rr >> 3) + 2 * creg);
                da[0]  = __uint_as_float(f2tf32(ra[i].x));
                da[4]  = __uint_as_float(f2tf32(ra[i].y));
                da[8]  = __uint_as_float(f2tf32(ra[i].z));
                da[12] = __uint_as_float(f2tf32(ra[i].w));
            }
            #pragma unroll
            for (int i = 0; i < 8; i++) {
                const int r = r0 + 32 * i;
                const int na = r >> 3, nn = r & 7;
                float* db = smB + (((s_idx * 32 + na) * 32 + nn * 4) << 1) + creg;
                db[0] = __uint_as_float(f2tf32(rb[i].x));
                db[2] = __uint_as_float(f2tf32(rb[i].y));
                db[4] = __uint_as_float(f2tf32(rb[i].z));
                db[6] = __uint_as_float(f2tf32(rb[i].w));
            }
            __syncthreads();
        }
    }

    // ---- epilogue ----
    const int gid = lane >> 2, tig = lane & 3;
    #pragma unroll
    for (int i = 0; i < 4; i++) {
        #pragma unroll
        for (int j = 0; j < 8; j++) {
            const int row0 = bm + wm * 64 + i * 16 + gid;
            const int col  = bn + wn * 64 + j * 8 + tig * 2;
            float2 v0 = {acc[i][j][0], acc[i][j][1]};
            float2 v1 = {acc[i][j][2], acc[i][j][3]};
            if (EPI == 2) {
                float2 q0 = *(const float2*)(R + (size_t)row0 * N + col);
                float2 q1 = *(const float2*)(R + (size_t)(row0 + 8) * N + col);
                v0.x += q0.x; v0.y += q0.y;
                v1.x += q1.x; v1.y += q1.y;
            }
            if (EPI == 1) {
                v0.x = gelu_exact(v0.x); v0.y = gelu_exact(v0.y);
                v1.x = gelu_exact(v1.x); v1.y = gelu_exact(v1.y);
            }
            *(float2*)(C + (size_t)row0 * N + col) = v0;
            *(float2*)(C + (size_t)(row0 + 8) * N + col) = v1;
        }
    }
}

// ---------------- hypersphere norm ----------------
__global__ void hnorm_kernel(const float* __restrict__ x, const float* __restrict__ g,
                             float* __restrict__ out) {
    const int row = blockIdx.x;
    const float* xr = x + (size_t)row * D_SZ;
    float ss = 0.f;
    for (int i = threadIdx.x; i < D_SZ; i += blockDim.x) {
        float v = xr[i];
        ss += v * v;
    }
    __shared__ float red[32];
    #pragma unroll
    for (int o = 16; o; o >>= 1) ss += __shfl_xor_sync(0xffffffffu, ss, o);
    if ((threadIdx.x & 31) == 0) red[threadIdx.x >> 5] = ss;
    __syncthreads();
    if (threadIdx.x < 32) {
        float v = (threadIdx.x < (blockDim.x >> 5)) ? red[threadIdx.x] : 0.f;
        #pragma unroll
        for (int o = 16; o; o >>= 1) v += __shfl_xor_sync(0xffffffffu, v, o);
        if (threadIdx.x == 0) red[0] = v;
    }
    __syncthreads();
    const float n = sqrtf(red[0]);
    const float scale = 45.254833995939045f / (n + 1e-6f);
    float* orow = out + (size_t)row * D_SZ;
    for (int i = threadIdx.x; i < D_SZ; i += blockDim.x)
        orow[i] = xr[i] * scale * g[i];
}

// ---------------- QK-norm ----------------
__global__ void qknorm_kernel(float* __restrict__ q) {
    const int vec = blockIdx.x * (blockDim.x >> 5) + (threadIdx.x >> 5);
    const int lane = threadIdx.x & 31;
    float* p = q + (size_t)vec * HD;
    float4 v = ((float4*)p)[lane];
    float ss = v.x * v.x + v.y * v.y + v.z * v.z + v.w * v.w;
    #pragma unroll
    for (int o = 16; o; o >>= 1) ss += __shfl_xor_sync(0xffffffffu, ss, o);
    const float s = 1.f / (sqrtf(ss) + 1e-6f);
    v.x *= s; v.y *= s; v.z *= s; v.w *= s;
    ((float4*)p)[lane] = v;
}

// ---------------- Flash attention (fp32, causal, online softmax) ----------------
#define QKV_LD 132
#define S_LD   68
#define FLASH_SMEM ((3 * 64 * QKV_LD + 64 * S_LD + 128) * 4)

__global__ void __launch_bounds__(256, 1)
flash_kernel(const float* __restrict__ Q, const float* __restrict__ K,
             const float* __restrict__ V, const float* __restrict__ scale_p,
             float* __restrict__ O) {
    extern __shared__ float smf[];
    float (*sQ)[QKV_LD] = (float(*)[QKV_LD])smf;
    float (*sK)[QKV_LD] = (float(*)[QKV_LD])(smf + 64 * QKV_LD);
    float (*sV)[QKV_LD] = (float(*)[QKV_LD])(smf + 2 * 64 * QKV_LD);
    float (*sS)[S_LD]   = (float(*)[S_LD]) (smf + 3 * 64 * QKV_LD);
    float* sAlpha = smf + 3 * 64 * QKV_LD + 64 * S_LD;
    float* sLinv  = sAlpha + 64;

    const int qt = blockIdx.x;
    const int bh = blockIdx.y;
    const int b = bh >> 4, h = bh & 15;
    const float scale = *scale_p;
    const int tid = threadIdx.x;
    const int tx = tid & 15, ty = tid >> 4;

    const size_t base = (size_t)b * S_SZ * D_SZ + (size_t)h * HD;
    const float* Qb = Q + base;
    const float* Kb = K + base;
    const float* Vb = V + base;

    {
        const int c4 = tid & 31;
        const int r0 = tid >> 5;
        #pragma unroll
        for (int i = 0; i < 8; i++) {
            const int r = r0 + i * 8;
            float4 t = *(const float4*)(Qb + (size_t)(qt * 64 + r) * D_SZ + c4 * 4);
            *(float4*)&sQ[r][c4 * 4] = t;
        }
    }

    float o[4][8];
    #pragma unroll
    for (int i = 0; i < 4; i++)
        #pragma unroll
        for (int j = 0; j < 8; j++) o[i][j] = 0.f;

    float m_run = -INFINITY, l_run = 0.f;

    for (int kt = 0; kt <= qt; kt++) {
        __syncthreads();
        {
            const int c4 = tid & 31;
            const int r0 = tid >> 5;
            #pragma unroll
            for (int i = 0; i < 8; i++) {
                const int r = r0 + i * 8;
                float4 tk = *(const float4*)(Kb + (size_t)(kt * 64 + r) * D_SZ + c4 * 4);
                *(float4*)&sK[r][c4 * 4] = tk;
                float4 tv = *(const float4*)(Vb + (size_t)(kt * 64 + r) * D_SZ + c4 * 4);
                *(float4*)&sV[r][c4 * 4] = tv;
            }
        }
        __syncthreads();

        float acc[4][4];
        #pragma unroll
        for (int i = 0; i < 4; i++)
            #pragma unroll
            for (int j = 0; j < 4; j++) acc[i][j] = 0.f;

        for (int d = 0; d < HD; d += 4) {
            float4 a[4], bq[4];
            #pragma unroll
            for (int i = 0; i < 4; i++) a[i]  = *(float4*)&sQ[ty * 4 + i][d];
            #pragma unroll
            for (int j = 0; j < 4; j++) bq[j] = *(float4*)&sK[tx * 4 + j][d];
            #pragma unroll
            for (int i = 0; i < 4; i++)
                #pragma unroll
                for (int j = 0; j < 4; j++) {
                    acc[i][j] = fmaf(a[i].x, bq[j].x, acc[i][j]);
                    acc[i][j] = fmaf(a[i].y, bq[j].y, acc[i][j]);
                    acc[i][j] = fmaf(a[i].z, bq[j].z, acc[i][j]);
                    acc[i][j] = fmaf(a[i].w, bq[j].w, acc[i][j]);
                }
        }

        const int qbase = qt * 64, kbase = kt * 64;
        #pragma unroll
        for (int i = 0; i < 4; i++)
            #pragma unroll
            for (int j = 0; j < 4; j++) {
                float s = acc[i][j] * scale;
                if (kbase + tx * 4 + j > qbase + ty * 4 + i) s = -INFINITY;
                sS[ty * 4 + i][tx * 4 + j] = s;
            }
        __syncthreads();

        if (tid < 64) {
            const int r = tid;
            float mt = -INFINITY;
            #pragma unroll 8
            for (int c = 0; c < 64; c++) mt = fmaxf(mt, sS[r][c]);
            const float mnew = fmaxf(m_run, mt);
            const float alpha = (m_run == -INFINITY) ? 0.f : __expf(m_run - mnew);
            float sum = 0.f;
            #pragma unroll 8
            for (int c = 0; c < 64; c++) {
                float p = __expf(sS[r][c] - mnew);
                sS[r][c] = p;
                sum += p;
            }
            l_run = l_run * alpha + sum;
            m_run = mnew;
            sAlpha[r] = alpha;
        }
        __syncthreads();

        float al[4];
        #pragma unroll
        for (int i = 0; i < 4; i++) al[i] = sAlpha[ty * 4 + i];
        #pragma unroll
        for (int i = 0; i < 4; i++)
            #pragma unroll
            for (int j = 0; j < 8; j++) o[i][j] *= al[i];

        for (int kk = 0; kk < 64; kk++) {
            float p[4];
            #pragma unroll
            for (int i = 0; i < 4; i++) p[i] = sS[ty * 4 + i][kk];
            float vv[8];
            *(float4*)(vv + 0) = *(float4*)&sV[kk][tx * 8 + 0];
            *(float4*)(vv + 4) = *(float4*)&sV[kk][tx * 8 + 4];
            #pragma unroll
            for (int i = 0; i < 4; i++)
                #pragma unroll
                for (int j = 0; j < 8; j++)
                    o[i][j] = fmaf(p[i], vv[j], o[i][j]);
        }
    }

    if (tid < 64) sLinv[tid] = 1.f / l_run;
    __syncthreads();

    float li[4];
    #pragma unroll
    for (int i = 0; i < 4; i++) li[i] = sLinv[ty * 4 + i];
    #pragma unroll
    for (int i = 0; i < 4; i++) {
        const int srow = qt * 64 + ty * 4 + i;
        float* orow = O + (size_t)(b * S_SZ + srow) * D_SZ + h * HD + tx * 8;
        float v[8];
        #pragma unroll
        for (int j = 0; j < 8; j++) v[j] = o[i][j] * li[i];
        *(float4*)(orow + 0) = *(float4*)(v + 0);
        *(float4*)(orow + 4) = *(float4*)(v + 4);
    }
}

// ---------------- driver ----------------
extern "C" void kernel_launch(void* const* d_in, const int* in_sizes, int n_in,
                              void* d_out, int out_size) {
    const float* hs    = (const float*)d_in[0];
    const float* Wq    = (const float*)d_in[1];
    const float* Wk    = (const float*)d_in[2];
    const float* Wv    = (const float*)d_in[3];
    const float* Wo    = (const float*)d_in[4];
    const float* Win   = (const float*)d_in[5];
    const float* Wout  = (const float*)d_in[6];
    const float* qkf   = (const float*)d_in[7];
    const float* gattn = (const float*)d_in[8];
    const float* gmlp  = (const float*)d_in[9];
    float* out = (float*)d_out;

    float *xn, *q, *k, *v, *attn, *h, *mlp;
    cudaGetSymbolAddress((void**)&xn,   g_xn);
    cudaGetSymbolAddress((void**)&q,    g_q);
    cudaGetSymbolAddress((void**)&k,    g_k);
    cudaGetSymbolAddress((void**)&v,    g_v);
    cudaGetSymbolAddress((void**)&attn, g_attn);
    cudaGetSymbolAddress((void**)&h,    g_h);
    cudaGetSymbolAddress((void**)&mlp,  g_mlp);

    cudaFuncSetAttribute(flash_kernel, cudaFuncAttributeMaxDynamicSharedMemorySize, FLASH_SMEM);
    cudaFuncSetAttribute(gemm_mma<0>, cudaFuncAttributeMaxDynamicSharedMemorySize, GEMM_SMEM);
    cudaFuncSetAttribute(gemm_mma<1>, cudaFuncAttributeMaxDynamicSharedMemorySize, GEMM_SMEM);
    cudaFuncSetAttribute(gemm_mma<2>, cudaFuncAttributeMaxDynamicSharedMemorySize, GEMM_SMEM);

    // 1) pre-attn hypersphere norm
    hnorm_kernel<<<MROWS, 256>>>(hs, gattn, xn);

    // 2) QKV projections (tf32 mma.sync)
    dim3 gD(MROWS / GBM, D_SZ / GBN);   // (32, 8)
    gemm_mma<0><<<gD, 256, GEMM_SMEM>>>(xn, Wq, nullptr, q, D_SZ, D_SZ);
    gemm_mma<0><<<gD, 256, GEMM_SMEM>>>(xn, Wk, nullptr, k, D_SZ, D_SZ);
    gemm_mma<0><<<gD, 256, GEMM_SMEM>>>(xn, Wv, nullptr, v, D_SZ, D_SZ);

    // 3) QK-norm
    const int nvec = MROWS * H_SZ;
    qknorm_kernel<<<nvec / 8, 256>>>(q);
    qknorm_kernel<<<nvec / 8, 256>>>(k);

    // 4) causal attention
    flash_kernel<<<dim3(S_SZ / 64, B_SZ * H_SZ), 256, FLASH_SMEM>>>(q, k, v, qkf, attn);

    // 5) output projection + residual
    gemm_mma<2><<<gD, 256, GEMM_SMEM>>>(attn, Wo, hs, h, D_SZ, D_SZ);

    // 6) pre-MLP hypersphere norm
    hnorm_kernel<<<MROWS, 256>>>(h, gmlp, xn);

    // 7) MLP in + exact GELU
    dim3 gF(MROWS / GBM, F_SZ / GBN);   // (32, 32)
    gemm_mma<1><<<gF, 256, GEMM_SMEM>>>(xn, Win, nullptr, mlp, F_SZ, D_SZ);

    // 8) MLP out + residual -> d_out
    gemm_mma<2><<<gD, 256, GEMM_SMEM>>>(mlp, Wout, h, out, D_SZ, F_SZ);
}

// round 8
// speedup vs baseline: 2.9985x; 1.4221x over previous
#include <cuda_runtime.h>
#include <cuda_bf16.h>
#include <math.h>
#include <stdint.h>

#define B_SZ 2
#define S_SZ 2048
#define D_SZ 2048
#define F_SZ 8192
#define H_SZ 16
#define HD   128
#define MROWS (B_SZ * S_SZ)   // 4096

// ---------------- scratch (device globals; no allocation) ----------------
__device__ float g_xn  [MROWS * D_SZ];
__device__ float g_q   [MROWS * D_SZ];
__device__ float g_k   [MROWS * D_SZ];
__device__ float g_v   [MROWS * D_SZ];
__device__ float g_attn[MROWS * D_SZ];
__device__ float g_h   [MROWS * D_SZ];
__device__ float g_mlp [MROWS * F_SZ];

// ==================== helpers ====================
__device__ __forceinline__ uint32_t f2tf32(float x) {
    uint32_t r;
    asm("cvt.rna.tf32.f32 %0, %1;" : "=r"(r) : "f"(x));
    return r;
}
__device__ __forceinline__ float f2tf32f(float x) {
    return __uint_as_float(f2tf32(x));
}
__device__ __forceinline__ void mma_tf32(float* d, const uint32_t* a, const uint32_t* b) {
    asm volatile(
        "mma.sync.aligned.m16n8k8.row.col.f32.tf32.tf32.f32 "
        "{%0,%1,%2,%3}, {%4,%5,%6,%7}, {%8,%9}, {%0,%1,%2,%3};"
        : "+f"(d[0]), "+f"(d[1]), "+f"(d[2]), "+f"(d[3])
        : "r"(a[0]), "r"(a[1]), "r"(a[2]), "r"(a[3]), "r"(b[0]), "r"(b[1]));
}
__device__ __forceinline__ float gelu_exact(float x) {
    return 0.5f * x * (1.f + erff(x * 0.7071067811865476f));
}

// ==================== tf32 mma.sync GEMM (unchanged from R6) ====================
#define GBM 128
#define GBN 256
#define GBK 32
#define STG_FLOATS 12288
#define GEMM_SMEM (2 * STG_FLOATS * 4)

template <int EPI>
__global__ void __launch_bounds__(256, 1)
gemm_mma(const float* __restrict__ A, const float* __restrict__ W,
         const float* __restrict__ R, float* __restrict__ C, int N, int K) {
    extern __shared__ float sm[];
    const int tid = threadIdx.x;
    const int lane = tid & 31;
    const int wid = tid >> 5;
    const int wm = wid >> 2;
    const int wn = wid & 3;
    const int bm = blockIdx.x * GBM;
    const int bn = blockIdx.y * GBN;

    const int r0 = tid >> 3;
    const int c4 = tid & 7;
    const int s_idx = c4 >> 1;
    const int creg = c4 & 1;

    float acc[4][8][4];
    #pragma unroll
    for (int i = 0; i < 4; i++)
        #pragma unroll
        for (int j = 0; j < 8; j++)
            #pragma unroll
            for (int r = 0; r < 4; r++) acc[i][j][r] = 0.f;

    float4 ra[4], rb[8];
    const int NT = K / GBK;

    #pragma unroll
    for (int i = 0; i < 4; i++)
        ra[i] = *(const float4*)(A + (size_t)(bm + r0 + 32 * i) * K + c4 * 4);
    #pragma unroll
    for (int i = 0; i < 8; i++)
        rb[i] = *(const float4*)(W + (size_t)(bn + r0 + 32 * i) * K + c4 * 4);

    {
        float* smA = sm;
        float* smB = sm + 4096;
        #pragma unroll
        for (int i = 0; i < 4; i++) {
            const int r = r0 + 32 * i;
            const int ma = r >> 4, rr = r & 15;
            float* da = smA + (((s_idx * 8 + ma) * 32 + (rr & 7) * 4) << 2) + ((rr >> 3) + 2 * creg);
            da[0]  = f2tf32f(ra[i].x);
            da[4]  = f2tf32f(ra[i].y);
            da[8]  = f2tf32f(ra[i].z);
            da[12] = f2tf32f(ra[i].w);
        }
        #pragma unroll
        for (int i = 0; i < 8; i++) {
            const int r = r0 + 32 * i;
            const int na = r >> 3, nn = r & 7;
            float* db = smB + (((s_idx * 32 + na) * 32 + nn * 4) << 1) + creg;
            db[0] = f2tf32f(rb[i].x);
            db[2] = f2tf32f(rb[i].y);
            db[4] = f2tf32f(rb[i].z);
            db[6] = f2tf32f(rb[i].w);
        }
    }
    __syncthreads();

    for (int kt = 0; kt < NT; kt++) {
        const int cur = kt & 1;
        if (kt + 1 < NT) {
            const int ko = (kt + 1) * GBK;
            #pragma unroll
            for (int i = 0; i < 4; i++)
                ra[i] = *(const float4*)(A + (size_t)(bm + r0 + 32 * i) * K + ko + c4 * 4);
            #pragma unroll
            for (int i = 0; i < 8; i++)
                rb[i] = *(const float4*)(W + (size_t)(bn + r0 + 32 * i) * K + ko + c4 * 4);
        }
        {
            const float* smA = sm + cur * STG_FLOATS;
            const float* smB = smA + 4096;
            #pragma unroll
            for (int s = 0; s < 4; s++) {
                uint32_t af[4][4];
                #pragma unroll
                for (int i = 0; i < 4; i++)
                    *(uint4*)af[i] = *(const uint4*)(smA + (((s * 8 + wm * 4 + i) * 32 + lane) << 2));
                uint32_t bf[8][2];
                #pragma unroll
                for (int j = 0; j < 8; j++)
                    *(uint2*)bf[j] = *(const uint2*)(smB + (((s * 32 + wn * 8 + j) * 32 + lane) << 1));
                #pragma unroll
                for (int i = 0; i < 4; i++)
                    #pragma unroll
                    for (int j = 0; j < 8; j++)
                        mma_tf32(acc[i][j], af[i], bf[j]);
            }
        }
        if (kt + 1 < NT) {
            float* smA = sm + ((kt + 1) & 1) * STG_FLOATS;
            float* smB = smA + 4096;
            #pragma unroll
            for (int i = 0; i < 4; i++) {
                const int r = r0 + 32 * i;
                const int ma = r >> 4, rr = r & 15;
                float* da = smA + (((s_idx * 8 + ma) * 32 + (rr & 7) * 4) << 2) + ((rr >> 3) + 2 * creg);
                da[0]  = f2tf32f(ra[i].x);
                da[4]  = f2tf32f(ra[i].y);
                da[8]  = f2tf32f(ra[i].z);
                da[12] = f2tf32f(ra[i].w);
            }
            #pragma unroll
            for (int i = 0; i < 8; i++) {
                const int r = r0 + 32 * i;
                const int na = r >> 3, nn = r & 7;
                float* db = smB + (((s_idx * 32 + na) * 32 + nn * 4) << 1) + creg;
                db[0] = f2tf32f(rb[i].x);
                db[2] = f2tf32f(rb[i].y);
                db[4] = f2tf32f(rb[i].z);
                db[6] = f2tf32f(rb[i].w);
            }
            __syncthreads();
        }
    }

    const int gid = lane >> 2, tig = lane & 3;
    #pragma unroll
    for (int i = 0; i < 4; i++) {
        #pragma unroll
        for (int j = 0; j < 8; j++) {
            const int row0 = bm + wm * 64 + i * 16 + gid;
            const int col  = bn + wn * 64 + j * 8 + tig * 2;
            float2 v0 = {acc[i][j][0], acc[i][j][1]};
            float2 v1 = {acc[i][j][2], acc[i][j][3]};
            if (EPI == 2) {
                float2 q0 = *(const float2*)(R + (size_t)row0 * N + col);
                float2 q1 = *(const float2*)(R + (size_t)(row0 + 8) * N + col);
                v0.x += q0.x; v0.y += q0.y;
                v1.x += q1.x; v1.y += q1.y;
            }
            if (EPI == 1) {
                v0.x = gelu_exact(v0.x); v0.y = gelu_exact(v0.y);
                v1.x = gelu_exact(v1.x); v1.y = gelu_exact(v1.y);
            }
            *(float2*)(C + (size_t)row0 * N + col) = v0;
            *(float2*)(C + (size_t)(row0 + 8) * N + col) = v1;
        }
    }
}

// ---------------- hypersphere norm ----------------
__global__ void hnorm_kernel(const float* __restrict__ x, const float* __restrict__ g,
                             float* __restrict__ out) {
    const int row = blockIdx.x;
    const float* xr = x + (size_t)row * D_SZ;
    float ss = 0.f;
    for (int i = threadIdx.x; i < D_SZ; i += blockDim.x) {
        float v = xr[i];
        ss += v * v;
    }
    __shared__ float red[32];
    #pragma unroll
    for (int o = 16; o; o >>= 1) ss += __shfl_xor_sync(0xffffffffu, ss, o);
    if ((threadIdx.x & 31) == 0) red[threadIdx.x >> 5] = ss;
    __syncthreads();
    if (threadIdx.x < 32) {
        float v = (threadIdx.x < (blockDim.x >> 5)) ? red[threadIdx.x] : 0.f;
        #pragma unroll
        for (int o = 16; o; o >>= 1) v += __shfl_xor_sync(0xffffffffu, v, o);
        if (threadIdx.x == 0) red[0] = v;
    }
    __syncthreads();
    const float n = sqrtf(red[0]);
    const float scale = 45.254833995939045f / (n + 1e-6f);
    float* orow = out + (size_t)row * D_SZ;
    for (int i = threadIdx.x; i < D_SZ; i += blockDim.x)
        orow[i] = xr[i] * scale * g[i];
}

// ---------------- QK-norm ----------------
__global__ void qknorm_kernel(float* __restrict__ q) {
    const int vec = blockIdx.x * (blockDim.x >> 5) + (threadIdx.x >> 5);
    const int lane = threadIdx.x & 31;
    float* p = q + (size_t)vec * HD;
    float4 v = ((float4*)p)[lane];
    float ss = v.x * v.x + v.y * v.y + v.z * v.z + v.w * v.w;
    #pragma unroll
    for (int o = 16; o; o >>= 1) ss += __shfl_xor_sync(0xffffffffu, ss, o);
    const float s = 1.f / (sqrtf(ss) + 1e-6f);
    v.x *= s; v.y *= s; v.z *= s; v.w *= s;
    ((float4*)p)[lane] = v;
}

// ==================== Flash attention via mma.sync tf32 ====================
// BQ=128 (8 warps x 16 rows), BKV=64. grid: x = S/128 (reversed), y = b*H+h.
// Smem (floats): sQ A-frag [chunk16][m8][lane32][4] = 16384
//                sK B-frag [chunk16][n8][lane32][2] =  8192
//                sVt B-frag [chunk8][n16][lane32][2] = 8192  (V transposed: n=d, k=key)
//                sP A-frag [chunk8][m8][lane32][4]  =  8192
#define FL_SQ  0
#define FL_SK  16384
#define FL_SVT 24576
#define FL_SP  32768
#define FLASH_SMEM (40960 * 4)

__global__ void __launch_bounds__(256, 1)
flash_mma(const float* __restrict__ Q, const float* __restrict__ K,
          const float* __restrict__ V, const float* __restrict__ scale_p,
          float* __restrict__ O) {
    extern __shared__ float fs[];
    float* sQ  = fs + FL_SQ;
    float* sK  = fs + FL_SK;
    float* sVt = fs + FL_SVT;
    float* sP  = fs + FL_SP;

    const int qt = gridDim.x - 1 - blockIdx.x;   // heaviest CTAs first
    const int bh = blockIdx.y;
    const int b = bh >> 4, h = bh & 15;
    const float scale = *scale_p;
    const int tid = threadIdx.x;
    const int lane = tid & 31;
    const int wid = tid >> 5;

    const size_t base = (size_t)b * S_SZ * D_SZ + (size_t)h * HD;

    // ---- stage Q tile into A-frag order (scale folded in); 2 threads per row,
    //      16 float4s each -> full 128-dim head ----
    {
        const int r = tid >> 1;
        const int ma = r >> 4, rr = r & 15;
        #pragma unroll
        for (int i = 0; i < 16; i++) {
            const int c4 = (tid & 1) * 16 + i;      // 0..31
            float4 v = *(const float4*)(Q + base + (size_t)(qt * 128 + r) * D_SZ + c4 * 4);
            const int chunk = c4 >> 1, ch = c4 & 1;
            float* da = sQ + (((chunk * 8 + ma) * 32 + (rr & 7) * 4) << 2) + ((rr >> 3) + 2 * ch);
            da[0]  = f2tf32f(v.x * scale);
            da[4]  = f2tf32f(v.y * scale);
            da[8]  = f2tf32f(v.z * scale);
            da[12] = f2tf32f(v.w * scale);
        }
    }

    float o[16][4];
    #pragma unroll
    for (int i = 0; i < 16; i++)
        #pragma unroll
        for (int r = 0; r < 4; r++) o[i][r] = 0.f;
    float m_run[2] = {-INFINITY, -INFINITY};
    float l_run[2] = {0.f, 0.f};

    const int NKT = 2 * qt + 2;
    for (int kt = 0; kt < NKT; kt++) {
        __syncthreads();   // prior iteration done with sK/sVt (and Q staged on kt=0)
        // ---- stage K (B-frag) and V^T (B-frag); 4 threads per key row,
        //      8 float4s each -> full 128-dim head ----
        {
            const int n0 = tid >> 2;           // key row 0..63
            #pragma unroll
            for (int i = 0; i < 8; i++) {
                const int c4i = (tid & 3) + 4 * i;   // 0..31
                const int d0 = c4i * 4;
                float4 kv = *(const float4*)(K + base + (size_t)(kt * 64 + n0) * D_SZ + d0);
                float* dk = sK + (((((d0 >> 3) * 8) + (n0 >> 3)) * 32 + (n0 & 7) * 4) << 1) + (c4i & 1);
                dk[0] = f2tf32f(kv.x);
                dk[2] = f2tf32f(kv.y);
                dk[4] = f2tf32f(kv.z);
                dk[6] = f2tf32f(kv.w);
                float4 vv = *(const float4*)(V + base + (size_t)(kt * 64 + n0) * D_SZ + d0);
                float* dv = sVt + ((((n0 >> 3) * 16 + (c4i >> 1)) * 32 + ((c4i & 1) * 4) * 4 + (n0 & 3)) << 1)
                          + ((n0 & 7) >> 2);
                dv[0]  = f2tf32f(vv.x);
                dv[8]  = f2tf32f(vv.y);
                dv[16] = f2tf32f(vv.z);
                dv[24] = f2tf32f(vv.w);
            }
        }
        __syncthreads();

        // ---- S = Q @ K^T (per warp: 16 rows x 64 keys) ----
        float sacc[8][4];
        #pragma unroll
        for (int j = 0; j < 8; j++)
            #pragma unroll
            for (int r = 0; r < 4; r++) sacc[j][r] = 0.f;
        #pragma unroll
        for (int c = 0; c < 16; c++) {
            uint32_t af[4];
            *(uint4*)af = *(const uint4*)(sQ + (((c * 8 + wid) * 32 + lane) << 2));
            #pragma unroll
            for (int j = 0; j < 8; j++) {
                uint32_t bf[2];
                *(uint2*)bf = *(const uint2*)(sK + (((c * 8 + j) * 32 + lane) << 1));
                mma_tf32(sacc[j], af, bf);
            }
        }

        // ---- causal mask (only possible on last two k-tiles) ----
        if (kt >= 2 * qt) {
            const int rbase = qt * 128 + wid * 16 + (lane >> 2);
            const int cbase = kt * 64 + 2 * (lane & 3);
            #pragma unroll
            for (int j = 0; j < 8; j++)
                #pragma unroll
                for (int r = 0; r < 4; r++) {
                    const int row = rbase + ((r >> 1) << 3);
                    const int col = cbase + j * 8 + (r & 1);
                    if (col > row) sacc[j][r] = -INFINITY;
                }
        }

        // ---- online softmax (register-level, per row-half) ----
        #pragma unroll
        for (int hh = 0; hh < 2; hh++) {
            float mt = -INFINITY;
            #pragma unroll
            for (int j = 0; j < 8; j++)
                mt = fmaxf(mt, fmaxf(sacc[j][2 * hh], sacc[j][2 * hh + 1]));
            mt = fmaxf(mt, __shfl_xor_sync(0xffffffffu, mt, 1));
            mt = fmaxf(mt, __shfl_xor_sync(0xffffffffu, mt, 2));
            const bool skip = (mt == -INFINITY);
            const float mold = m_run[hh];
            const float mnew = skip ? mold : fmaxf(mold, mt);
            const float msafe = (mnew == -INFINITY) ? 0.f : mnew;
            const float alpha = skip ? 1.f : __expf(mold - mnew);
            float sum = 0.f;
            #pragma unroll
            for (int j = 0; j < 8; j++) {
                float p0 = __expf(sacc[j][2 * hh]     - msafe);
                float p1 = __expf(sacc[j][2 * hh + 1] - msafe);
                sacc[j][2 * hh]     = p0;
                sacc[j][2 * hh + 1] = p1;
                sum += p0 + p1;
            }
            sum += __shfl_xor_sync(0xffffffffu, sum, 1);
            sum += __shfl_xor_sync(0xffffffffu, sum, 2);
            l_run[hh] = l_run[hh] * alpha + sum;
            m_run[hh] = mnew;
            #pragma unroll
            for (int j = 0; j < 16; j++) {
                o[j][2 * hh]     *= alpha;
                o[j][2 * hh + 1] *= alpha;
            }
        }

        // ---- store P into A-frag order (warp-private region) ----
        __syncwarp();
        {
            const int rlow = lane >> 2, q = lane & 3;
            #pragma unroll
            for (int j = 0; j < 8; j++) {
                #pragma unroll
                for (int hh = 0; hh < 2; hh++) {
                    #pragma unroll
                    for (int bb = 0; bb < 2; bb++) {
                        const int cc = 2 * q + bb;           // col within 8-wide chunk
                        const int lt = rlow * 4 + (cc & 3);
                        const int rt = hh + 2 * (cc >> 2);
                        sP[(((j * 8 + wid) * 32 + lt) << 2) + rt] = f2tf32f(sacc[j][2 * hh + bb]);
                    }
                }
            }
        }
        __syncwarp();

        // ---- O += P @ V ----
        #pragma unroll
        for (int c = 0; c < 8; c++) {
            uint32_t af[4];
            *(uint4*)af = *(const uint4*)(sP + (((c * 8 + wid) * 32 + lane) << 2));
            #pragma unroll
            for (int j = 0; j < 16; j++) {
                uint32_t bf[2];
                *(uint2*)bf = *(const uint2*)(sVt + (((c * 16 + j) * 32 + lane) << 1));
                mma_tf32(o[j], af, bf);
            }
        }
    }

    // ---- epilogue: normalize and write ----
    const float il0 = 1.f / l_run[0];
    const float il1 = 1.f / l_run[1];
    const int row_g = qt * 128 + wid * 16 + (lane >> 2);
    #pragma unroll
    for (int j = 0; j < 16; j++) {
        const int col = h * HD + j * 8 + 2 * (lane & 3);
        float2 v0 = {o[j][0] * il0, o[j][1] * il0};
        float2 v1 = {o[j][2] * il1, o[j][3] * il1};
        *(float2*)(O + (size_t)(b * S_SZ + row_g) * D_SZ + col) = v0;
        *(float2*)(O + (size_t)(b * S_SZ + row_g + 8) * D_SZ + col) = v1;
    }
}

// ---------------- driver ----------------
extern "C" void kernel_launch(void* const* d_in, const int* in_sizes, int n_in,
                              void* d_out, int out_size) {
    const float* hs    = (const float*)d_in[0];
    const float* Wq    = (const float*)d_in[1];
    const float* Wk    = (const float*)d_in[2];
    const float* Wv    = (const float*)d_in[3];
    const float* Wo    = (const float*)d_in[4];
    const float* Win   = (const float*)d_in[5];
    const float* Wout  = (const float*)d_in[6];
    const float* qkf   = (const float*)d_in[7];
    const float* gattn = (const float*)d_in[8];
    const float* gmlp  = (const float*)d_in[9];
    float* out = (float*)d_out;

    float *xn, *q, *k, *v, *attn, *h, *mlp;
    cudaGetSymbolAddress((void**)&xn,   g_xn);
    cudaGetSymbolAddress((void**)&q,    g_q);
    cudaGetSymbolAddress((void**)&k,    g_k);
    cudaGetSymbolAddress((void**)&v,    g_v);
    cudaGetSymbolAddress((void**)&attn, g_attn);
    cudaGetSymbolAddress((void**)&h,    g_h);
    cudaGetSymbolAddress((void**)&mlp,  g_mlp);

    cudaFuncSetAttribute(flash_mma, cudaFuncAttributeMaxDynamicSharedMemorySize, FLASH_SMEM);
    cudaFuncSetAttribute(gemm_mma<0>, cudaFuncAttributeMaxDynamicSharedMemorySize, GEMM_SMEM);
    cudaFuncSetAttribute(gemm_mma<1>, cudaFuncAttributeMaxDynamicSharedMemorySize, GEMM_SMEM);
    cudaFuncSetAttribute(gemm_mma<2>, cudaFuncAttributeMaxDynamicSharedMemorySize, GEMM_SMEM);

    // 1) pre-attn hypersphere norm
    hnorm_kernel<<<MROWS, 256>>>(hs, gattn, xn);

    // 2) QKV projections (tf32 mma.sync)
    dim3 gD(MROWS / GBM, D_SZ / GBN);   // (32, 8)
    gemm_mma<0><<<gD, 256, GEMM_SMEM>>>(xn, Wq, nullptr, q, D_SZ, D_SZ);
    gemm_mma<0><<<gD, 256, GEMM_SMEM>>>(xn, Wk, nullptr, k, D_SZ, D_SZ);
    gemm_mma<0><<<gD, 256, GEMM_SMEM>>>(xn, Wv, nullptr, v, D_SZ, D_SZ);

    // 3) QK-norm
    const int nvec = MROWS * H_SZ;
    qknorm_kernel<<<nvec / 8, 256>>>(q);
    qknorm_kernel<<<nvec / 8, 256>>>(k);

    // 4) causal attention (tensor-core flash)
    flash_mma<<<dim3(S_SZ / 128, B_SZ * H_SZ), 256, FLASH_SMEM>>>(q, k, v, qkf, attn);

    // 5) output projection + residual
    gemm_mma<2><<<gD, 256, GEMM_SMEM>>>(attn, Wo, hs, h, D_SZ, D_SZ);

    // 6) pre-MLP hypersphere norm
    hnorm_kernel<<<MROWS, 256>>>(h, gmlp, xn);

    // 7) MLP in + exact GELU
    dim3 gF(MROWS / GBM, F_SZ / GBN);   // (32, 32)
    gemm_mma<1><<<gF, 256, GEMM_SMEM>>>(xn, Win, nullptr, mlp, F_SZ, D_SZ);

    // 8) MLP out + residual -> d_out
    gemm_mma<2><<<gD, 256, GEMM_SMEM>>>(mlp, Wout, h, out, D_SZ, F_SZ);
}

// round 9
// speedup vs baseline: 3.5227x; 1.1748x over previous
#include <cuda_runtime.h>
#include <cuda_bf16.h>
#include <math.h>
#include <stdint.h>

#define B_SZ 2
#define S_SZ 2048
#define D_SZ 2048
#define F_SZ 8192
#define H_SZ 16
#define HD   128
#define MROWS (B_SZ * S_SZ)   // 4096

// ---------------- scratch (device globals; no allocation) ----------------
__device__ float g_xn  [MROWS * D_SZ];
__device__ float g_q   [MROWS * D_SZ];
__device__ float g_k   [MROWS * D_SZ];
__device__ float g_v   [MROWS * D_SZ];
__device__ float g_attn[MROWS * D_SZ];
__device__ float g_h   [MROWS * D_SZ];
__device__ float g_mlp [MROWS * F_SZ];

// ==================== helpers ====================
__device__ __forceinline__ uint32_t f2tf32(float x) {
    uint32_t r;
    asm("cvt.rna.tf32.f32 %0, %1;" : "=r"(r) : "f"(x));
    return r;
}
__device__ __forceinline__ float f2tf32f(float x) {
    return __uint_as_float(f2tf32(x));
}
__device__ __forceinline__ void mma_tf32(float* d, const uint32_t* a, const uint32_t* b) {
    asm volatile(
        "mma.sync.aligned.m16n8k8.row.col.f32.tf32.tf32.f32 "
        "{%0,%1,%2,%3}, {%4,%5,%6,%7}, {%8,%9}, {%0,%1,%2,%3};"
        : "+f"(d[0]), "+f"(d[1]), "+f"(d[2]), "+f"(d[3])
        : "r"(a[0]), "r"(a[1]), "r"(a[2]), "r"(a[3]), "r"(b[0]), "r"(b[1]));
}
__device__ __forceinline__ float gelu_exact(float x) {
    return 0.5f * x * (1.f + erff(x * 0.7071067811865476f));
}

// ==================== tf32 mma.sync GEMM ====================
// C[M,N] = A[M,K] @ W[N,K]^T (+epilogue).
// CTA tile 128x256, BK=32, 256 threads = 8 warps (2m x 4n), warp tile 64x64.
// Fragment-order smem with XOR-by-chunk lane swizzle (kills STS bank conflicts):
//   A-frag: [s(4)][ma(8)][lane^s(32)][reg(4)]          = 4096 floats
//   B-frag: [s(4)][na_pair(16)][lane^s(32)][reg(4)]    = 8192 floats
//     (pair layout: atoms 2p,2p+1 share a uint4 -> bf via LDS.128)
// Double buffered: stage = 12288 floats (48KB), total 96KB dynamic smem.
#define GBM 128
#define GBN 256
#define GBK 32
#define STG_FLOATS 12288
#define GEMM_SMEM (2 * STG_FLOATS * 4)

__device__ __forceinline__ void stage_store(float* smA, const float4* ra, const float4* rb,
                                            int r0, int s_idx, int creg) {
    float* smB = smA + 4096;
    #pragma unroll
    for (int i = 0; i < 4; i++) {
        const int r = r0 + 32 * i;
        const int ma = r >> 4, rr = r & 15;
        const int rg = (rr >> 3) + 2 * creg;
        const int Lb = (rr & 7) * 4;
        float av[4] = {ra[i].x, ra[i].y, ra[i].z, ra[i].w};
        #pragma unroll
        for (int e = 0; e < 4; e++)
            smA[(((s_idx * 8 + ma) * 32 + ((Lb + e) ^ s_idx)) << 2) + rg] = f2tf32f(av[e]);
    }
    #pragma unroll
    for (int i = 0; i < 8; i++) {
        const int r = r0 + 32 * i;
        const int na = r >> 3, nn = r & 7;
        const int rg = (na & 1) * 2 + creg;
        const int Lb = nn * 4;
        float bv[4] = {rb[i].x, rb[i].y, rb[i].z, rb[i].w};
        #pragma unroll
        for (int e = 0; e < 4; e++)
            smB[(((s_idx * 16 + (na >> 1)) * 32 + ((Lb + e) ^ s_idx)) << 2) + rg] = f2tf32f(bv[e]);
    }
}

// EPI: 0=none, 1=exact GELU, 2=residual add
template <int EPI>
__device__ __forceinline__ void gemm_body(
    const float* __restrict__ A, const float* __restrict__ W,
    const float* __restrict__ R, float* __restrict__ C,
    int N, int K, int bm, int bn, float* sm) {
    const int tid = threadIdx.x;
    const int lane = tid & 31;
    const int wid = tid >> 5;
    const int wm = wid >> 2;
    const int wn = wid & 3;

    const int r0 = tid >> 3;
    const int c4 = tid & 7;
    const int s_idx = c4 >> 1;
    const int creg = c4 & 1;

    float acc[4][8][4];
    #pragma unroll
    for (int i = 0; i < 4; i++)
        #pragma unroll
        for (int j = 0; j < 8; j++)
            #pragma unroll
            for (int r = 0; r < 4; r++) acc[i][j][r] = 0.f;

    float4 ra[4], rb[8];
    const int NT = K / GBK;

    #pragma unroll
    for (int i = 0; i < 4; i++)
        ra[i] = *(const float4*)(A + (size_t)(bm + r0 + 32 * i) * K + c4 * 4);
    #pragma unroll
    for (int i = 0; i < 8; i++)
        rb[i] = *(const float4*)(W + (size_t)(bn + r0 + 32 * i) * K + c4 * 4);

    stage_store(sm, ra, rb, r0, s_idx, creg);
    __syncthreads();

    for (int kt = 0; kt < NT; kt++) {
        const int cur = kt & 1;
        if (kt + 1 < NT) {
            const int ko = (kt + 1) * GBK;
            #pragma unroll
            for (int i = 0; i < 4; i++)
                ra[i] = *(const float4*)(A + (size_t)(bm + r0 + 32 * i) * K + ko + c4 * 4);
            #pragma unroll
            for (int i = 0; i < 8; i++)
                rb[i] = *(const float4*)(W + (size_t)(bn + r0 + 32 * i) * K + ko + c4 * 4);
        }
        {
            const float* smA = sm + cur * STG_FLOATS;
            const float* smB = smA + 4096;
            #pragma unroll
            for (int s = 0; s < 4; s++) {
                const int lx = lane ^ s;
                uint32_t af[4][4];
                #pragma unroll
                for (int i = 0; i < 4; i++)
                    *(uint4*)af[i] = *(const uint4*)(smA + (((s * 8 + wm * 4 + i) * 32 + lx) << 2));
                uint32_t bf[4][4];
                #pragma unroll
                for (int jj = 0; jj < 4; jj++)
                    *(uint4*)bf[jj] = *(const uint4*)(smB + (((s * 16 + wn * 4 + jj) * 32 + lx) << 2));
                #pragma unroll
                for (int i = 0; i < 4; i++)
                    #pragma unroll
                    for (int jj = 0; jj < 4; jj++) {
                        mma_tf32(acc[i][2 * jj],     af[i], bf[jj]);
                        mma_tf32(acc[i][2 * jj + 1], af[i], bf[jj] + 2);
                    }
            }
        }
        if (kt + 1 < NT) {
            stage_store(sm + ((kt + 1) & 1) * STG_FLOATS, ra, rb, r0, s_idx, creg);
            __syncthreads();
        }
    }

    const int gid = lane >> 2, tig = lane & 3;
    #pragma unroll
    for (int i = 0; i < 4; i++) {
        #pragma unroll
        for (int j = 0; j < 8; j++) {
            const int row0 = bm + wm * 64 + i * 16 + gid;
            const int col  = bn + wn * 64 + j * 8 + tig * 2;
            float2 v0 = {acc[i][j][0], acc[i][j][1]};
            float2 v1 = {acc[i][j][2], acc[i][j][3]};
            if (EPI == 2) {
                float2 q0 = *(const float2*)(R + (size_t)row0 * N + col);
                float2 q1 = *(const float2*)(R + (size_t)(row0 + 8) * N + col);
                v0.x += q0.x; v0.y += q0.y;
                v1.x += q1.x; v1.y += q1.y;
            }
            if (EPI == 1) {
                v0.x = gelu_exact(v0.x); v0.y = gelu_exact(v0.y);
                v1.x = gelu_exact(v1.x); v1.y = gelu_exact(v1.y);
            }
            *(float2*)(C + (size_t)row0 * N + col) = v0;
            *(float2*)(C + (size_t)(row0 + 8) * N + col) = v1;
        }
    }
}

template <int EPI>
__global__ void __launch_bounds__(256, 1)
gemm_mma(const float* __restrict__ A, const float* __restrict__ W,
         const float* __restrict__ R, float* __restrict__ C, int N, int K) {
    extern __shared__ float sm[];
    gemm_body<EPI>(A, W, R, C, N, K, blockIdx.x * GBM, blockIdx.y * GBN, sm);
}

// Fused QKV: grid.y covers N=6144; per-CTA select weight/output by bn>>11.
__global__ void __launch_bounds__(256, 1)
qkv_mma(const float* __restrict__ A,
        const float* __restrict__ Wq, const float* __restrict__ Wk,
        const float* __restrict__ Wv,
        float* __restrict__ q, float* __restrict__ k, float* __restrict__ v,
        int K) {
    extern __shared__ float sm[];
    const int bn = blockIdx.y * GBN;
    const int which = bn >> 11;
    const float* W = (which == 0) ? Wq : (which == 1) ? Wk : Wv;
    float* C = (which == 0) ? q : (which == 1) ? k : v;
    gemm_body<0>(A, W, nullptr, C, D_SZ, K, blockIdx.x * GBM, bn & 2047, sm);
}

// ---------------- hypersphere norm ----------------
__global__ void hnorm_kernel(const float* __restrict__ x, const float* __restrict__ g,
                             float* __restrict__ out) {
    const int row = blockIdx.x;
    const float* xr = x + (size_t)row * D_SZ;
    float ss = 0.f;
    for (int i = threadIdx.x; i < D_SZ; i += blockDim.x) {
        float v = xr[i];
        ss += v * v;
    }
    __shared__ float red[32];
    #pragma unroll
    for (int o = 16; o; o >>= 1) ss += __shfl_xor_sync(0xffffffffu, ss, o);
    if ((threadIdx.x & 31) == 0) red[threadIdx.x >> 5] = ss;
    __syncthreads();
    if (threadIdx.x < 32) {
        float v = (threadIdx.x < (blockDim.x >> 5)) ? red[threadIdx.x] : 0.f;
        #pragma unroll
        for (int o = 16; o; o >>= 1) v += __shfl_xor_sync(0xffffffffu, v, o);
        if (threadIdx.x == 0) red[0] = v;
    }
    __syncthreads();
    const float n = sqrtf(red[0]);
    const float scale = 45.254833995939045f / (n + 1e-6f);
    float* orow = out + (size_t)row * D_SZ;
    for (int i = threadIdx.x; i < D_SZ; i += blockDim.x)
        orow[i] = xr[i] * scale * g[i];
}

// ---------------- QK-norm ----------------
__global__ void qknorm_kernel(float* __restrict__ q) {
    const int vec = blockIdx.x * (blockDim.x >> 5) + (threadIdx.x >> 5);
    const int lane = threadIdx.x & 31;
    float* p = q + (size_t)vec * HD;
    float4 v = ((float4*)p)[lane];
    float ss = v.x * v.x + v.y * v.y + v.z * v.z + v.w * v.w;
    #pragma unroll
    for (int o = 16; o; o >>= 1) ss += __shfl_xor_sync(0xffffffffu, ss, o);
    const float s = 1.f / (sqrtf(ss) + 1e-6f);
    v.x *= s; v.y *= s; v.z *= s; v.w *= s;
    ((float4*)p)[lane] = v;
}

// ==================== Flash attention via mma.sync tf32 (unchanged R8) ====================
#define FL_SQ  0
#define FL_SK  16384
#define FL_SVT 24576
#define FL_SP  32768
#define FLASH_SMEM (40960 * 4)

__global__ void __launch_bounds__(256, 1)
flash_mma(const float* __restrict__ Q, const float* __restrict__ K,
          const float* __restrict__ V, const float* __restrict__ scale_p,
          float* __restrict__ O) {
    extern __shared__ float fs[];
    float* sQ  = fs + FL_SQ;
    float* sK  = fs + FL_SK;
    float* sVt = fs + FL_SVT;
    float* sP  = fs + FL_SP;

    const int qt = gridDim.x - 1 - blockIdx.x;
    const int bh = blockIdx.y;
    const int b = bh >> 4, h = bh & 15;
    const float scale = *scale_p;
    const int tid = threadIdx.x;
    const int lane = tid & 31;
    const int wid = tid >> 5;

    const size_t base = (size_t)b * S_SZ * D_SZ + (size_t)h * HD;

    {
        const int r = tid >> 1;
        const int ma = r >> 4, rr = r & 15;
        #pragma unroll
        for (int i = 0; i < 16; i++) {
            const int c4 = (tid & 1) * 16 + i;
            float4 v = *(const float4*)(Q + base + (size_t)(qt * 128 + r) * D_SZ + c4 * 4);
            const int chunk = c4 >> 1, ch = c4 & 1;
            float* da = sQ + (((chunk * 8 + ma) * 32 + (rr & 7) * 4) << 2) + ((rr >> 3) + 2 * ch);
            da[0]  = f2tf32f(v.x * scale);
            da[4]  = f2tf32f(v.y * scale);
            da[8]  = f2tf32f(v.z * scale);
            da[12] = f2tf32f(v.w * scale);
        }
    }

    float o[16][4];
    #pragma unroll
    for (int i = 0; i < 16; i++)
        #pragma unroll
        for (int r = 0; r < 4; r++) o[i][r] = 0.f;
    float m_run[2] = {-INFINITY, -INFINITY};
    float l_run[2] = {0.f, 0.f};

    const int NKT = 2 * qt + 2;
    for (int kt = 0; kt < NKT; kt++) {
        __syncthreads();
        {
            const int n0 = tid >> 2;
            #pragma unroll
            for (int i = 0; i < 8; i++) {
                const int c4i = (tid & 3) + 4 * i;
                const int d0 = c4i * 4;
                float4 kv = *(const float4*)(K + base + (size_t)(kt * 64 + n0) * D_SZ + d0);
                float* dk = sK + (((((d0 >> 3) * 8) + (n0 >> 3)) * 32 + (n0 & 7) * 4) << 1) + (c4i & 1);
                dk[0] = f2tf32f(kv.x);
                dk[2] = f2tf32f(kv.y);
                dk[4] = f2tf32f(kv.z);
                dk[6] = f2tf32f(kv.w);
                float4 vv = *(const float4*)(V + base + (size_t)(kt * 64 + n0) * D_SZ + d0);
                float* dv = sVt + ((((n0 >> 3) * 16 + (c4i >> 1)) * 32 + ((c4i & 1) * 4) * 4 + (n0 & 3)) << 1)
                          + ((n0 & 7) >> 2);
                dv[0]  = f2tf32f(vv.x);
                dv[8]  = f2tf32f(vv.y);
                dv[16] = f2tf32f(vv.z);
                dv[24] = f2tf32f(vv.w);
            }
        }
        __syncthreads();

        float sacc[8][4];
        #pragma unroll
        for (int j = 0; j < 8; j++)
            #pragma unroll
            for (int r = 0; r < 4; r++) sacc[j][r] = 0.f;
        #pragma unroll
        for (int c = 0; c < 16; c++) {
            uint32_t af[4];
            *(uint4*)af = *(const uint4*)(sQ + (((c * 8 + wid) * 32 + lane) << 2));
            #pragma unroll
            for (int j = 0; j < 8; j++) {
                uint32_t bf[2];
                *(uint2*)bf = *(const uint2*)(sK + (((c * 8 + j) * 32 + lane) << 1));
                mma_tf32(sacc[j], af, bf);
            }
        }

        if (kt >= 2 * qt) {
            const int rbase = qt * 128 + wid * 16 + (lane >> 2);
            const int cbase = kt * 64 + 2 * (lane & 3);
            #pragma unroll
            for (int j = 0; j < 8; j++)
                #pragma unroll
                for (int r = 0; r < 4; r++) {
                    const int row = rbase + ((r >> 1) << 3);
                    const int col = cbase + j * 8 + (r & 1);
                    if (col > row) sacc[j][r] = -INFINITY;
                }
        }

        #pragma unroll
        for (int hh = 0; hh < 2; hh++) {
            float mt = -INFINITY;
            #pragma unroll
            for (int j = 0; j < 8; j++)
                mt = fmaxf(mt, fmaxf(sacc[j][2 * hh], sacc[j][2 * hh + 1]));
            mt = fmaxf(mt, __shfl_xor_sync(0xffffffffu, mt, 1));
            mt = fmaxf(mt, __shfl_xor_sync(0xffffffffu, mt, 2));
            const bool skip = (mt == -INFINITY);
            const float mold = m_run[hh];
            const float mnew = skip ? mold : fmaxf(mold, mt);
            const float msafe = (mnew == -INFINITY) ? 0.f : mnew;
            const float alpha = skip ? 1.f : __expf(mold - mnew);
            float sum = 0.f;
            #pragma unroll
            for (int j = 0; j < 8; j++) {
                float p0 = __expf(sacc[j][2 * hh]     - msafe);
                float p1 = __expf(sacc[j][2 * hh + 1] - msafe);
                sacc[j][2 * hh]     = p0;
                sacc[j][2 * hh + 1] = p1;
                sum += p0 + p1;
            }
            sum += __shfl_xor_sync(0xffffffffu, sum, 1);
            sum += __shfl_xor_sync(0xffffffffu, sum, 2);
            l_run[hh] = l_run[hh] * alpha + sum;
            m_run[hh] = mnew;
            #pragma unroll
            for (int j = 0; j < 16; j++) {
                o[j][2 * hh]     *= alpha;
                o[j][2 * hh + 1] *= alpha;
            }
        }

        __syncwarp();
        {
            const int rlow = lane >> 2, q = lane & 3;
            #pragma unroll
            for (int j = 0; j < 8; j++) {
                #pragma unroll
                for (int hh = 0; hh < 2; hh++) {
                    #pragma unroll
                    for (int bb = 0; bb < 2; bb++) {
                        const int cc = 2 * q + bb;
                        const int lt = rlow * 4 + (cc & 3);
                        const int rt = hh + 2 * (cc >> 2);
                        sP[(((j * 8 + wid) * 32 + lt) << 2) + rt] = f2tf32f(sacc[j][2 * hh + bb]);
                    }
                }
            }
        }
        __syncwarp();

        #pragma unroll
        for (int c = 0; c < 8; c++) {
            uint32_t af[4];
            *(uint4*)af = *(const uint4*)(sP + (((c * 8 + wid) * 32 + lane) << 2));
            #pragma unroll
            for (int j = 0; j < 16; j++) {
                uint32_t bf[2];
                *(uint2*)bf = *(const uint2*)(sVt + (((c * 16 + j) * 32 + lane) << 1));
                mma_tf32(o[j], af, bf);
            }
        }
    }

    const float il0 = 1.f / l_run[0];
    const float il1 = 1.f / l_run[1];
    const int row_g = qt * 128 + wid * 16 + (lane >> 2);
    #pragma unroll
    for (int j = 0; j < 16; j++) {
        const int col = h * HD + j * 8 + 2 * (lane & 3);
        float2 v0 = {o[j][0] * il0, o[j][1] * il0};
        float2 v1 = {o[j][2] * il1, o[j][3] * il1};
        *(float2*)(O + (size_t)(b * S_SZ + row_g) * D_SZ + col) = v0;
        *(float2*)(O + (size_t)(b * S_SZ + row_g + 8) * D_SZ + col) = v1;
    }
}

// ---------------- driver ----------------
extern "C" void kernel_launch(void* const* d_in, const int* in_sizes, int n_in,
                              void* d_out, int out_size) {
    const float* hs    = (const float*)d_in[0];
    const float* Wq    = (const float*)d_in[1];
    const float* Wk    = (const float*)d_in[2];
    const float* Wv    = (const float*)d_in[3];
    const float* Wo    = (const float*)d_in[4];
    const float* Win   = (const float*)d_in[5];
    const float* Wout  = (const float*)d_in[6];
    const float* qkf   = (const float*)d_in[7];
    const float* gattn = (const float*)d_in[8];
    const float* gmlp  = (const float*)d_in[9];
    float* out = (float*)d_out;

    float *xn, *q, *k, *v, *attn, *h, *mlp;
    cudaGetSymbolAddress((void**)&xn,   g_xn);
    cudaGetSymbolAddress((void**)&q,    g_q);
    cudaGetSymbolAddress((void**)&k,    g_k);
    cudaGetSymbolAddress((void**)&v,    g_v);
    cudaGetSymbolAddress((void**)&attn, g_attn);
    cudaGetSymbolAddress((void**)&h,    g_h);
    cudaGetSymbolAddress((void**)&mlp,  g_mlp);

    cudaFuncSetAttribute(flash_mma, cudaFuncAttributeMaxDynamicSharedMemorySize, FLASH_SMEM);
    cudaFuncSetAttribute(qkv_mma, cudaFuncAttributeMaxDynamicSharedMemorySize, GEMM_SMEM);
    cudaFuncSetAttribute(gemm_mma<0>, cudaFuncAttributeMaxDynamicSharedMemorySize, GEMM_SMEM);
    cudaFuncSetAttribute(gemm_mma<1>, cudaFuncAttributeMaxDynamicSharedMemorySize, GEMM_SMEM);
    cudaFuncSetAttribute(gemm_mma<2>, cudaFuncAttributeMaxDynamicSharedMemorySize, GEMM_SMEM);

    // 1) pre-attn hypersphere norm
    hnorm_kernel<<<MROWS, 256>>>(hs, gattn, xn);

    // 2) fused QKV projection (one launch, 768 CTAs)
    qkv_mma<<<dim3(MROWS / GBM, 3 * D_SZ / GBN), 256, GEMM_SMEM>>>(
        xn, Wq, Wk, Wv, q, k, v, D_SZ);

    // 3) QK-norm
    const int nvec = MROWS * H_SZ;
    qknorm_kernel<<<nvec / 8, 256>>>(q);
    qknorm_kernel<<<nvec / 8, 256>>>(k);

    // 4) causal attention (tensor-core flash)
    flash_mma<<<dim3(S_SZ / 128, B_SZ * H_SZ), 256, FLASH_SMEM>>>(q, k, v, qkf, attn);

    // 5) output projection + residual
    dim3 gD(MROWS / GBM, D_SZ / GBN);   // (32, 8)
    gemm_mma<2><<<gD, 256, GEMM_SMEM>>>(attn, Wo, hs, h, D_SZ, D_SZ);

    // 6) pre-MLP hypersphere norm
    hnorm_kernel<<<MROWS, 256>>>(h, gmlp, xn);

    // 7) MLP in + exact GELU
    dim3 gF(MROWS / GBM, F_SZ / GBN);   // (32, 32)
    gemm_mma<1><<<gF, 256, GEMM_SMEM>>>(xn, Win, nullptr, mlp, F_SZ, D_SZ);

    // 8) MLP out + residual -> d_out
    gemm_mma<2><<<gD, 256, GEMM_SMEM>>>(mlp, Wout, h, out, D_SZ, F_SZ);
}

// round 10
// speedup vs baseline: 4.0117x; 1.1388x over previous
#include <cuda_runtime.h>
#include <cuda_bf16.h>
#include <math.h>
#include <stdint.h>

#define B_SZ 2
#define S_SZ 2048
#define D_SZ 2048
#define F_SZ 8192
#define H_SZ 16
#define HD   128
#define MROWS (B_SZ * S_SZ)   // 4096

// ---------------- scratch (device globals; no allocation) ----------------
__device__ float g_xn  [MROWS * D_SZ];
__device__ float g_xnp [MROWS * D_SZ];
__device__ float g_q   [MROWS * D_SZ];
__device__ float g_k   [MROWS * D_SZ];
__device__ float g_v   [MROWS * D_SZ];
__device__ float g_attnp[MROWS * D_SZ];
__device__ float g_h   [MROWS * D_SZ];
__device__ float g_mlpp[(size_t)MROWS * F_SZ];
__device__ float g_wqp [D_SZ * D_SZ];
__device__ float g_wkp [D_SZ * D_SZ];
__device__ float g_wvp [D_SZ * D_SZ];
__device__ float g_wop [D_SZ * D_SZ];
__device__ float g_winp[(size_t)F_SZ * D_SZ];
__device__ float g_woutp[(size_t)D_SZ * F_SZ];

// ==================== helpers ====================
__device__ __forceinline__ uint32_t f2tf32(float x) {
    uint32_t r;
    asm("cvt.rna.tf32.f32 %0, %1;" : "=r"(r) : "f"(x));
    return r;
}
__device__ __forceinline__ float f2tf32f(float x) {
    return __uint_as_float(f2tf32(x));
}
__device__ __forceinline__ uint32_t smem_u32(const void* p) {
    uint32_t a;
    asm("{ .reg .u64 t; cvta.to.shared.u64 t, %1; cvt.u32.u64 %0, t; }" : "=r"(a) : "l"(p));
    return a;
}
__device__ __forceinline__ void cp16(uint32_t saddr, const void* g) {
    asm volatile("cp.async.ca.shared.global [%0], [%1], 16;" :: "r"(saddr), "l"(g) : "memory");
}
__device__ __forceinline__ void mma_tf32(float* d, const uint32_t* a, const uint32_t* b) {
    asm volatile(
        "mma.sync.aligned.m16n8k8.row.col.f32.tf32.tf32.f32 "
        "{%0,%1,%2,%3}, {%4,%5,%6,%7}, {%8,%9}, {%0,%1,%2,%3};"
        : "+f"(d[0]), "+f"(d[1]), "+f"(d[2]), "+f"(d[3])
        : "r"(a[0]), "r"(a[1]), "r"(a[2]), "r"(a[3]), "r"(b[0]), "r"(b[1]));
}
__device__ __forceinline__ float gelu_exact(float x) {
    return 0.5f * x * (1.f + erff(x * 0.7071067811865476f));
}

// A-perm flat index for element (row, col) of an [M, Kdim] operand.
// Chunk (mt, kt) = 4096 floats: [s(4)][ma(8)][lane(32)][reg(4)].
__device__ __forceinline__ size_t aperm_idx(int row, int col, int Kdim) {
    const int mt = row >> 7, kt = col >> 5;
    const int s = (col >> 3) & 3, ma = (row >> 4) & 7;
    const int rr = row & 15, cc = col & 7;
    const int lane = (rr & 7) * 4 + (cc & 3);
    const int rg = (rr >> 3) + 2 * (cc >> 2);
    return ((size_t)(mt * (Kdim >> 5) + kt) * 4096) + (((s * 8 + ma) * 32 + lane) << 2) + rg;
}

// ==================== permute kernels (coalesced uint4 writes) ====================
// W[N,K] row-major -> B-frag chunks [nt][kt][2048 u4]: [s(4)][pair(16)][lane(32)] u4
__global__ void permute_w(const float* __restrict__ W, float* __restrict__ Wp, int N, int K) {
    const int u = blockIdx.x * 256 + threadIdx.x;        // uint4 index
    const int chunk = u >> 11, o = u & 2047;
    const int ktn = K >> 5;
    const int nt = chunk / ktn, kt = chunk % ktn;
    const int lane = o & 31, pair = (o >> 5) & 15, s = o >> 9;
    const int nn = lane >> 2, cl = lane & 3;
    const int ne = nt * 256 + pair * 16 + nn;
    const int k0 = kt * 32 + s * 8 + cl;
    uint4 r;
    r.x = f2tf32(W[(size_t)ne * K + k0]);
    r.y = f2tf32(W[(size_t)ne * K + k0 + 4]);
    r.z = f2tf32(W[(size_t)(ne + 8) * K + k0]);
    r.w = f2tf32(W[(size_t)(ne + 8) * K + k0 + 4]);
    ((uint4*)Wp)[u] = r;
}

// A[M,K] row-major -> A-frag chunks [mt][kt][1024 u4]: [s(4)][ma(8)][lane(32)] u4
__global__ void permute_a(const float* __restrict__ A, float* __restrict__ Ap, int K) {
    const int u = blockIdx.x * 256 + threadIdx.x;
    const int chunk = u >> 10, o = u & 1023;
    const int ktn = K >> 5;
    const int mt = chunk / ktn, kt = chunk % ktn;
    const int lane = o & 31, ma = (o >> 5) & 7, s = o >> 8;
    const int rl = lane >> 2, cl = lane & 3;
    const int r0 = mt * 128 + ma * 16 + rl;
    const int k0 = kt * 32 + s * 8 + cl;
    uint4 r;
    r.x = f2tf32(A[(size_t)r0 * K + k0]);
    r.y = f2tf32(A[(size_t)(r0 + 8) * K + k0]);
    r.z = f2tf32(A[(size_t)r0 * K + k0 + 4]);
    r.w = f2tf32(A[(size_t)(r0 + 8) * K + k0 + 4]);
    ((uint4*)Ap)[u] = r;
}

// ==================== cp.async tf32 GEMM on pre-permuted operands ====================
// C[M,N] = A[M,K] @ W[N,K]^T. CTA 128x256, BK=32, 8 warps (2m x 4n), warp 64x64.
// 3-stage cp.async pipeline; stage = 4096(A)+8192(B) floats = 48KB.
#define NSTG 3
#define STAGE_U4 3072
#define GEMMCP_SMEM (NSTG * STAGE_U4 * 16)   // 147456

// EPI: 0 none, 1 GELU, 2 residual. PERMC: write C in A-perm layout (tf32-rounded).
template <int EPI, bool PERMC>
__device__ __forceinline__ void gemm_cp_body(
    const float* __restrict__ Ap, const float* __restrict__ Wp,
    const float* __restrict__ R, float* __restrict__ C,
    int N, int K, int mt, int nt, float* sm) {
    const uint32_t sb = smem_u32(sm);
    const int tid = threadIdx.x, lane = tid & 31, wid = tid >> 5;
    const int wm = wid >> 2, wn = wid & 3;
    const int NT = K >> 5;
    const uint4* Agc = (const uint4*)Ap + (size_t)mt * NT * 1024;
    const uint4* Bgc = (const uint4*)Wp + (size_t)nt * NT * 2048;

    float acc[4][8][4];
    #pragma unroll
    for (int i = 0; i < 4; i++)
        #pragma unroll
        for (int j = 0; j < 8; j++)
            #pragma unroll
            for (int r = 0; r < 4; r++) acc[i][j][r] = 0.f;

    auto issue = [&](int kt) {
        const int st = kt % NSTG;
        const uint32_t sa = sb + st * STAGE_U4 * 16;
        const uint4* ag = Agc + (size_t)kt * 1024;
        const uint4* bg = Bgc + (size_t)kt * 2048;
        #pragma unroll
        for (int i = 0; i < 4; i++)
            cp16(sa + (tid + 256 * i) * 16, ag + tid + 256 * i);
        const uint32_t sbb = sa + 1024 * 16;
        #pragma unroll
        for (int i = 0; i < 8; i++)
            cp16(sbb + (tid + 256 * i) * 16, bg + tid + 256 * i);
        asm volatile("cp.async.commit_group;" ::: "memory");
    };

    issue(0);
    if (NT > 1) issue(1);

    for (int kt = 0; kt < NT; kt++) {
        if (kt + NSTG - 1 < NT)
            asm volatile("cp.async.wait_group 1;" ::: "memory");
        else
            asm volatile("cp.async.wait_group 0;" ::: "memory");
        __syncthreads();
        if (kt + NSTG - 1 < NT) issue(kt + NSTG - 1);

        const float* smA = sm + (kt % NSTG) * STAGE_U4 * 4;
        const float* smB = smA + 4096;
        #pragma unroll
        for (int s = 0; s < 4; s++) {
            uint32_t af[4][4];
            #pragma unroll
            for (int i = 0; i < 4; i++)
                *(uint4*)af[i] = *(const uint4*)(smA + (((s * 8 + wm * 4 + i) * 32 + lane) << 2));
            uint32_t bf[4][4];
            #pragma unroll
            for (int jj = 0; jj < 4; jj++)
                *(uint4*)bf[jj] = *(const uint4*)(smB + (((s * 16 + wn * 4 + jj) * 32 + lane) << 2));
            #pragma unroll
            for (int i = 0; i < 4; i++)
                #pragma unroll
                for (int jj = 0; jj < 4; jj++) {
                    mma_tf32(acc[i][2 * jj],     af[i], bf[jj]);
                    mma_tf32(acc[i][2 * jj + 1], af[i], bf[jj] + 2);
                }
        }
    }

    const int gid = lane >> 2, tig = lane & 3;
    #pragma unroll
    for (int i = 0; i < 4; i++) {
        #pragma unroll
        for (int j = 0; j < 8; j++) {
            const int row0 = mt * 128 + wm * 64 + i * 16 + gid;
            const int col  = nt * 256 + wn * 64 + j * 8 + tig * 2;
            float2 v0 = {acc[i][j][0], acc[i][j][1]};
            float2 v1 = {acc[i][j][2], acc[i][j][3]};
            if (EPI == 2) {
                float2 q0 = *(const float2*)(R + (size_t)row0 * N + col);
                float2 q1 = *(const float2*)(R + (size_t)(row0 + 8) * N + col);
                v0.x += q0.x; v0.y += q0.y;
                v1.x += q1.x; v1.y += q1.y;
            }
            if (EPI == 1) {
                v0.x = gelu_exact(v0.x); v0.y = gelu_exact(v0.y);
                v1.x = gelu_exact(v1.x); v1.y = gelu_exact(v1.y);
            }
            if (PERMC) {
                C[aperm_idx(row0, col, N)]     = f2tf32f(v0.x);
                C[aperm_idx(row0, col + 1, N)] = f2tf32f(v0.y);
                C[aperm_idx(row0 + 8, col, N)]     = f2tf32f(v1.x);
                C[aperm_idx(row0 + 8, col + 1, N)] = f2tf32f(v1.y);
            } else {
                *(float2*)(C + (size_t)row0 * N + col) = v0;
                *(float2*)(C + (size_t)(row0 + 8) * N + col) = v1;
            }
        }
    }
}

template <int EPI, bool PERMC>
__global__ void __launch_bounds__(256, 1)
gemm_cp(const float* __restrict__ Ap, const float* __restrict__ Wp,
        const float* __restrict__ R, float* __restrict__ C, int N, int K) {
    extern __shared__ float sm[];
    gemm_cp_body<EPI, PERMC>(Ap, Wp, R, C, N, K, blockIdx.x, blockIdx.y, sm);
}

// Fused QKV over pre-permuted weights. grid.y = 24: which = y>>3, nt = y&7.
__global__ void __launch_bounds__(256, 1)
qkv_cp(const float* __restrict__ Ap,
       const float* __restrict__ wqp, const float* __restrict__ wkp,
       const float* __restrict__ wvp,
       float* __restrict__ q, float* __restrict__ k, float* __restrict__ v) {
    extern __shared__ float sm[];
    const int which = blockIdx.y >> 3;
    const float* Wp = (which == 0) ? wqp : (which == 1) ? wkp : wvp;
    float* C = (which == 0) ? q : (which == 1) ? k : v;
    gemm_cp_body<0, false>(Ap, Wp, nullptr, C, D_SZ, D_SZ, blockIdx.x, blockIdx.y & 7, sm);
}

// ---------------- hypersphere norm ----------------
__global__ void hnorm_kernel(const float* __restrict__ x, const float* __restrict__ g,
                             float* __restrict__ out) {
    const int row = blockIdx.x;
    const float* xr = x + (size_t)row * D_SZ;
    float ss = 0.f;
    for (int i = threadIdx.x; i < D_SZ; i += blockDim.x) {
        float v = xr[i];
        ss += v * v;
    }
    __shared__ float red[32];
    #pragma unroll
    for (int o = 16; o; o >>= 1) ss += __shfl_xor_sync(0xffffffffu, ss, o);
    if ((threadIdx.x & 31) == 0) red[threadIdx.x >> 5] = ss;
    __syncthreads();
    if (threadIdx.x < 32) {
        float v = (threadIdx.x < (blockDim.x >> 5)) ? red[threadIdx.x] : 0.f;
        #pragma unroll
        for (int o = 16; o; o >>= 1) v += __shfl_xor_sync(0xffffffffu, v, o);
        if (threadIdx.x == 0) red[0] = v;
    }
    __syncthreads();
    const float n = sqrtf(red[0]);
    const float scale = 45.254833995939045f / (n + 1e-6f);
    float* orow = out + (size_t)row * D_SZ;
    for (int i = threadIdx.x; i < D_SZ; i += blockDim.x)
        orow[i] = xr[i] * scale * g[i];
}

// ---------------- QK-norm ----------------
__global__ void qknorm_kernel(float* __restrict__ q) {
    const int vec = blockIdx.x * (blockDim.x >> 5) + (threadIdx.x >> 5);
    const int lane = threadIdx.x & 31;
    float* p = q + (size_t)vec * HD;
    float4 v = ((float4*)p)[lane];
    float ss = v.x * v.x + v.y * v.y + v.z * v.z + v.w * v.w;
    #pragma unroll
    for (int o = 16; o; o >>= 1) ss += __shfl_xor_sync(0xffffffffu, ss, o);
    const float s = 1.f / (sqrtf(ss) + 1e-6f);
    v.x *= s; v.y *= s; v.z *= s; v.w *= s;
    ((float4*)p)[lane] = v;
}

// ==================== Flash attention via mma.sync tf32 ====================
// Unchanged from R8/R9 except: epilogue writes O in A-perm layout (for Wo GEMM).
#define FL_SQ  0
#define FL_SK  16384
#define FL_SVT 24576
#define FL_SP  32768
#define FLASH_SMEM (40960 * 4)

__global__ void __launch_bounds__(256, 1)
flash_mma(const float* __restrict__ Q, const float* __restrict__ K,
          const float* __restrict__ V, const float* __restrict__ scale_p,
          float* __restrict__ O) {
    extern __shared__ float fs[];
    float* sQ  = fs + FL_SQ;
    float* sK  = fs + FL_SK;
    float* sVt = fs + FL_SVT;
    float* sP  = fs + FL_SP;

    const int qt = gridDim.x - 1 - blockIdx.x;
    const int bh = blockIdx.y;
    const int b = bh >> 4, h = bh & 15;
    const float scale = *scale_p;
    const int tid = threadIdx.x;
    const int lane = tid & 31;
    const int wid = tid >> 5;

    const size_t base = (size_t)b * S_SZ * D_SZ + (size_t)h * HD;

    {
        const int r = tid >> 1;
        const int ma = r >> 4, rr = r & 15;
        #pragma unroll
        for (int i = 0; i < 16; i++) {
            const int c4 = (tid & 1) * 16 + i;
            float4 v = *(const float4*)(Q + base + (size_t)(qt * 128 + r) * D_SZ + c4 * 4);
            const int chunk = c4 >> 1, ch = c4 & 1;
            float* da = sQ + (((chunk * 8 + ma) * 32 + (rr & 7) * 4) << 2) + ((rr >> 3) + 2 * ch);
            da[0]  = f2tf32f(v.x * scale);
            da[4]  = f2tf32f(v.y * scale);
            da[8]  = f2tf32f(v.z * scale);
            da[12] = f2tf32f(v.w * scale);
        }
    }

    float o[16][4];
    #pragma unroll
    for (int i = 0; i < 16; i++)
        #pragma unroll
        for (int r = 0; r < 4; r++) o[i][r] = 0.f;
    float m_run[2] = {-INFINITY, -INFINITY};
    float l_run[2] = {0.f, 0.f};

    const int NKT = 2 * qt + 2;
    for (int kt = 0; kt < NKT; kt++) {
        __syncthreads();
        {
            const int n0 = tid >> 2;
            #pragma unroll
            for (int i = 0; i < 8; i++) {
                const int c4i = (tid & 3) + 4 * i;
                const int d0 = c4i * 4;
                float4 kv = *(const float4*)(K + base + (size_t)(kt * 64 + n0) * D_SZ + d0);
                float* dk = sK + (((((d0 >> 3) * 8) + (n0 >> 3)) * 32 + (n0 & 7) * 4) << 1) + (c4i & 1);
                dk[0] = f2tf32f(kv.x);
                dk[2] = f2tf32f(kv.y);
                dk[4] = f2tf32f(kv.z);
                dk[6] = f2tf32f(kv.w);
                float4 vv = *(const float4*)(V + base + (size_t)(kt * 64 + n0) * D_SZ + d0);
                float* dv = sVt + ((((n0 >> 3) * 16 + (c4i >> 1)) * 32 + ((c4i & 1) * 4) * 4 + (n0 & 3)) << 1)
                          + ((n0 & 7) >> 2);
                dv[0]  = f2tf32f(vv.x);
                dv[8]  = f2tf32f(vv.y);
                dv[16] = f2tf32f(vv.z);
                dv[24] = f2tf32f(vv.w);
            }
        }
        __syncthreads();

        float sacc[8][4];
        #pragma unroll
        for (int j = 0; j < 8; j++)
            #pragma unroll
            for (int r = 0; r < 4; r++) sacc[j][r] = 0.f;
        #pragma unroll
        for (int c = 0; c < 16; c++) {
            uint32_t af[4];
            *(uint4*)af = *(const uint4*)(sQ + (((c * 8 + wid) * 32 + lane) << 2));
            #pragma unroll
            for (int j = 0; j < 8; j++) {
                uint32_t bf[2];
                *(uint2*)bf = *(const uint2*)(sK + (((c * 8 + j) * 32 + lane) << 1));
                mma_tf32(sacc[j], af, bf);
            }
        }

        if (kt >= 2 * qt) {
            const int rbase = qt * 128 + wid * 16 + (lane >> 2);
            const int cbase = kt * 64 + 2 * (lane & 3);
            #pragma unroll
            for (int j = 0; j < 8; j++)
                #pragma unroll
                for (int r = 0; r < 4; r++) {
                    const int row = rbase + ((r >> 1) << 3);
                    const int col = cbase + j * 8 + (r & 1);
                    if (col > row) sacc[j][r] = -INFINITY;
                }
        }

        #pragma unroll
        for (int hh = 0; hh < 2; hh++) {
            float mt = -INFINITY;
            #pragma unroll
            for (int j = 0; j < 8; j++)
                mt = fmaxf(mt, fmaxf(sacc[j][2 * hh], sacc[j][2 * hh + 1]));
            mt = fmaxf(mt, __shfl_xor_sync(0xffffffffu, mt, 1));
            mt = fmaxf(mt, __shfl_xor_sync(0xffffffffu, mt, 2));
            const bool skip = (mt == -INFINITY);
            const float mold = m_run[hh];
            const float mnew = skip ? mold : fmaxf(mold, mt);
            const float msafe = (mnew == -INFINITY) ? 0.f : mnew;
            const float alpha = skip ? 1.f : __expf(mold - mnew);
            float sum = 0.f;
            #pragma unroll
            for (int j = 0; j < 8; j++) {
                float p0 = __expf(sacc[j][2 * hh]     - msafe);
                float p1 = __expf(sacc[j][2 * hh + 1] - msafe);
                sacc[j][2 * hh]     = p0;
                sacc[j][2 * hh + 1] = p1;
                sum += p0 + p1;
            }
            sum += __shfl_xor_sync(0xffffffffu, sum, 1);
            sum += __shfl_xor_sync(0xffffffffu, sum, 2);
            l_run[hh] = l_run[hh] * alpha + sum;
            m_run[hh] = mnew;
            #pragma unroll
            for (int j = 0; j < 16; j++) {
                o[j][2 * hh]     *= alpha;
                o[j][2 * hh + 1] *= alpha;
            }
        }

        __syncwarp();
        {
            const int rlow = lane >> 2, q = lane & 3;
            #pragma unroll
            for (int j = 0; j < 8; j++) {
                #pragma unroll
                for (int hh = 0; hh < 2; hh++) {
                    #pragma unroll
                    for (int bb = 0; bb < 2; bb++) {
                        const int cc = 2 * q + bb;
                        const int lt = rlow * 4 + (cc & 3);
                        const int rt = hh + 2 * (cc >> 2);
                        sP[(((j * 8 + wid) * 32 + lt) << 2) + rt] = f2tf32f(sacc[j][2 * hh + bb]);
                    }
                }
            }
        }
        __syncwarp();

        #pragma unroll
        for (int c = 0; c < 8; c++) {
            uint32_t af[4];
            *(uint4*)af = *(const uint4*)(sP + (((c * 8 + wid) * 32 + lane) << 2));
            #pragma unroll
            for (int j = 0; j < 16; j++) {
                uint32_t bf[2];
                *(uint2*)bf = *(const uint2*)(sVt + (((c * 16 + j) * 32 + lane) << 1));
                mma_tf32(o[j], af, bf);
            }
        }
    }

    // epilogue: normalize and write in A-perm layout (tf32-rounded)
    const float il0 = 1.f / l_run[0];
    const float il1 = 1.f / l_run[1];
    const int grow = b * S_SZ + qt * 128 + wid * 16 + (lane >> 2);
    #pragma unroll
    for (int j = 0; j < 16; j++) {
        const int col = h * HD + j * 8 + 2 * (lane & 3);
        O[aperm_idx(grow, col, D_SZ)]     = f2tf32f(o[j][0] * il0);
        O[aperm_idx(grow, col + 1, D_SZ)] = f2tf32f(o[j][1] * il0);
        O[aperm_idx(grow + 8, col, D_SZ)]     = f2tf32f(o[j][2] * il1);
        O[aperm_idx(grow + 8, col + 1, D_SZ)] = f2tf32f(o[j][3] * il1);
    }
}

// ---------------- driver ----------------
extern "C" void kernel_launch(void* const* d_in, const int* in_sizes, int n_in,
                              void* d_out, int out_size) {
    const float* hs    = (const float*)d_in[0];
    const float* Wq    = (const float*)d_in[1];
    const float* Wk    = (const float*)d_in[2];
    const float* Wv    = (const float*)d_in[3];
    const float* Wo    = (const float*)d_in[4];
    const float* Win   = (const float*)d_in[5];
    const float* Wout  = (const float*)d_in[6];
    const float* qkf   = (const float*)d_in[7];
    const float* gattn = (const float*)d_in[8];
    const float* gmlp  = (const float*)d_in[9];
    float* out = (float*)d_out;

    float *xn, *xnp, *q, *k, *v, *attnp, *h, *mlpp;
    float *wqp, *wkp, *wvp, *wop, *winp, *woutp;
    cudaGetSymbolAddress((void**)&xn,    g_xn);
    cudaGetSymbolAddress((void**)&xnp,   g_xnp);
    cudaGetSymbolAddress((void**)&q,     g_q);
    cudaGetSymbolAddress((void**)&k,     g_k);
    cudaGetSymbolAddress((void**)&v,     g_v);
    cudaGetSymbolAddress((void**)&attnp, g_attnp);
    cudaGetSymbolAddress((void**)&h,     g_h);
    cudaGetSymbolAddress((void**)&mlpp,  g_mlpp);
    cudaGetSymbolAddress((void**)&wqp,   g_wqp);
    cudaGetSymbolAddress((void**)&wkp,   g_wkp);
    cudaGetSymbolAddress((void**)&wvp,   g_wvp);
    cudaGetSymbolAddress((void**)&wop,   g_wop);
    cudaGetSymbolAddress((void**)&winp,  g_winp);
    cudaGetSymbolAddress((void**)&woutp, g_woutp);

    cudaFuncSetAttribute(flash_mma, cudaFuncAttributeMaxDynamicSharedMemorySize, FLASH_SMEM);
    cudaFuncSetAttribute(qkv_cp, cudaFuncAttributeMaxDynamicSharedMemorySize, GEMMCP_SMEM);
    cudaFuncSetAttribute(gemm_cp<1, true>,  cudaFuncAttributeMaxDynamicSharedMemorySize, GEMMCP_SMEM);
    cudaFuncSetAttribute(gemm_cp<2, false>, cudaFuncAttributeMaxDynamicSharedMemorySize, GEMMCP_SMEM);

    // 0) pre-permute weights into fragment order (tf32-rounded)
    permute_w<<<D_SZ * D_SZ / 1024, 256>>>(Wq, wqp, D_SZ, D_SZ);
    permute_w<<<D_SZ * D_SZ / 1024, 256>>>(Wk, wkp, D_SZ, D_SZ);
    permute_w<<<D_SZ * D_SZ / 1024, 256>>>(Wv, wvp, D_SZ, D_SZ);
    permute_w<<<D_SZ * D_SZ / 1024, 256>>>(Wo, wop, D_SZ, D_SZ);
    permute_w<<<F_SZ * D_SZ / 1024, 256>>>(Win, winp, F_SZ, D_SZ);
    permute_w<<<F_SZ * D_SZ / 1024, 256>>>(Wout, woutp, D_SZ, F_SZ);

    // 1) pre-attn hypersphere norm + A-permute
    hnorm_kernel<<<MROWS, 256>>>(hs, gattn, xn);
    permute_a<<<MROWS * D_SZ / 1024, 256>>>(xn, xnp, D_SZ);

    // 2) fused QKV projection
    qkv_cp<<<dim3(MROWS / 128, 24), 256, GEMMCP_SMEM>>>(xnp, wqp, wkp, wvp, q, k, v);

    // 3) QK-norm
    const int nvec = MROWS * H_SZ;
    qknorm_kernel<<<nvec / 8, 256>>>(q);
    qknorm_kernel<<<nvec / 8, 256>>>(k);

    // 4) causal attention -> attn in A-perm layout
    flash_mma<<<dim3(S_SZ / 128, B_SZ * H_SZ), 256, FLASH_SMEM>>>(q, k, v, qkf, attnp);

    // 5) output projection + residual -> h (normal layout)
    gemm_cp<2, false><<<dim3(32, 8), 256, GEMMCP_SMEM>>>(attnp, wop, hs, h, D_SZ, D_SZ);

    // 6) pre-MLP hypersphere norm + A-permute
    hnorm_kernel<<<MROWS, 256>>>(h, gmlp, xn);
    permute_a<<<MROWS * D_SZ / 1024, 256>>>(xn, xnp, D_SZ);

    // 7) MLP in + GELU -> mlp in A-perm layout
    gemm_cp<1, true><<<dim3(32, 32), 256, GEMMCP_SMEM>>>(xnp, winp, nullptr, mlpp, F_SZ, D_SZ);

    // 8) MLP out + residual -> d_out (normal layout)
    gemm_cp<2, false><<<dim3(32, 8), 256, GEMMCP_SMEM>>>(mlpp, woutp, h, out, D_SZ, F_SZ);
}

// round 11
// speedup vs baseline: 4.0296x; 1.0045x over previous
#include <cuda_runtime.h>
#include <cuda_bf16.h>
#include <math.h>
#include <stdint.h>

#define B_SZ 2
#define S_SZ 2048
#define D_SZ 2048
#define F_SZ 8192
#define H_SZ 16
#define HD   128
#define MROWS (B_SZ * S_SZ)   // 4096

// ---------------- scratch (device globals; no allocation) ----------------
__device__ float g_xnp [MROWS * D_SZ];
__device__ float g_q   [MROWS * D_SZ];
__device__ float g_k   [MROWS * D_SZ];
__device__ float g_v   [MROWS * D_SZ];
__device__ float g_attnp[MROWS * D_SZ];
__device__ float g_h   [MROWS * D_SZ];
__device__ float g_mlpp[(size_t)MROWS * F_SZ];
__device__ float g_wqp [D_SZ * D_SZ];
__device__ float g_wkp [D_SZ * D_SZ];
__device__ float g_wvp [D_SZ * D_SZ];
__device__ float g_wop [D_SZ * D_SZ];
__device__ float g_winp[(size_t)F_SZ * D_SZ];
__device__ float g_woutp[(size_t)D_SZ * F_SZ];

// ==================== helpers ====================
__device__ __forceinline__ uint32_t f2tf32(float x) {
    uint32_t r;
    asm("cvt.rna.tf32.f32 %0, %1;" : "=r"(r) : "f"(x));
    return r;
}
__device__ __forceinline__ float f2tf32f(float x) {
    return __uint_as_float(f2tf32(x));
}
__device__ __forceinline__ uint32_t smem_u32(const void* p) {
    uint32_t a;
    asm("{ .reg .u64 t; cvta.to.shared.u64 t, %1; cvt.u32.u64 %0, t; }" : "=r"(a) : "l"(p));
    return a;
}
__device__ __forceinline__ void cp16(uint32_t saddr, const void* g) {
    asm volatile("cp.async.ca.shared.global [%0], [%1], 16;" :: "r"(saddr), "l"(g) : "memory");
}
__device__ __forceinline__ void mma_tf32(float* d, const uint32_t* a, const uint32_t* b) {
    asm volatile(
        "mma.sync.aligned.m16n8k8.row.col.f32.tf32.tf32.f32 "
        "{%0,%1,%2,%3}, {%4,%5,%6,%7}, {%8,%9}, {%0,%1,%2,%3};"
        : "+f"(d[0]), "+f"(d[1]), "+f"(d[2]), "+f"(d[3])
        : "r"(a[0]), "r"(a[1]), "r"(a[2]), "r"(a[3]), "r"(b[0]), "r"(b[1]));
}
__device__ __forceinline__ float gelu_exact(float x) {
    return 0.5f * x * (1.f + erff(x * 0.7071067811865476f));
}

// A-perm flat index for element (row, col) of an [M, Kdim] operand.
// Chunk (mt, kt) = 4096 floats: [s(4)][ma(8)][lane(32)][reg(4)].
__device__ __forceinline__ size_t aperm_idx(int row, int col, int Kdim) {
    const int mt = row >> 7, kt = col >> 5;
    const int s = (col >> 3) & 3, ma = (row >> 4) & 7;
    const int rr = row & 15, cc = col & 7;
    const int lane = (rr & 7) * 4 + (cc & 3);
    const int rg = (rr >> 3) + 2 * (cc >> 2);
    return ((size_t)(mt * (Kdim >> 5) + kt) * 4096) + (((s * 8 + ma) * 32 + lane) << 2) + rg;
}

// ==================== permute kernels (coalesced uint4 writes) ====================
// W[N,K] row-major -> B-frag chunks [nt][kt][2048 u4]: [s(4)][pair(16)][lane(32)] u4
__global__ void permute_w(const float* __restrict__ W, float* __restrict__ Wp, int N, int K) {
    const int u = blockIdx.x * 256 + threadIdx.x;        // uint4 index
    const int chunk = u >> 11, o = u & 2047;
    const int ktn = K >> 5;
    const int nt = chunk / ktn, kt = chunk % ktn;
    const int lane = o & 31, pair = (o >> 5) & 15, s = o >> 9;
    const int nn = lane >> 2, cl = lane & 3;
    const int ne = nt * 256 + pair * 16 + nn;
    const int k0 = kt * 32 + s * 8 + cl;
    uint4 r;
    r.x = f2tf32(W[(size_t)ne * K + k0]);
    r.y = f2tf32(W[(size_t)ne * K + k0 + 4]);
    r.z = f2tf32(W[(size_t)(ne + 8) * K + k0]);
    r.w = f2tf32(W[(size_t)(ne + 8) * K + k0 + 4]);
    ((uint4*)Wp)[u] = r;
}

// ==================== cp.async tf32 GEMM on pre-permuted operands ====================
// C[M,N] = A[M,K] @ W[N,K]^T. CTA 128x256, BK=32, 8 warps (2m x 4n), warp 64x64.
// 3-stage cp.async pipeline; stage = 4096(A)+8192(B) floats = 48KB.
#define NSTG 3
#define STAGE_U4 3072
#define GEMMCP_SMEM (NSTG * STAGE_U4 * 16)   // 147456

// EPI: 0 none, 1 GELU, 2 residual. PERMC: write C in A-perm layout (tf32-rounded).
template <int EPI, bool PERMC>
__device__ __forceinline__ void gemm_cp_body(
    const float* __restrict__ Ap, const float* __restrict__ Wp,
    const float* __restrict__ R, float* __restrict__ C,
    int N, int K, int mt, int nt, float* sm) {
    const uint32_t sb = smem_u32(sm);
    const int tid = threadIdx.x, lane = tid & 31, wid = tid >> 5;
    const int wm = wid >> 2, wn = wid & 3;
    const int NT = K >> 5;
    const uint4* Agc = (const uint4*)Ap + (size_t)mt * NT * 1024;
    const uint4* Bgc = (const uint4*)Wp + (size_t)nt * NT * 2048;

    float acc[4][8][4];
    #pragma unroll
    for (int i = 0; i < 4; i++)
        #pragma unroll
        for (int j = 0; j < 8; j++)
            #pragma unroll
            for (int r = 0; r < 4; r++) acc[i][j][r] = 0.f;

    auto issue = [&](int kt) {
        const int st = kt % NSTG;
        const uint32_t sa = sb + st * STAGE_U4 * 16;
        const uint4* ag = Agc + (size_t)kt * 1024;
        const uint4* bg = Bgc + (size_t)kt * 2048;
        #pragma unroll
        for (int i = 0; i < 4; i++)
            cp16(sa + (tid + 256 * i) * 16, ag + tid + 256 * i);
        const uint32_t sbb = sa + 1024 * 16;
        #pragma unroll
        for (int i = 0; i < 8; i++)
            cp16(sbb + (tid + 256 * i) * 16, bg + tid + 256 * i);
        asm volatile("cp.async.commit_group;" ::: "memory");
    };

    issue(0);
    if (NT > 1) issue(1);

    for (int kt = 0; kt < NT; kt++) {
        if (kt + NSTG - 1 < NT)
            asm volatile("cp.async.wait_group 1;" ::: "memory");
        else
            asm volatile("cp.async.wait_group 0;" ::: "memory");
        __syncthreads();
        if (kt + NSTG - 1 < NT) issue(kt + NSTG - 1);

        const float* smA = sm + (kt % NSTG) * STAGE_U4 * 4;
        const float* smB = smA + 4096;
        #pragma unroll
        for (int s = 0; s < 4; s++) {
            uint32_t af[4][4];
            #pragma unroll
            for (int i = 0; i < 4; i++)
                *(uint4*)af[i] = *(const uint4*)(smA + (((s * 8 + wm * 4 + i) * 32 + lane) << 2));
            uint32_t bf[4][4];
            #pragma unroll
            for (int jj = 0; jj < 4; jj++)
                *(uint4*)bf[jj] = *(const uint4*)(smB + (((s * 16 + wn * 4 + jj) * 32 + lane) << 2));
            #pragma unroll
            for (int i = 0; i < 4; i++)
                #pragma unroll
                for (int jj = 0; jj < 4; jj++) {
                    mma_tf32(acc[i][2 * jj],     af[i], bf[jj]);
                    mma_tf32(acc[i][2 * jj + 1], af[i], bf[jj] + 2);
                }
        }
    }

    const int gid = lane >> 2, tig = lane & 3;
    #pragma unroll
    for (int i = 0; i < 4; i++) {
        #pragma unroll
        for (int j = 0; j < 8; j++) {
            const int row0 = mt * 128 + wm * 64 + i * 16 + gid;
            const int col  = nt * 256 + wn * 64 + j * 8 + tig * 2;
            float2 v0 = {acc[i][j][0], acc[i][j][1]};
            float2 v1 = {acc[i][j][2], acc[i][j][3]};
            if (EPI == 2) {
                float2 q0 = *(const float2*)(R + (size_t)row0 * N + col);
                float2 q1 = *(const float2*)(R + (size_t)(row0 + 8) * N + col);
                v0.x += q0.x; v0.y += q0.y;
                v1.x += q1.x; v1.y += q1.y;
            }
            if (EPI == 1) {
                v0.x = gelu_exact(v0.x); v0.y = gelu_exact(v0.y);
                v1.x = gelu_exact(v1.x); v1.y = gelu_exact(v1.y);
            }
            if (PERMC) {
                C[aperm_idx(row0, col, N)]     = f2tf32f(v0.x);
                C[aperm_idx(row0, col + 1, N)] = f2tf32f(v0.y);
                C[aperm_idx(row0 + 8, col, N)]     = f2tf32f(v1.x);
                C[aperm_idx(row0 + 8, col + 1, N)] = f2tf32f(v1.y);
            } else {
                *(float2*)(C + (size_t)row0 * N + col) = v0;
                *(float2*)(C + (size_t)(row0 + 8) * N + col) = v1;
            }
        }
    }
}

template <int EPI, bool PERMC>
__global__ void __launch_bounds__(256, 1)
gemm_cp(const float* __restrict__ Ap, const float* __restrict__ Wp,
        const float* __restrict__ R, float* __restrict__ C, int N, int K) {
    extern __shared__ float sm[];
    gemm_cp_body<EPI, PERMC>(Ap, Wp, R, C, N, K, blockIdx.x, blockIdx.y, sm);
}

// Fused QKV over pre-permuted weights. grid.y = 24: which = y>>3, nt = y&7.
__global__ void __launch_bounds__(256, 1)
qkv_cp(const float* __restrict__ Ap,
       const float* __restrict__ wqp, const float* __restrict__ wkp,
       const float* __restrict__ wvp,
       float* __restrict__ q, float* __restrict__ k, float* __restrict__ v) {
    extern __shared__ float sm[];
    const int which = blockIdx.y >> 3;
    const float* Wp = (which == 0) ? wqp : (which == 1) ? wkp : wvp;
    float* C = (which == 0) ? q : (which == 1) ? k : v;
    gemm_cp_body<0, false>(Ap, Wp, nullptr, C, D_SZ, D_SZ, blockIdx.x, blockIdx.y & 7, sm);
}

// ---------------- fused hypersphere norm + A-permute ----------------
// out[aperm(row, col)] = tf32( x[row,col] / (||x_row||+eps) * sqrt(D) * g[col] )
__global__ void hnorm_perm(const float* __restrict__ x, const float* __restrict__ g,
                           float* __restrict__ Ap) {
    const int row = blockIdx.x;
    const float* xr = x + (size_t)row * D_SZ;
    float ss = 0.f;
    for (int i = threadIdx.x; i < D_SZ; i += blockDim.x) {
        float v = xr[i];
        ss += v * v;
    }
    __shared__ float red[32];
    #pragma unroll
    for (int o = 16; o; o >>= 1) ss += __shfl_xor_sync(0xffffffffu, ss, o);
    if ((threadIdx.x & 31) == 0) red[threadIdx.x >> 5] = ss;
    __syncthreads();
    if (threadIdx.x < 32) {
        float v = (threadIdx.x < (blockDim.x >> 5)) ? red[threadIdx.x] : 0.f;
        #pragma unroll
        for (int o = 16; o; o >>= 1) v += __shfl_xor_sync(0xffffffffu, v, o);
        if (threadIdx.x == 0) red[0] = v;
    }
    __syncthreads();
    const float n = sqrtf(red[0]);
    const float scale = 45.254833995939045f / (n + 1e-6f);  // sqrt(2048)
    // permuted writes (reads hit L1/L2 from the reduction pass)
    #pragma unroll
    for (int i = 0; i < 8; i++) {
        const int col = threadIdx.x + 256 * i;
        Ap[aperm_idx(row, col, D_SZ)] = f2tf32f(xr[col] * scale * g[col]);
    }
}

// ==================== Flash attention via mma.sync tf32 ====================
// QK-norm fused into staging: Q/K rows unit-normalized (eps 1e-6) during
// fragment staging; qk scale folded into Q. Epilogue writes A-perm layout.
#define FL_SQ  0
#define FL_SK  16384
#define FL_SVT 24576
#define FL_SP  32768
#define FLASH_SMEM (40960 * 4)

__global__ void __launch_bounds__(256, 1)
flash_mma(const float* __restrict__ Q, const float* __restrict__ K,
          const float* __restrict__ V, const float* __restrict__ scale_p,
          float* __restrict__ O) {
    extern __shared__ float fs[];
    float* sQ  = fs + FL_SQ;
    float* sK  = fs + FL_SK;
    float* sVt = fs + FL_SVT;
    float* sP  = fs + FL_SP;

    const int qt = gridDim.x - 1 - blockIdx.x;
    const int bh = blockIdx.y;
    const int b = bh >> 4, h = bh & 15;
    const float scale = *scale_p;
    const int tid = threadIdx.x;
    const int lane = tid & 31;
    const int wid = tid >> 5;

    const size_t base = (size_t)b * S_SZ * D_SZ + (size_t)h * HD;

    // ---- stage Q tile: fused row-norm (2 lanes/row) + qk scale + A-frag ----
    {
        const int r = tid >> 1;
        const int ma = r >> 4, rr = r & 15;
        const float* qrow = Q + base + (size_t)(qt * 128 + r) * D_SZ;
        float ssq = 0.f;
        #pragma unroll
        for (int i = 0; i < 16; i++) {
            const int c4 = (tid & 1) * 16 + i;
            float4 v = *(const float4*)(qrow + c4 * 4);
            ssq += v.x * v.x + v.y * v.y + v.z * v.z + v.w * v.w;
        }
        ssq += __shfl_xor_sync(0xffffffffu, ssq, 1);
        const float qs = scale / (sqrtf(ssq) + 1e-6f);
        #pragma unroll
        for (int i = 0; i < 16; i++) {
            const int c4 = (tid & 1) * 16 + i;
            float4 v = *(const float4*)(qrow + c4 * 4);
            const int chunk = c4 >> 1, ch = c4 & 1;
            float* da = sQ + (((chunk * 8 + ma) * 32 + (rr & 7) * 4) << 2) + ((rr >> 3) + 2 * ch);
            da[0]  = f2tf32f(v.x * qs);
            da[4]  = f2tf32f(v.y * qs);
            da[8]  = f2tf32f(v.z * qs);
            da[12] = f2tf32f(v.w * qs);
        }
    }

    float o[16][4];
    #pragma unroll
    for (int i = 0; i < 16; i++)
        #pragma unroll
        for (int r = 0; r < 4; r++) o[i][r] = 0.f;
    float m_run[2] = {-INFINITY, -INFINITY};
    float l_run[2] = {0.f, 0.f};

    const int NKT = 2 * qt + 2;
    for (int kt = 0; kt < NKT; kt++) {
        __syncthreads();
        // ---- stage K (fused row-norm, 4 lanes/row) and V^T ----
        {
            const int n0 = tid >> 2;
            const float* krow = K + base + (size_t)(kt * 64 + n0) * D_SZ;
            const float* vrow = V + base + (size_t)(kt * 64 + n0) * D_SZ;
            float ssk = 0.f;
            #pragma unroll
            for (int i = 0; i < 8; i++) {
                const int c4i = (tid & 3) + 4 * i;
                float4 kv = *(const float4*)(krow + c4i * 4);
                ssk += kv.x * kv.x + kv.y * kv.y + kv.z * kv.z + kv.w * kv.w;
            }
            ssk += __shfl_xor_sync(0xffffffffu, ssk, 1);
            ssk += __shfl_xor_sync(0xffffffffu, ssk, 2);
            const float ks = 1.f / (sqrtf(ssk) + 1e-6f);
            #pragma unroll
            for (int i = 0; i < 8; i++) {
                const int c4i = (tid & 3) + 4 * i;
                const int d0 = c4i * 4;
                float4 kv = *(const float4*)(krow + d0);
                float* dk = sK + (((((d0 >> 3) * 8) + (n0 >> 3)) * 32 + (n0 & 7) * 4) << 1) + (c4i & 1);
                dk[0] = f2tf32f(kv.x * ks);
                dk[2] = f2tf32f(kv.y * ks);
                dk[4] = f2tf32f(kv.z * ks);
                dk[6] = f2tf32f(kv.w * ks);
                float4 vv = *(const float4*)(vrow + d0);
                float* dv = sVt + ((((n0 >> 3) * 16 + (c4i >> 1)) * 32 + ((c4i & 1) * 4) * 4 + (n0 & 3)) << 1)
                          + ((n0 & 7) >> 2);
                dv[0]  = f2tf32f(vv.x);
                dv[8]  = f2tf32f(vv.y);
                dv[16] = f2tf32f(vv.z);
                dv[24] = f2tf32f(vv.w);
            }
        }
        __syncthreads();

        float sacc[8][4];
        #pragma unroll
        for (int j = 0; j < 8; j++)
            #pragma unroll
            for (int r = 0; r < 4; r++) sacc[j][r] = 0.f;
        #pragma unroll
        for (int c = 0; c < 16; c++) {
            uint32_t af[4];
            *(uint4*)af = *(const uint4*)(sQ + (((c * 8 + wid) * 32 + lane) << 2));
            #pragma unroll
            for (int j = 0; j < 8; j++) {
                uint32_t bf[2];
                *(uint2*)bf = *(const uint2*)(sK + (((c * 8 + j) * 32 + lane) << 1));
                mma_tf32(sacc[j], af, bf);
            }
        }

        if (kt >= 2 * qt) {
            const int rbase = qt * 128 + wid * 16 + (lane >> 2);
            const int cbase = kt * 64 + 2 * (lane & 3);
            #pragma unroll
            for (int j = 0; j < 8; j++)
                #pragma unroll
                for (int r = 0; r < 4; r++) {
                    const int row = rbase + ((r >> 1) << 3);
                    const int col = cbase + j * 8 + (r & 1);
                    if (col > row) sacc[j][r] = -INFINITY;
                }
        }

        #pragma unroll
        for (int hh = 0; hh < 2; hh++) {
            float mt = -INFINITY;
            #pragma unroll
            for (int j = 0; j < 8; j++)
                mt = fmaxf(mt, fmaxf(sacc[j][2 * hh], sacc[j][2 * hh + 1]));
            mt = fmaxf(mt, __shfl_xor_sync(0xffffffffu, mt, 1));
            mt = fmaxf(mt, __shfl_xor_sync(0xffffffffu, mt, 2));
            const bool skip = (mt == -INFINITY);
            const float mold = m_run[hh];
            const float mnew = skip ? mold : fmaxf(mold, mt);
            const float msafe = (mnew == -INFINITY) ? 0.f : mnew;
            const float alpha = skip ? 1.f : __expf(mold - mnew);
            float sum = 0.f;
            #pragma unroll
            for (int j = 0; j < 8; j++) {
                float p0 = __expf(sacc[j][2 * hh]     - msafe);
                float p1 = __expf(sacc[j][2 * hh + 1] - msafe);
                sacc[j][2 * hh]     = p0;
                sacc[j][2 * hh + 1] = p1;
                sum += p0 + p1;
            }
            sum += __shfl_xor_sync(0xffffffffu, sum, 1);
            sum += __shfl_xor_sync(0xffffffffu, sum, 2);
            l_run[hh] = l_run[hh] * alpha + sum;
            m_run[hh] = mnew;
            #pragma unroll
            for (int j = 0; j < 16; j++) {
                o[j][2 * hh]     *= alpha;
                o[j][2 * hh + 1] *= alpha;
            }
        }

        __syncwarp();
        {
            const int rlow = lane >> 2, q = lane & 3;
            #pragma unroll
            for (int j = 0; j < 8; j++) {
                #pragma unroll
                for (int hh = 0; hh < 2; hh++) {
                    #pragma unroll
                    for (int bb = 0; bb < 2; bb++) {
                        const int cc = 2 * q + bb;
                        const int lt = rlow * 4 + (cc & 3);
                        const int rt = hh + 2 * (cc >> 2);
                        sP[(((j * 8 + wid) * 32 + lt) << 2) + rt] = f2tf32f(sacc[j][2 * hh + bb]);
                    }
                }
            }
        }
        __syncwarp();

        #pragma unroll
        for (int c = 0; c < 8; c++) {
            uint32_t af[4];
            *(uint4*)af = *(const uint4*)(sP + (((c * 8 + wid) * 32 + lane) << 2));
            #pragma unroll
            for (int j = 0; j < 16; j++) {
                uint32_t bf[2];
                *(uint2*)bf = *(const uint2*)(sVt + (((c * 16 + j) * 32 + lane) << 1));
                mma_tf32(o[j], af, bf);
            }
        }
    }

    // epilogue: normalize and write in A-perm layout (tf32-rounded)
    const float il0 = 1.f / l_run[0];
    const float il1 = 1.f / l_run[1];
    const int grow = b * S_SZ + qt * 128 + wid * 16 + (lane >> 2);
    #pragma unroll
    for (int j = 0; j < 16; j++) {
        const int col = h * HD + j * 8 + 2 * (lane & 3);
        O[aperm_idx(grow, col, D_SZ)]     = f2tf32f(o[j][0] * il0);
        O[aperm_idx(grow, col + 1, D_SZ)] = f2tf32f(o[j][1] * il0);
        O[aperm_idx(grow + 8, col, D_SZ)]     = f2tf32f(o[j][2] * il1);
        O[aperm_idx(grow + 8, col + 1, D_SZ)] = f2tf32f(o[j][3] * il1);
    }
}

// ---------------- driver ----------------
extern "C" void kernel_launch(void* const* d_in, const int* in_sizes, int n_in,
                              void* d_out, int out_size) {
    const float* hs    = (const float*)d_in[0];
    const float* Wq    = (const float*)d_in[1];
    const float* Wk    = (const float*)d_in[2];
    const float* Wv    = (const float*)d_in[3];
    const float* Wo    = (const float*)d_in[4];
    const float* Win   = (const float*)d_in[5];
    const float* Wout  = (const float*)d_in[6];
    const float* qkf   = (const float*)d_in[7];
    const float* gattn = (const float*)d_in[8];
    const float* gmlp  = (const float*)d_in[9];
    float* out = (float*)d_out;

    float *xnp, *q, *k, *v, *attnp, *h, *mlpp;
    float *wqp, *wkp, *wvp, *wop, *winp, *woutp;
    cudaGetSymbolAddress((void**)&xnp,   g_xnp);
    cudaGetSymbolAddress((void**)&q,     g_q);
    cudaGetSymbolAddress((void**)&k,     g_k);
    cudaGetSymbolAddress((void**)&v,     g_v);
    cudaGetSymbolAddress((void**)&attnp, g_attnp);
    cudaGetSymbolAddress((void**)&h,     g_h);
    cudaGetSymbolAddress((void**)&mlpp,  g_mlpp);
    cudaGetSymbolAddress((void**)&wqp,   g_wqp);
    cudaGetSymbolAddress((void**)&wkp,   g_wkp);
    cudaGetSymbolAddress((void**)&wvp,   g_wvp);
    cudaGetSymbolAddress((void**)&wop,   g_wop);
    cudaGetSymbolAddress((void**)&winp,  g_winp);
    cudaGetSymbolAddress((void**)&woutp, g_woutp);

    cudaFuncSetAttribute(flash_mma, cudaFuncAttributeMaxDynamicSharedMemorySize, FLASH_SMEM);
    cudaFuncSetAttribute(qkv_cp, cudaFuncAttributeMaxDynamicSharedMemorySize, GEMMCP_SMEM);
    cudaFuncSetAttribute(gemm_cp<1, true>,  cudaFuncAttributeMaxDynamicSharedMemorySize, GEMMCP_SMEM);
    cudaFuncSetAttribute(gemm_cp<2, false>, cudaFuncAttributeMaxDynamicSharedMemorySize, GEMMCP_SMEM);

    // 0) pre-permute weights into fragment order (tf32-rounded)
    permute_w<<<D_SZ * D_SZ / 1024, 256>>>(Wq, wqp, D_SZ, D_SZ);
    permute_w<<<D_SZ * D_SZ / 1024, 256>>>(Wk, wkp, D_SZ, D_SZ);
    permute_w<<<D_SZ * D_SZ / 1024, 256>>>(Wv, wvp, D_SZ, D_SZ);
    permute_w<<<D_SZ * D_SZ / 1024, 256>>>(Wo, wop, D_SZ, D_SZ);
    permute_w<<<F_SZ * D_SZ / 1024, 256>>>(Win, winp, F_SZ, D_SZ);
    permute_w<<<F_SZ * D_SZ / 1024, 256>>>(Wout, woutp, D_SZ, F_SZ);

    // 1) pre-attn hypersphere norm fused with A-permute
    hnorm_perm<<<MROWS, 256>>>(hs, gattn, xnp);

    // 2) fused QKV projection (raw q/k; norm applied inside flash staging)
    qkv_cp<<<dim3(MROWS / 128, 24), 256, GEMMCP_SMEM>>>(xnp, wqp, wkp, wvp, q, k, v);

    // 3) causal attention (QK-norm fused) -> attn in A-perm layout
    flash_mma<<<dim3(S_SZ / 128, B_SZ * H_SZ), 256, FLASH_SMEM>>>(q, k, v, qkf, attnp);

    // 4) output projection + residual -> h (normal layout)
    gemm_cp<2, false><<<dim3(32, 8), 256, GEMMCP_SMEM>>>(attnp, wop, hs, h, D_SZ, D_SZ);

    // 5) pre-MLP hypersphere norm fused with A-permute
    hnorm_perm<<<MROWS, 256>>>(h, gmlp, xnp);

    // 6) MLP in + GELU -> mlp in A-perm layout
    gemm_cp<1, true><<<dim3(32, 32), 256, GEMMCP_SMEM>>>(xnp, winp, nullptr, mlpp, F_SZ, D_SZ);

    // 7) MLP out + residual -> d_out (normal layout)
    gemm_cp<2, false><<<dim3(32, 8), 256, GEMMCP_SMEM>>>(mlpp, woutp, h, out, D_SZ, F_SZ);
}

// round 12
// speedup vs baseline: 6.6614x; 1.6531x over previous
#include <cuda_runtime.h>
#include <cuda_fp16.h>
#include <math.h>
#include <stdint.h>

#define B_SZ 2
#define S_SZ 2048
#define D_SZ 2048
#define F_SZ 8192
#define H_SZ 16
#define HD   128
#define MROWS (B_SZ * S_SZ)   // 4096

// ---------------- scratch (device globals; no allocation) ----------------
__device__ uint32_t g_xnp [MROWS * D_SZ / 2];
__device__ float    g_q   [MROWS * D_SZ];
__device__ float    g_k   [MROWS * D_SZ];
__device__ float    g_v   [MROWS * D_SZ];
__device__ uint32_t g_attnp[MROWS * D_SZ / 2];
__device__ float    g_h   [MROWS * D_SZ];
__device__ uint32_t g_mlpp[(size_t)MROWS * F_SZ / 2];
__device__ uint32_t g_wqp [D_SZ * D_SZ / 2];
__device__ uint32_t g_wkp [D_SZ * D_SZ / 2];
__device__ uint32_t g_wvp [D_SZ * D_SZ / 2];
__device__ uint32_t g_wop [D_SZ * D_SZ / 2];
__device__ uint32_t g_winp[(size_t)F_SZ * D_SZ / 2];
__device__ uint32_t g_woutp[(size_t)D_SZ * F_SZ / 2];

// ==================== helpers ====================
__device__ __forceinline__ uint32_t h2u(float lo, float hi) {
    __half2 h = __floats2half2_rn(lo, hi);
    return *(uint32_t*)&h;
}
__device__ __forceinline__ uint32_t smem_u32(const void* p) {
    uint32_t a;
    asm("{ .reg .u64 t; cvta.to.shared.u64 t, %1; cvt.u32.u64 %0, t; }" : "=r"(a) : "l"(p));
    return a;
}
__device__ __forceinline__ void cp16(uint32_t saddr, const void* g) {
    asm volatile("cp.async.ca.shared.global [%0], [%1], 16;" :: "r"(saddr), "l"(g) : "memory");
}
// m16n8k16 fp16 mma, fp32 accumulate
__device__ __forceinline__ void mma_f16(float* d, const uint32_t* a, const uint32_t* b) {
    asm volatile(
        "mma.sync.aligned.m16n8k16.row.col.f32.f16.f16.f32 "
        "{%0,%1,%2,%3}, {%4,%5,%6,%7}, {%8,%9}, {%0,%1,%2,%3};"
        : "+f"(d[0]), "+f"(d[1]), "+f"(d[2]), "+f"(d[3])
        : "r"(a[0]), "r"(a[1]), "r"(a[2]), "r"(a[3]), "r"(b[0]), "r"(b[1]));
}
__device__ __forceinline__ float gelu_exact(float x) {
    return 0.5f * x * (1.f + erff(x * 0.7071067811865476f));
}

// fp16 A-perm u32 index for the half2 pair (col even) of element (row, col).
// Chunk (mt, kt) = 2048 u32: [s(2)][ma(8)][lane(32)][reg(4)].
__device__ __forceinline__ size_t hperm_u32(int row, int col, int Kdim) {
    const int mt = row >> 7, kt = col >> 5;
    const int s = (col >> 4) & 1, ma = (row >> 4) & 7;
    const int rr = row & 15, cc = col & 15;
    const int lane = (rr & 7) * 4 + ((cc >> 1) & 3);
    const int reg = (rr >> 3) + 2 * ((cc >> 3) & 1);
    return ((size_t)(mt * (Kdim >> 5) + kt) * 2048) + (((s * 8 + ma) * 32 + lane) << 2) + reg;
}

// ==================== weight permute (fp16 B-frag, coalesced uint4 writes) ====
// W[N,K] -> chunks [nt][kt][1024 u4]: u4 index o: lane=o&31, pair=(o>>5)&15, s=o>>9
__global__ void permute_w(const float* __restrict__ W, uint32_t* __restrict__ Wp,
                          int N, int K) {
    const int u = blockIdx.x * 256 + threadIdx.x;        // uint4 index
    const int chunk = u >> 10, o = u & 1023;
    const int ktn = K >> 5;
    const int nt = chunk / ktn, kt = chunk % ktn;
    const int lane = o & 31, pair = (o >> 5) & 15, s = o >> 9;
    const int n_lo = nt * 256 + pair * 16 + (lane >> 2);
    const int kb = kt * 32 + s * 16 + (lane & 3) * 2;
    float2 a0 = *(const float2*)(W + (size_t)n_lo * K + kb);
    float2 a1 = *(const float2*)(W + (size_t)n_lo * K + kb + 8);
    float2 a2 = *(const float2*)(W + (size_t)(n_lo + 8) * K + kb);
    float2 a3 = *(const float2*)(W + (size_t)(n_lo + 8) * K + kb + 8);
    uint4 r;
    r.x = h2u(a0.x, a0.y);
    r.y = h2u(a1.x, a1.y);
    r.z = h2u(a2.x, a2.y);
    r.w = h2u(a3.x, a3.y);
    ((uint4*)Wp)[u] = r;
}

// ==================== cp.async fp16 GEMM on pre-permuted operands ====================
// C[M,N] = A[M,K] @ W[N,K]^T. CTA 128x256, BK=32, 8 warps (2m x 4n), warp 64x64.
// Stage: A 2048 u32 (8KB) + B 4096 u32 (16KB) = 24KB. 4 stages = 96KB.
#define NSTG 4
#define STAGE_U32 6144
#define GEMMCP_SMEM (NSTG * STAGE_U32 * 4)   // 98304

// EPI: 0 none, 1 GELU, 2 residual. PERMC: write C in fp16 A-perm layout.
template <int EPI, bool PERMC>
__device__ __forceinline__ void gemm_cp_body(
    const uint32_t* __restrict__ Ap, const uint32_t* __restrict__ Wp,
    const float* __restrict__ R, void* __restrict__ Cv,
    int N, int K, int mt, int nt, uint32_t* sm) {
    const uint32_t sb = smem_u32(sm);
    const int tid = threadIdx.x, lane = tid & 31, wid = tid >> 5;
    const int wm = wid >> 2, wn = wid & 3;
    const int NT = K >> 5;
    const uint4* Agc = (const uint4*)Ap + (size_t)mt * NT * 512;
    const uint4* Bgc = (const uint4*)Wp + (size_t)nt * NT * 1024;

    float acc[4][8][4];
    #pragma unroll
    for (int i = 0; i < 4; i++)
        #pragma unroll
        for (int j = 0; j < 8; j++)
            #pragma unroll
            for (int r = 0; r < 4; r++) acc[i][j][r] = 0.f;

    auto issue = [&](int kt) {
        const int st = kt % NSTG;
        const uint32_t sa = sb + st * STAGE_U32 * 4;
        const uint4* ag = Agc + (size_t)kt * 512;
        const uint4* bg = Bgc + (size_t)kt * 1024;
        #pragma unroll
        for (int i = 0; i < 2; i++)
            cp16(sa + (tid + 256 * i) * 16, ag + tid + 256 * i);
        const uint32_t sbb = sa + 2048 * 4;
        #pragma unroll
        for (int i = 0; i < 4; i++)
            cp16(sbb + (tid + 256 * i) * 16, bg + tid + 256 * i);
        asm volatile("cp.async.commit_group;" ::: "memory");
    };

    #pragma unroll
    for (int p = 0; p < NSTG - 1; p++)
        if (p < NT) issue(p);

    for (int kt = 0; kt < NT; kt++) {
        if (kt + NSTG - 1 < NT)
            asm volatile("cp.async.wait_group %0;" :: "n"(NSTG - 2) : "memory");
        else
            asm volatile("cp.async.wait_group 0;" ::: "memory");
        __syncthreads();
        if (kt + NSTG - 1 < NT) issue(kt + NSTG - 1);

        const uint32_t* smA = sm + (kt % NSTG) * STAGE_U32;
        const uint32_t* smB = smA + 2048;
        #pragma unroll
        for (int s = 0; s < 2; s++) {
            uint32_t af[4][4];
            #pragma unroll
            for (int i = 0; i < 4; i++)
                *(uint4*)af[i] = *(const uint4*)(smA + (((s * 8 + wm * 4 + i) * 32 + lane) << 2));
            uint32_t bf[4][4];
            #pragma unroll
            for (int jj = 0; jj < 4; jj++)
                *(uint4*)bf[jj] = *(const uint4*)(smB + (((s * 16 + wn * 4 + jj) * 32 + lane) << 2));
            #pragma unroll
            for (int i = 0; i < 4; i++)
                #pragma unroll
                for (int jj = 0; jj < 4; jj++) {
                    mma_f16(acc[i][2 * jj],     af[i], bf[jj]);
                    mma_f16(acc[i][2 * jj + 1], af[i], bf[jj] + 2);
                }
        }
    }

    const int gid = lane >> 2, tig = lane & 3;
    #pragma unroll
    for (int i = 0; i < 4; i++) {
        #pragma unroll
        for (int j = 0; j < 8; j++) {
            const int row0 = mt * 128 + wm * 64 + i * 16 + gid;
            const int col  = nt * 256 + wn * 64 + j * 8 + tig * 2;
            float2 v0 = {acc[i][j][0], acc[i][j][1]};
            float2 v1 = {acc[i][j][2], acc[i][j][3]};
            if (EPI == 2) {
                float2 q0 = *(const float2*)(R + (size_t)row0 * N + col);
                float2 q1 = *(const float2*)(R + (size_t)(row0 + 8) * N + col);
                v0.x += q0.x; v0.y += q0.y;
                v1.x += q1.x; v1.y += q1.y;
            }
            if (EPI == 1) {
                v0.x = gelu_exact(v0.x); v0.y = gelu_exact(v0.y);
                v1.x = gelu_exact(v1.x); v1.y = gelu_exact(v1.y);
            }
            if (PERMC) {
                uint32_t* Ch = (uint32_t*)Cv;
                Ch[hperm_u32(row0, col, N)]     = h2u(v0.x, v0.y);
                Ch[hperm_u32(row0 + 8, col, N)] = h2u(v1.x, v1.y);
            } else {
                float* C = (float*)Cv;
                *(float2*)(C + (size_t)row0 * N + col) = v0;
                *(float2*)(C + (size_t)(row0 + 8) * N + col) = v1;
            }
        }
    }
}

template <int EPI, bool PERMC>
__global__ void __launch_bounds__(256, 1)
gemm_cp(const uint32_t* __restrict__ Ap, const uint32_t* __restrict__ Wp,
        const float* __restrict__ R, void* __restrict__ C, int N, int K) {
    extern __shared__ uint32_t smu[];
    gemm_cp_body<EPI, PERMC>(Ap, Wp, R, C, N, K, blockIdx.x, blockIdx.y, smu);
}

// Fused QKV. grid.y = 24: which = y>>3, nt = y&7.
__global__ void __launch_bounds__(256, 1)
qkv_cp(const uint32_t* __restrict__ Ap,
       const uint32_t* __restrict__ wqp, const uint32_t* __restrict__ wkp,
       const uint32_t* __restrict__ wvp,
       float* __restrict__ q, float* __restrict__ k, float* __restrict__ v) {
    extern __shared__ uint32_t smu[];
    const int which = blockIdx.y >> 3;
    const uint32_t* Wp = (which == 0) ? wqp : (which == 1) ? wkp : wvp;
    float* C = (which == 0) ? q : (which == 1) ? k : v;
    gemm_cp_body<0, false>(Ap, Wp, nullptr, C, D_SZ, D_SZ, blockIdx.x, blockIdx.y & 7, smu);
}

// ---------------- fused hypersphere norm + fp16 A-permute ----------------
__global__ void hnorm_perm(const float* __restrict__ x, const float* __restrict__ g,
                           uint32_t* __restrict__ Ap) {
    const int row = blockIdx.x;
    const float* xr = x + (size_t)row * D_SZ;
    float ss = 0.f;
    for (int i = threadIdx.x; i < D_SZ; i += blockDim.x) {
        float v = xr[i];
        ss += v * v;
    }
    __shared__ float red[32];
    #pragma unroll
    for (int o = 16; o; o >>= 1) ss += __shfl_xor_sync(0xffffffffu, ss, o);
    if ((threadIdx.x & 31) == 0) red[threadIdx.x >> 5] = ss;
    __syncthreads();
    if (threadIdx.x < 32) {
        float v = (threadIdx.x < (blockDim.x >> 5)) ? red[threadIdx.x] : 0.f;
        #pragma unroll
        for (int o = 16; o; o >>= 1) v += __shfl_xor_sync(0xffffffffu, v, o);
        if (threadIdx.x == 0) red[0] = v;
    }
    __syncthreads();
    const float n = sqrtf(red[0]);
    const float scale = 45.254833995939045f / (n + 1e-6f);  // sqrt(2048)
    #pragma unroll
    for (int i = 0; i < 4; i++) {
        const int col = (threadIdx.x + 256 * i) * 2;
        float2 xv = *(const float2*)(xr + col);
        float2 gv = *(const float2*)(g + col);
        Ap[hperm_u32(row, col, D_SZ)] = h2u(xv.x * scale * gv.x, xv.y * scale * gv.y);
    }
}

// ==================== Flash attention via mma.sync fp16 ====================
// BQ=128 (8 warps x 16 rows), BKV=64. QK-norm fused in staging; epilogue ->
// fp16 A-perm. smem (u32): sQ [c8][ma8][lane][4]=8192, sK [c8][pair4][lane][4]=4096,
// sVt [c4][pair8][lane][4]=4096, sP [c4][ma8][lane][4]=4096. Total 20480 u32 = 80KB.
#define FL_SQ  0
#define FL_SK  8192
#define FL_SVT 12288
#define FL_SP  16384
#define FLASH_SMEM (20480 * 4)

__global__ void __launch_bounds__(256, 1)
flash_mma(const float* __restrict__ Q, const float* __restrict__ K,
          const float* __restrict__ V, const float* __restrict__ scale_p,
          uint32_t* __restrict__ O) {
    extern __shared__ uint32_t fsu[];
    uint32_t* sQ  = fsu + FL_SQ;
    uint32_t* sK  = fsu + FL_SK;
    uint32_t* sVt = fsu + FL_SVT;
    uint32_t* sP  = fsu + FL_SP;

    const int qt = gridDim.x - 1 - blockIdx.x;
    const int bh = blockIdx.y;
    const int b = bh >> 4, h = bh & 15;
    const float scale = *scale_p;
    const int tid = threadIdx.x;
    const int lane = tid & 31;
    const int wid = tid >> 5;

    const size_t base = (size_t)b * S_SZ * D_SZ + (size_t)h * HD;

    // ---- stage Q: fused row-norm (2 lanes/row) + qk scale, fp16 A-frag ----
    {
        const int r = tid >> 1;
        const int ma = r >> 4, rr = r & 15;
        const float* qrow = Q + base + (size_t)(qt * 128 + r) * D_SZ;
        float ssq = 0.f;
        #pragma unroll
        for (int i = 0; i < 16; i++) {
            const int c4 = (tid & 1) * 16 + i;
            float4 v = *(const float4*)(qrow + c4 * 4);
            ssq += v.x * v.x + v.y * v.y + v.z * v.z + v.w * v.w;
        }
        ssq += __shfl_xor_sync(0xffffffffu, ssq, 1);
        const float qs = scale / (sqrtf(ssq) + 1e-6f);
        #pragma unroll
        for (int i = 0; i < 16; i++) {
            const int c4 = (tid & 1) * 16 + i;
            float4 v = *(const float4*)(qrow + c4 * 4);
            const int chunk = c4 >> 2;
            const int lq = (rr & 7) * 4 + 2 * (c4 & 1);
            const int reg = (rr >> 3) + 2 * ((c4 >> 1) & 1);
            uint32_t* dst = sQ + (((chunk * 8 + ma) * 32 + lq) << 2) + reg;
            dst[0] = h2u(v.x * qs, v.y * qs);
            dst[4] = h2u(v.z * qs, v.w * qs);   // lane+1 => +4 u32
        }
    }

    float o[16][4];
    #pragma unroll
    for (int i = 0; i < 16; i++)
        #pragma unroll
        for (int r = 0; r < 4; r++) o[i][r] = 0.f;
    float m_run[2] = {-INFINITY, -INFINITY};
    float l_run[2] = {0.f, 0.f};

    const int NKT = 2 * qt + 2;
    for (int kt = 0; kt < NKT; kt++) {
        __syncthreads();
        // ---- stage K (fused row-norm, 4 lanes/row) and V^T, fp16 frags ----
        {
            const int n0 = tid >> 2;
            const float* krow = K + base + (size_t)(kt * 64 + n0) * D_SZ;
            const float* vrow = V + base + (size_t)(kt * 64 + n0) * D_SZ;
            float ssk = 0.f;
            #pragma unroll
            for (int i = 0; i < 8; i++) {
                const int c4i = (tid & 3) + 4 * i;
                float4 kv = *(const float4*)(krow + c4i * 4);
                ssk += kv.x * kv.x + kv.y * kv.y + kv.z * kv.z + kv.w * kv.w;
            }
            ssk += __shfl_xor_sync(0xffffffffu, ssk, 1);
            ssk += __shfl_xor_sync(0xffffffffu, ssk, 2);
            const float ks = 1.f / (sqrtf(ssk) + 1e-6f);
            __half* sVtH = (__half*)sVt;
            #pragma unroll
            for (int i = 0; i < 8; i++) {
                const int c4i = (tid & 3) + 4 * i;
                const int d0 = c4i * 4;
                float4 kv = *(const float4*)(krow + d0);
                {
                    const int chunk = c4i >> 2;
                    const int pair = n0 >> 4;
                    const int lk = (n0 & 7) * 4 + ((d0 & 7) >> 1);
                    const int reg = ((n0 >> 3) & 1) * 2 + ((c4i >> 1) & 1);
                    uint32_t* dk = sK + (((chunk * 4 + pair) * 32 + lk) << 2) + reg;
                    dk[0] = h2u(kv.x * ks, kv.y * ks);
                    dk[4] = h2u(kv.z * ks, kv.w * ks);
                }
                float4 vv = *(const float4*)(vrow + d0);
                {
                    const int chunk = n0 >> 4;
                    const int pair = d0 >> 4;                 // constant over e
                    const int regv = (((d0 >> 3) & 1) << 1) + ((n0 >> 3) & 1);
                    const int lbase = (d0 & 7) * 4 + ((n0 & 7) >> 1);
                    const int hbit = n0 & 1;
                    float ve[4] = {vv.x, vv.y, vv.z, vv.w};
                    #pragma unroll
                    for (int e = 0; e < 4; e++) {
                        const uint32_t u = (((chunk * 8 + pair) * 32 + lbase + e * 4) << 2) + regv;
                        sVtH[u * 2 + hbit] = __float2half_rn(ve[e]);
                    }
                }
            }
        }
        __syncthreads();

        // ---- S = Q @ K^T ----
        float sacc[8][4];
        #pragma unroll
        for (int j = 0; j < 8; j++)
            #pragma unroll
            for (int r = 0; r < 4; r++) sacc[j][r] = 0.f;
        #pragma unroll
        for (int c = 0; c < 8; c++) {
            uint32_t af[4];
            *(uint4*)af = *(const uint4*)(sQ + (((c * 8 + wid) * 32 + lane) << 2));
            #pragma unroll
            for (int j2 = 0; j2 < 4; j2++) {
                uint32_t bf[4];
                *(uint4*)bf = *(const uint4*)(sK + (((c * 4 + j2) * 32 + lane) << 2));
                mma_f16(sacc[2 * j2],     af, bf);
                mma_f16(sacc[2 * j2 + 1], af, bf + 2);
            }
        }

        if (kt >= 2 * qt) {
            const int rbase = qt * 128 + wid * 16 + (lane >> 2);
            const int cbase = kt * 64 + 2 * (lane & 3);
            #pragma unroll
            for (int j = 0; j < 8; j++)
                #pragma unroll
                for (int r = 0; r < 4; r++) {
                    const int row = rbase + ((r >> 1) << 3);
                    const int col = cbase + j * 8 + (r & 1);
                    if (col > row) sacc[j][r] = -INFINITY;
                }
        }

        #pragma unroll
        for (int hh = 0; hh < 2; hh++) {
            float mt = -INFINITY;
            #pragma unroll
            for (int j = 0; j < 8; j++)
                mt = fmaxf(mt, fmaxf(sacc[j][2 * hh], sacc[j][2 * hh + 1]));
            mt = fmaxf(mt, __shfl_xor_sync(0xffffffffu, mt, 1));
            mt = fmaxf(mt, __shfl_xor_sync(0xffffffffu, mt, 2));
            const bool skip = (mt == -INFINITY);
            const float mold = m_run[hh];
            const float mnew = skip ? mold : fmaxf(mold, mt);
            const float msafe = (mnew == -INFINITY) ? 0.f : mnew;
            const float alpha = skip ? 1.f : __expf(mold - mnew);
            float sum = 0.f;
            #pragma unroll
            for (int j = 0; j < 8; j++) {
                float p0 = __expf(sacc[j][2 * hh]     - msafe);
                float p1 = __expf(sacc[j][2 * hh + 1] - msafe);
                sacc[j][2 * hh]     = p0;
                sacc[j][2 * hh + 1] = p1;
                sum += p0 + p1;
            }
            sum += __shfl_xor_sync(0xffffffffu, sum, 1);
            sum += __shfl_xor_sync(0xffffffffu, sum, 2);
            l_run[hh] = l_run[hh] * alpha + sum;
            m_run[hh] = mnew;
            #pragma unroll
            for (int j = 0; j < 16; j++) {
                o[j][2 * hh]     *= alpha;
                o[j][2 * hh + 1] *= alpha;
            }
        }

        // ---- store P (fp16 A-frag, warp-private, half2 packed) ----
        __syncwarp();
        {
            const int rlow = lane >> 2, qq = lane & 3;
            #pragma unroll
            for (int j = 0; j < 8; j++) {
                #pragma unroll
                for (int hh = 0; hh < 2; hh++) {
                    const int lt = rlow * 4 + qq;
                    const int rt = hh + 2 * (j & 1);
                    sP[((((j >> 1) * 8 + wid) * 32 + lt) << 2) + rt] =
                        h2u(sacc[j][2 * hh], sacc[j][2 * hh + 1]);
                }
            }
        }
        __syncwarp();

        // ---- O += P @ V ----
        #pragma unroll
        for (int c = 0; c < 4; c++) {
            uint32_t af[4];
            *(uint4*)af = *(const uint4*)(sP + (((c * 8 + wid) * 32 + lane) << 2));
            #pragma unroll
            for (int j2 = 0; j2 < 8; j2++) {
                uint32_t bf[4];
                *(uint4*)bf = *(const uint4*)(sVt + (((c * 8 + j2) * 32 + lane) << 2));
                mma_f16(o[2 * j2],     af, bf);
                mma_f16(o[2 * j2 + 1], af, bf + 2);
            }
        }
    }

    // ---- epilogue: normalize, write fp16 A-perm ----
    const float il0 = 1.f / l_run[0];
    const float il1 = 1.f / l_run[1];
    const int grow = b * S_SZ + qt * 128 + wid * 16 + (lane >> 2);
    #pragma unroll
    for (int j = 0; j < 16; j++) {
        const int col = h * HD + j * 8 + 2 * (lane & 3);
        O[hperm_u32(grow, col, D_SZ)]     = h2u(o[j][0] * il0, o[j][1] * il0);
        O[hperm_u32(grow + 8, col, D_SZ)] = h2u(o[j][2] * il1, o[j][3] * il1);
    }
}

// ---------------- driver ----------------
extern "C" void kernel_launch(void* const* d_in, const int* in_sizes, int n_in,
                              void* d_out, int out_size) {
    const float* hs    = (const float*)d_in[0];
    const float* Wq    = (const float*)d_in[1];
    const float* Wk    = (const float*)d_in[2];
    const float* Wv    = (const float*)d_in[3];
    const float* Wo    = (const float*)d_in[4];
    const float* Win   = (const float*)d_in[5];
    const float* Wout  = (const float*)d_in[6];
    const float* qkf   = (const float*)d_in[7];
    const float* gattn = (const float*)d_in[8];
    const float* gmlp  = (const float*)d_in[9];
    float* out = (float*)d_out;

    uint32_t *xnp, *attnp, *mlpp, *wqp, *wkp, *wvp, *wop, *winp, *woutp;
    float *q, *k, *v, *h;
    cudaGetSymbolAddress((void**)&xnp,   g_xnp);
    cudaGetSymbolAddress((void**)&q,     g_q);
    cudaGetSymbolAddress((void**)&k,     g_k);
    cudaGetSymbolAddress((void**)&v,     g_v);
    cudaGetSymbolAddress((void**)&attnp, g_attnp);
    cudaGetSymbolAddress((void**)&h,     g_h);
    cudaGetSymbolAddress((void**)&mlpp,  g_mlpp);
    cudaGetSymbolAddress((void**)&wqp,   g_wqp);
    cudaGetSymbolAddress((void**)&wkp,   g_wkp);
    cudaGetSymbolAddress((void**)&wvp,   g_wvp);
    cudaGetSymbolAddress((void**)&wop,   g_wop);
    cudaGetSymbolAddress((void**)&winp,  g_winp);
    cudaGetSymbolAddress((void**)&woutp, g_woutp);

    cudaFuncSetAttribute(flash_mma, cudaFuncAttributeMaxDynamicSharedMemorySize, FLASH_SMEM);
    cudaFuncSetAttribute(qkv_cp, cudaFuncAttributeMaxDynamicSharedMemorySize, GEMMCP_SMEM);
    cudaFuncSetAttribute(gemm_cp<1, true>,  cudaFuncAttributeMaxDynamicSharedMemorySize, GEMMCP_SMEM);
    cudaFuncSetAttribute(gemm_cp<2, false>, cudaFuncAttributeMaxDynamicSharedMemorySize, GEMMCP_SMEM);

    // 0) permute weights to fp16 fragment order
    permute_w<<<D_SZ * D_SZ / 8 / 256, 256>>>(Wq, wqp, D_SZ, D_SZ);
    permute_w<<<D_SZ * D_SZ / 8 / 256, 256>>>(Wk, wkp, D_SZ, D_SZ);
    permute_w<<<D_SZ * D_SZ / 8 / 256, 256>>>(Wv, wvp, D_SZ, D_SZ);
    permute_w<<<D_SZ * D_SZ / 8 / 256, 256>>>(Wo, wop, D_SZ, D_SZ);
    permute_w<<<F_SZ * D_SZ / 8 / 256, 256>>>(Win, winp, F_SZ, D_SZ);
    permute_w<<<F_SZ * D_SZ / 8 / 256, 256>>>(Wout, woutp, D_SZ, F_SZ);

    // 1) pre-attn hypersphere norm fused with fp16 A-permute
    hnorm_perm<<<MROWS, 256>>>(hs, gattn, xnp);

    // 2) fused QKV projection (f32 outputs; QK-norm happens in flash staging)
    qkv_cp<<<dim3(MROWS / 128, 24), 256, GEMMCP_SMEM>>>(xnp, wqp, wkp, wvp, q, k, v);

    // 3) causal attention -> attn in fp16 A-perm layout
    flash_mma<<<dim3(S_SZ / 128, B_SZ * H_SZ), 256, FLASH_SMEM>>>(q, k, v, qkf, attnp);

    // 4) output projection + residual -> h (f32)
    gemm_cp<2, false><<<dim3(32, 8), 256, GEMMCP_SMEM>>>(attnp, wop, hs, h, D_SZ, D_SZ);

    // 5) pre-MLP hypersphere norm fused with fp16 A-permute
    hnorm_perm<<<MROWS, 256>>>(h, gmlp, xnp);

    // 6) MLP in + GELU -> mlp in fp16 A-perm layout
    gemm_cp<1, true><<<dim3(32, 32), 256, GEMMCP_SMEM>>>(xnp, winp, nullptr, mlpp, F_SZ, D_SZ);

    // 7) MLP out + residual -> d_out (f32)
    gemm_cp<2, false><<<dim3(32, 8), 256, GEMMCP_SMEM>>>(mlpp, woutp, h, out, D_SZ, F_SZ);
}

// round 13
// speedup vs baseline: 6.6628x; 1.0002x over previous
#include <cuda_runtime.h>
#include <cuda_fp16.h>
#include <math.h>
#include <stdint.h>

#define B_SZ 2
#define S_SZ 2048
#define D_SZ 2048
#define F_SZ 8192
#define H_SZ 16
#define HD   128
#define MROWS (B_SZ * S_SZ)   // 4096

// ---------------- scratch (device globals; no allocation) ----------------
__device__ uint32_t g_xnp [MROWS * D_SZ / 2];
__device__ float    g_q   [MROWS * D_SZ];
__device__ float    g_k   [MROWS * D_SZ];
__device__ float    g_v   [MROWS * D_SZ];
__device__ uint32_t g_attnp[MROWS * D_SZ / 2];
__device__ float    g_h   [MROWS * D_SZ];
__device__ uint32_t g_mlpp[(size_t)MROWS * F_SZ / 2];
__device__ uint32_t g_wqp [D_SZ * D_SZ / 2];
__device__ uint32_t g_wkp [D_SZ * D_SZ / 2];
__device__ uint32_t g_wvp [D_SZ * D_SZ / 2];
__device__ uint32_t g_wop [D_SZ * D_SZ / 2];
__device__ uint32_t g_winp[(size_t)F_SZ * D_SZ / 2];
__device__ uint32_t g_woutp[(size_t)D_SZ * F_SZ / 2];

// ==================== helpers ====================
__device__ __forceinline__ uint32_t h2u(float lo, float hi) {
    __half2 h = __floats2half2_rn(lo, hi);
    return *(uint32_t*)&h;
}
__device__ __forceinline__ uint32_t smem_u32(const void* p) {
    uint32_t a;
    asm("{ .reg .u64 t; cvta.to.shared.u64 t, %1; cvt.u32.u64 %0, t; }" : "=r"(a) : "l"(p));
    return a;
}
__device__ __forceinline__ void cp16(uint32_t saddr, const void* g) {
    asm volatile("cp.async.ca.shared.global [%0], [%1], 16;" :: "r"(saddr), "l"(g) : "memory");
}
// m16n8k16 fp16 mma, fp32 accumulate
__device__ __forceinline__ void mma_f16(float* d, const uint32_t* a, const uint32_t* b) {
    asm volatile(
        "mma.sync.aligned.m16n8k16.row.col.f32.f16.f16.f32 "
        "{%0,%1,%2,%3}, {%4,%5,%6,%7}, {%8,%9}, {%0,%1,%2,%3};"
        : "+f"(d[0]), "+f"(d[1]), "+f"(d[2]), "+f"(d[3])
        : "r"(a[0]), "r"(a[1]), "r"(a[2]), "r"(a[3]), "r"(b[0]), "r"(b[1]));
}
__device__ __forceinline__ float gelu_exact(float x) {
    return 0.5f * x * (1.f + erff(x * 0.7071067811865476f));
}

// fp16 A-perm u32 index for the half2 pair (col even) of element (row, col).
// Chunk (mt, kt) = 2048 u32: [s(2)][ma(8)][lane(32)][reg(4)].
__device__ __forceinline__ size_t hperm_u32(int row, int col, int Kdim) {
    const int mt = row >> 7, kt = col >> 5;
    const int s = (col >> 4) & 1, ma = (row >> 4) & 7;
    const int rr = row & 15, cc = col & 15;
    const int lane = (rr & 7) * 4 + ((cc >> 1) & 3);
    const int reg = (rr >> 3) + 2 * ((cc >> 3) & 1);
    return ((size_t)(mt * (Kdim >> 5) + kt) * 2048) + (((s * 8 + ma) * 32 + lane) << 2) + reg;
}

// ==================== weight permute (fp16 B-frag, coalesced uint4 writes) ====
// W[N,K] -> chunks [nt][kt][1024 u4]: u4 index o: lane=o&31, pair=(o>>5)&15, s=o>>9
__global__ void permute_w(const float* __restrict__ W, uint32_t* __restrict__ Wp,
                          int N, int K) {
    const int u = blockIdx.x * 256 + threadIdx.x;        // uint4 index
    const int chunk = u >> 10, o = u & 1023;
    const int ktn = K >> 5;
    const int nt = chunk / ktn, kt = chunk % ktn;
    const int lane = o & 31, pair = (o >> 5) & 15, s = o >> 9;
    const int n_lo = nt * 256 + pair * 16 + (lane >> 2);
    const int kb = kt * 32 + s * 16 + (lane & 3) * 2;
    float2 a0 = *(const float2*)(W + (size_t)n_lo * K + kb);
    float2 a1 = *(const float2*)(W + (size_t)n_lo * K + kb + 8);
    float2 a2 = *(const float2*)(W + (size_t)(n_lo + 8) * K + kb);
    float2 a3 = *(const float2*)(W + (size_t)(n_lo + 8) * K + kb + 8);
    uint4 r;
    r.x = h2u(a0.x, a0.y);
    r.y = h2u(a1.x, a1.y);
    r.z = h2u(a2.x, a2.y);
    r.w = h2u(a3.x, a3.y);
    ((uint4*)Wp)[u] = r;
}

// ==================== cp.async fp16 GEMM on pre-permuted operands ====================
// C[M,N] = A[M,K] @ W[N,K]^T. CTA 128x256, BK=32, 8 warps (2m x 4n), warp 64x64.
// Stage: A 2048 u32 (8KB) + B 4096 u32 (16KB) = 24KB. 4 stages = 96KB.
#define NSTG 4
#define STAGE_U32 6144
#define GEMMCP_SMEM (NSTG * STAGE_U32 * 4)   // 98304

// EPI: 0 none, 1 GELU, 2 residual. PERMC: write C in fp16 A-perm layout.
template <int EPI, bool PERMC>
__device__ __forceinline__ void gemm_cp_body(
    const uint32_t* __restrict__ Ap, const uint32_t* __restrict__ Wp,
    const float* __restrict__ R, void* __restrict__ Cv,
    int N, int K, int mt, int nt, uint32_t* sm) {
    const uint32_t sb = smem_u32(sm);
    const int tid = threadIdx.x, lane = tid & 31, wid = tid >> 5;
    const int wm = wid >> 2, wn = wid & 3;
    const int NT = K >> 5;
    const uint4* Agc = (const uint4*)Ap + (size_t)mt * NT * 512;
    const uint4* Bgc = (const uint4*)Wp + (size_t)nt * NT * 1024;

    float acc[4][8][4];
    #pragma unroll
    for (int i = 0; i < 4; i++)
        #pragma unroll
        for (int j = 0; j < 8; j++)
            #pragma unroll
            for (int r = 0; r < 4; r++) acc[i][j][r] = 0.f;

    auto issue = [&](int kt) {
        const int st = kt % NSTG;
        const uint32_t sa = sb + st * STAGE_U32 * 4;
        const uint4* ag = Agc + (size_t)kt * 512;
        const uint4* bg = Bgc + (size_t)kt * 1024;
        #pragma unroll
        for (int i = 0; i < 2; i++)
            cp16(sa + (tid + 256 * i) * 16, ag + tid + 256 * i);
        const uint32_t sbb = sa + 2048 * 4;
        #pragma unroll
        for (int i = 0; i < 4; i++)
            cp16(sbb + (tid + 256 * i) * 16, bg + tid + 256 * i);
        asm volatile("cp.async.commit_group;" ::: "memory");
    };

    #pragma unroll
    for (int p = 0; p < NSTG - 1; p++)
        if (p < NT) issue(p);

    for (int kt = 0; kt < NT; kt++) {
        if (kt + NSTG - 1 < NT)
            asm volatile("cp.async.wait_group %0;" :: "n"(NSTG - 2) : "memory");
        else
            asm volatile("cp.async.wait_group 0;" ::: "memory");
        __syncthreads();
        if (kt + NSTG - 1 < NT) issue(kt + NSTG - 1);

        const uint32_t* smA = sm + (kt % NSTG) * STAGE_U32;
        const uint32_t* smB = smA + 2048;
        #pragma unroll
        for (int s = 0; s < 2; s++) {
            uint32_t af[4][4];
            #pragma unroll
            for (int i = 0; i < 4; i++)
                *(uint4*)af[i] = *(const uint4*)(smA + (((s * 8 + wm * 4 + i) * 32 + lane) << 2));
            uint32_t bf[4][4];
            #pragma unroll
            for (int jj = 0; jj < 4; jj++)
                *(uint4*)bf[jj] = *(const uint4*)(smB + (((s * 16 + wn * 4 + jj) * 32 + lane) << 2));
            #pragma unroll
            for (int i = 0; i < 4; i++)
                #pragma unroll
                for (int jj = 0; jj < 4; jj++) {
                    mma_f16(acc[i][2 * jj],     af[i], bf[jj]);
                    mma_f16(acc[i][2 * jj + 1], af[i], bf[jj] + 2);
                }
        }
    }

    const int gid = lane >> 2, tig = lane & 3;
    #pragma unroll
    for (int i = 0; i < 4; i++) {
        #pragma unroll
        for (int j = 0; j < 8; j++) {
            const int row0 = mt * 128 + wm * 64 + i * 16 + gid;
            const int col  = nt * 256 + wn * 64 + j * 8 + tig * 2;
            float2 v0 = {acc[i][j][0], acc[i][j][1]};
            float2 v1 = {acc[i][j][2], acc[i][j][3]};
            if (EPI == 2) {
                float2 q0 = *(const float2*)(R + (size_t)row0 * N + col);
                float2 q1 = *(const float2*)(R + (size_t)(row0 + 8) * N + col);
                v0.x += q0.x; v0.y += q0.y;
                v1.x += q1.x; v1.y += q1.y;
            }
            if (EPI == 1) {
                v0.x = gelu_exact(v0.x); v0.y = gelu_exact(v0.y);
                v1.x = gelu_exact(v1.x); v1.y = gelu_exact(v1.y);
            }
            if (PERMC) {
                uint32_t* Ch = (uint32_t*)Cv;
                Ch[hperm_u32(row0, col, N)]     = h2u(v0.x, v0.y);
                Ch[hperm_u32(row0 + 8, col, N)] = h2u(v1.x, v1.y);
            } else {
                float* C = (float*)Cv;
                *(float2*)(C + (size_t)row0 * N + col) = v0;
                *(float2*)(C + (size_t)(row0 + 8) * N + col) = v1;
            }
        }
    }
}

template <int EPI, bool PERMC>
__global__ void __launch_bounds__(256, 1)
gemm_cp(const uint32_t* __restrict__ Ap, const uint32_t* __restrict__ Wp,
        const float* __restrict__ R, void* __restrict__ C, int N, int K) {
    extern __shared__ uint32_t smu[];
    gemm_cp_body<EPI, PERMC>(Ap, Wp, R, C, N, K, blockIdx.x, blockIdx.y, smu);
}

// Fused QKV. grid.y = 24: which = y>>3, nt = y&7.
__global__ void __launch_bounds__(256, 1)
qkv_cp(const uint32_t* __restrict__ Ap,
       const uint32_t* __restrict__ wqp, const uint32_t* __restrict__ wkp,
       const uint32_t* __restrict__ wvp,
       float* __restrict__ q, float* __restrict__ k, float* __restrict__ v) {
    extern __shared__ uint32_t smu[];
    const int which = blockIdx.y >> 3;
    const uint32_t* Wp = (which == 0) ? wqp : (which == 1) ? wkp : wvp;
    float* C = (which == 0) ? q : (which == 1) ? k : v;
    gemm_cp_body<0, false>(Ap, Wp, nullptr, C, D_SZ, D_SZ, blockIdx.x, blockIdx.y & 7, smu);
}

// ---------------- fused hypersphere norm + fp16 A-permute ----------------
__global__ void hnorm_perm(const float* __restrict__ x, const float* __restrict__ g,
                           uint32_t* __restrict__ Ap) {
    const int row = blockIdx.x;
    const float* xr = x + (size_t)row * D_SZ;
    float ss = 0.f;
    for (int i = threadIdx.x; i < D_SZ; i += blockDim.x) {
        float v = xr[i];
        ss += v * v;
    }
    __shared__ float red[32];
    #pragma unroll
    for (int o = 16; o; o >>= 1) ss += __shfl_xor_sync(0xffffffffu, ss, o);
    if ((threadIdx.x & 31) == 0) red[threadIdx.x >> 5] = ss;
    __syncthreads();
    if (threadIdx.x < 32) {
        float v = (threadIdx.x < (blockDim.x >> 5)) ? red[threadIdx.x] : 0.f;
        #pragma unroll
        for (int o = 16; o; o >>= 1) v += __shfl_xor_sync(0xffffffffu, v, o);
        if (threadIdx.x == 0) red[0] = v;
    }
    __syncthreads();
    const float n = sqrtf(red[0]);
    const float scale = 45.254833995939045f / (n + 1e-6f);  // sqrt(2048)
    #pragma unroll
    for (int i = 0; i < 4; i++) {
        const int col = (threadIdx.x + 256 * i) * 2;
        float2 xv = *(const float2*)(xr + col);
        float2 gv = *(const float2*)(g + col);
        Ap[hperm_u32(row, col, D_SZ)] = h2u(xv.x * scale * gv.x, xv.y * scale * gv.y);
    }
}

// ==================== Flash attention via mma.sync fp16 ====================
// BQ=128 (8 warps x 16 rows), BKV=64. QK-norm fused in staging; epilogue ->
// fp16 A-perm. smem (u32): sQ [c8][ma8][lane][4]=8192, sK [c8][pair4][lane][4]=4096,
// sVt [c4][pair8][lane][4]=4096, sP [c4][ma8][lane][4]=4096. Total 20480 u32 = 80KB.
#define FL_SQ  0
#define FL_SK  8192
#define FL_SVT 12288
#define FL_SP  16384
#define FLASH_SMEM (20480 * 4)

__global__ void __launch_bounds__(256, 1)
flash_mma(const float* __restrict__ Q, const float* __restrict__ K,
          const float* __restrict__ V, const float* __restrict__ scale_p,
          uint32_t* __restrict__ O) {
    extern __shared__ uint32_t fsu[];
    uint32_t* sQ  = fsu + FL_SQ;
    uint32_t* sK  = fsu + FL_SK;
    uint32_t* sVt = fsu + FL_SVT;
    uint32_t* sP  = fsu + FL_SP;

    const int qt = gridDim.x - 1 - blockIdx.x;
    const int bh = blockIdx.y;
    const int b = bh >> 4, h = bh & 15;
    const float scale = *scale_p;
    const int tid = threadIdx.x;
    const int lane = tid & 31;
    const int wid = tid >> 5;

    const size_t base = (size_t)b * S_SZ * D_SZ + (size_t)h * HD;

    // ---- stage Q: fused row-norm (2 lanes/row) + qk scale, fp16 A-frag ----
    {
        const int r = tid >> 1;
        const int ma = r >> 4, rr = r & 15;
        const float* qrow = Q + base + (size_t)(qt * 128 + r) * D_SZ;
        float ssq = 0.f;
        #pragma unroll
        for (int i = 0; i < 16; i++) {
            const int c4 = (tid & 1) * 16 + i;
            float4 v = *(const float4*)(qrow + c4 * 4);
            ssq += v.x * v.x + v.y * v.y + v.z * v.z + v.w * v.w;
        }
        ssq += __shfl_xor_sync(0xffffffffu, ssq, 1);
        const float qs = scale / (sqrtf(ssq) + 1e-6f);
        #pragma unroll
        for (int i = 0; i < 16; i++) {
            const int c4 = (tid & 1) * 16 + i;
            float4 v = *(const float4*)(qrow + c4 * 4);
            const int chunk = c4 >> 2;
            const int lq = (rr & 7) * 4 + 2 * (c4 & 1);
            const int reg = (rr >> 3) + 2 * ((c4 >> 1) & 1);
            uint32_t* dst = sQ + (((chunk * 8 + ma) * 32 + lq) << 2) + reg;
            dst[0] = h2u(v.x * qs, v.y * qs);
            dst[4] = h2u(v.z * qs, v.w * qs);   // lane+1 => +4 u32
        }
    }

    float o[16][4];
    #pragma unroll
    for (int i = 0; i < 16; i++)
        #pragma unroll
        for (int r = 0; r < 4; r++) o[i][r] = 0.f;
    float m_run[2] = {-INFINITY, -INFINITY};
    float l_run[2] = {0.f, 0.f};

    const int NKT = 2 * qt + 2;
    for (int kt = 0; kt < NKT; kt++) {
        __syncthreads();
        // ---- stage K (fused row-norm, 4 lanes/row) and V^T, fp16 frags ----
        {
            const int n0 = tid >> 2;
            const float* krow = K + base + (size_t)(kt * 64 + n0) * D_SZ;
            const float* vrow = V + base + (size_t)(kt * 64 + n0) * D_SZ;
            float ssk = 0.f;
            #pragma unroll
            for (int i = 0; i < 8; i++) {
                const int c4i = (tid & 3) + 4 * i;
                float4 kv = *(const float4*)(krow + c4i * 4);
                ssk += kv.x * kv.x + kv.y * kv.y + kv.z * kv.z + kv.w * kv.w;
            }
            ssk += __shfl_xor_sync(0xffffffffu, ssk, 1);
            ssk += __shfl_xor_sync(0xffffffffu, ssk, 2);
            const float ks = 1.f / (sqrtf(ssk) + 1e-6f);
            __half* sVtH = (__half*)sVt;
            #pragma unroll
            for (int i = 0; i < 8; i++) {
                const int c4i = (tid & 3) + 4 * i;
                const int d0 = c4i * 4;
                float4 kv = *(const float4*)(krow + d0);
                {
                    const int chunk = c4i >> 2;
                    const int pair = n0 >> 4;
                    const int lk = (n0 & 7) * 4 + ((d0 & 7) >> 1);
                    const int reg = ((n0 >> 3) & 1) * 2 + ((c4i >> 1) & 1);
                    uint32_t* dk = sK + (((chunk * 4 + pair) * 32 + lk) << 2) + reg;
                    dk[0] = h2u(kv.x * ks, kv.y * ks);
                    dk[4] = h2u(kv.z * ks, kv.w * ks);
                }
                float4 vv = *(const float4*)(vrow + d0);
                {
                    const int chunk = n0 >> 4;
                    const int pair = d0 >> 4;                 // constant over e
                    const int regv = (((d0 >> 3) & 1) << 1) + ((n0 >> 3) & 1);
                    const int lbase = (d0 & 7) * 4 + ((n0 & 7) >> 1);
                    const int hbit = n0 & 1;
                    float ve[4] = {vv.x, vv.y, vv.z, vv.w};
                    #pragma unroll
                    for (int e = 0; e < 4; e++) {
                        const uint32_t u = (((chunk * 8 + pair) * 32 + lbase + e * 4) << 2) + regv;
                        sVtH[u * 2 + hbit] = __float2half_rn(ve[e]);
                    }
                }
            }
        }
        __syncthreads();

        // ---- S = Q @ K^T ----
        float sacc[8][4];
        #pragma unroll
        for (int j = 0; j < 8; j++)
            #pragma unroll
            for (int r = 0; r < 4; r++) sacc[j][r] = 0.f;
        #pragma unroll
        for (int c = 0; c < 8; c++) {
            uint32_t af[4];
            *(uint4*)af = *(const uint4*)(sQ + (((c * 8 + wid) * 32 + lane) << 2));
            #pragma unroll
            for (int j2 = 0; j2 < 4; j2++) {
                uint32_t bf[4];
                *(uint4*)bf = *(const uint4*)(sK + (((c * 4 + j2) * 32 + lane) << 2));
                mma_f16(sacc[2 * j2],     af, bf);
                mma_f16(sacc[2 * j2 + 1], af, bf + 2);
            }
        }

        if (kt >= 2 * qt) {
            const int rbase = qt * 128 + wid * 16 + (lane >> 2);
            const int cbase = kt * 64 + 2 * (lane & 3);
            #pragma unroll
            for (int j = 0; j < 8; j++)
                #pragma unroll
                for (int r = 0; r < 4; r++) {
                    const int row = rbase + ((r >> 1) << 3);
                    const int col = cbase + j * 8 + (r & 1);
                    if (col > row) sacc[j][r] = -INFINITY;
                }
        }

        #pragma unroll
        for (int hh = 0; hh < 2; hh++) {
            float mt = -INFINITY;
            #pragma unroll
            for (int j = 0; j < 8; j++)
                mt = fmaxf(mt, fmaxf(sacc[j][2 * hh], sacc[j][2 * hh + 1]));
            mt = fmaxf(mt, __shfl_xor_sync(0xffffffffu, mt, 1));
            mt = fmaxf(mt, __shfl_xor_sync(0xffffffffu, mt, 2));
            const bool skip = (mt == -INFINITY);
            const float mold = m_run[hh];
            const float mnew = skip ? mold : fmaxf(mold, mt);
            const float msafe = (mnew == -INFINITY) ? 0.f : mnew;
            const float alpha = skip ? 1.f : __expf(mold - mnew);
            float sum = 0.f;
            #pragma unroll
            for (int j = 0; j < 8; j++) {
                float p0 = __expf(sacc[j][2 * hh]     - msafe);
                float p1 = __expf(sacc[j][2 * hh + 1] - msafe);
                sacc[j][2 * hh]     = p0;
                sacc[j][2 * hh + 1] = p1;
                sum += p0 + p1;
            }
            sum += __shfl_xor_sync(0xffffffffu, sum, 1);
            sum += __shfl_xor_sync(0xffffffffu, sum, 2);
            l_run[hh] = l_run[hh] * alpha + sum;
            m_run[hh] = mnew;
            #pragma unroll
            for (int j = 0; j < 16; j++) {
                o[j][2 * hh]     *= alpha;
                o[j][2 * hh + 1] *= alpha;
            }
        }

        // ---- store P (fp16 A-frag, warp-private, half2 packed) ----
        __syncwarp();
        {
            const int rlow = lane >> 2, qq = lane & 3;
            #pragma unroll
            for (int j = 0; j < 8; j++) {
                #pragma unroll
                for (int hh = 0; hh < 2; hh++) {
                    const int lt = rlow * 4 + qq;
                    const int rt = hh + 2 * (j & 1);
                    sP[((((j >> 1) * 8 + wid) * 32 + lt) << 2) + rt] =
                        h2u(sacc[j][2 * hh], sacc[j][2 * hh + 1]);
                }
            }
        }
        __syncwarp();

        // ---- O += P @ V ----
        #pragma unroll
        for (int c = 0; c < 4; c++) {
            uint32_t af[4];
            *(uint4*)af = *(const uint4*)(sP + (((c * 8 + wid) * 32 + lane) << 2));
            #pragma unroll
            for (int j2 = 0; j2 < 8; j2++) {
                uint32_t bf[4];
                *(uint4*)bf = *(const uint4*)(sVt + (((c * 8 + j2) * 32 + lane) << 2));
                mma_f16(o[2 * j2],     af, bf);
                mma_f16(o[2 * j2 + 1], af, bf + 2);
            }
        }
    }

    // ---- epilogue: normalize, write fp16 A-perm ----
    const float il0 = 1.f / l_run[0];
    const float il1 = 1.f / l_run[1];
    const int grow = b * S_SZ + qt * 128 + wid * 16 + (lane >> 2);
    #pragma unroll
    for (int j = 0; j < 16; j++) {
        const int col = h * HD + j * 8 + 2 * (lane & 3);
        O[hperm_u32(grow, col, D_SZ)]     = h2u(o[j][0] * il0, o[j][1] * il0);
        O[hperm_u32(grow + 8, col, D_SZ)] = h2u(o[j][2] * il1, o[j][3] * il1);
    }
}

// ---------------- driver ----------------
extern "C" void kernel_launch(void* const* d_in, const int* in_sizes, int n_in,
                              void* d_out, int out_size) {
    const float* hs    = (const float*)d_in[0];
    const float* Wq    = (const float*)d_in[1];
    const float* Wk    = (const float*)d_in[2];
    const float* Wv    = (const float*)d_in[3];
    const float* Wo    = (const float*)d_in[4];
    const float* Win   = (const float*)d_in[5];
    const float* Wout  = (const float*)d_in[6];
    const float* qkf   = (const float*)d_in[7];
    const float* gattn = (const float*)d_in[8];
    const float* gmlp  = (const float*)d_in[9];
    float* out = (float*)d_out;

    uint32_t *xnp, *attnp, *mlpp, *wqp, *wkp, *wvp, *wop, *winp, *woutp;
    float *q, *k, *v, *h;
    cudaGetSymbolAddress((void**)&xnp,   g_xnp);
    cudaGetSymbolAddress((void**)&q,     g_q);
    cudaGetSymbolAddress((void**)&k,     g_k);
    cudaGetSymbolAddress((void**)&v,     g_v);
    cudaGetSymbolAddress((void**)&attnp, g_attnp);
    cudaGetSymbolAddress((void**)&h,     g_h);
    cudaGetSymbolAddress((void**)&mlpp,  g_mlpp);
    cudaGetSymbolAddress((void**)&wqp,   g_wqp);
    cudaGetSymbolAddress((void**)&wkp,   g_wkp);
    cudaGetSymbolAddress((void**)&wvp,   g_wvp);
    cudaGetSymbolAddress((void**)&wop,   g_wop);
    cudaGetSymbolAddress((void**)&winp,  g_winp);
    cudaGetSymbolAddress((void**)&woutp, g_woutp);

    cudaFuncSetAttribute(flash_mma, cudaFuncAttributeMaxDynamicSharedMemorySize, FLASH_SMEM);
    cudaFuncSetAttribute(qkv_cp, cudaFuncAttributeMaxDynamicSharedMemorySize, GEMMCP_SMEM);
    cudaFuncSetAttribute(gemm_cp<1, true>,  cudaFuncAttributeMaxDynamicSharedMemorySize, GEMMCP_SMEM);
    cudaFuncSetAttribute(gemm_cp<2, false>, cudaFuncAttributeMaxDynamicSharedMemorySize, GEMMCP_SMEM);

    // 0) permute weights to fp16 fragment order
    permute_w<<<D_SZ * D_SZ / 8 / 256, 256>>>(Wq, wqp, D_SZ, D_SZ);
    permute_w<<<D_SZ * D_SZ / 8 / 256, 256>>>(Wk, wkp, D_SZ, D_SZ);
    permute_w<<<D_SZ * D_SZ / 8 / 256, 256>>>(Wv, wvp, D_SZ, D_SZ);
    permute_w<<<D_SZ * D_SZ / 8 / 256, 256>>>(Wo, wop, D_SZ, D_SZ);
    permute_w<<<F_SZ * D_SZ / 8 / 256, 256>>>(Win, winp, F_SZ, D_SZ);
    permute_w<<<F_SZ * D_SZ / 8 / 256, 256>>>(Wout, woutp, D_SZ, F_SZ);

    // 1) pre-attn hypersphere norm fused with fp16 A-permute
    hnorm_perm<<<MROWS, 256>>>(hs, gattn, xnp);

    // 2) fused QKV projection (f32 outputs; QK-norm happens in flash staging)
    qkv_cp<<<dim3(MROWS / 128, 24), 256, GEMMCP_SMEM>>>(xnp, wqp, wkp, wvp, q, k, v);

    // 3) causal attention -> attn in fp16 A-perm layout
    flash_mma<<<dim3(S_SZ / 128, B_SZ * H_SZ), 256, FLASH_SMEM>>>(q, k, v, qkf, attnp);

    // 4) output projection + residual -> h (f32)
    gemm_cp<2, false><<<dim3(32, 8), 256, GEMMCP_SMEM>>>(attnp, wop, hs, h, D_SZ, D_SZ);

    // 5) pre-MLP hypersphere norm fused with fp16 A-permute
    hnorm_perm<<<MROWS, 256>>>(h, gmlp, xnp);

    // 6) MLP in + GELU -> mlp in fp16 A-perm layout
    gemm_cp<1, true><<<dim3(32, 32), 256, GEMMCP_SMEM>>>(xnp, winp, nullptr, mlpp, F_SZ, D_SZ);

    // 7) MLP out + residual -> d_out (f32)
    gemm_cp<2, false><<<dim3(32, 8), 256, GEMMCP_SMEM>>>(mlpp, woutp, h, out, D_SZ, F_SZ);
}

// round 14
// speedup vs baseline: 7.8761x; 1.1821x over previous
#include <cuda_runtime.h>
#include <cuda_fp16.h>
#include <math.h>
#include <stdint.h>

#define B_SZ 2
#define S_SZ 2048
#define D_SZ 2048
#define F_SZ 8192
#define H_SZ 16
#define HD   128
#define MROWS (B_SZ * S_SZ)   // 4096

// ---------------- scratch (device globals; no allocation) ----------------
__device__ uint32_t g_xnp [MROWS * D_SZ / 2];
__device__ float    g_q   [MROWS * D_SZ];
__device__ float    g_k   [MROWS * D_SZ];
__device__ float    g_v   [MROWS * D_SZ];
__device__ uint32_t g_attnp[MROWS * D_SZ / 2];
__device__ float    g_h   [MROWS * D_SZ];
__device__ uint32_t g_mlpp[(size_t)MROWS * F_SZ / 2];
__device__ uint32_t g_wqp [D_SZ * D_SZ / 2];
__device__ uint32_t g_wkp [D_SZ * D_SZ / 2];
__device__ uint32_t g_wvp [D_SZ * D_SZ / 2];
__device__ uint32_t g_wop [D_SZ * D_SZ / 2];
__device__ uint32_t g_winp[(size_t)F_SZ * D_SZ / 2];
__device__ uint32_t g_woutp[(size_t)D_SZ * F_SZ / 2];

// ==================== helpers ====================
__device__ __forceinline__ uint32_t h2u(float lo, float hi) {
    __half2 h = __floats2half2_rn(lo, hi);
    return *(uint32_t*)&h;
}
__device__ __forceinline__ uint32_t smem_u32(const void* p) {
    uint32_t a;
    asm("{ .reg .u64 t; cvta.to.shared.u64 t, %1; cvt.u32.u64 %0, t; }" : "=r"(a) : "l"(p));
    return a;
}
__device__ __forceinline__ void cp16(uint32_t saddr, const void* g) {
    asm volatile("cp.async.cg.shared.global [%0], [%1], 16;" :: "r"(saddr), "l"(g) : "memory");
}
// m16n8k16 fp16 mma, fp32 accumulate
__device__ __forceinline__ void mma_f16(float* d, const uint32_t* a, const uint32_t* b) {
    asm volatile(
        "mma.sync.aligned.m16n8k16.row.col.f32.f16.f16.f32 "
        "{%0,%1,%2,%3}, {%4,%5,%6,%7}, {%8,%9}, {%0,%1,%2,%3};"
        : "+f"(d[0]), "+f"(d[1]), "+f"(d[2]), "+f"(d[3])
        : "r"(a[0]), "r"(a[1]), "r"(a[2]), "r"(a[3]), "r"(b[0]), "r"(b[1]));
}
__device__ __forceinline__ float gelu_exact(float x) {
    return 0.5f * x * (1.f + erff(x * 0.7071067811865476f));
}

// fp16 A-perm u32 index for the half2 pair (col even) of element (row, col).
// Chunk (mt, kt) = 2048 u32: [s(2)][ma(8)][lane(32)][reg(4)].
__device__ __forceinline__ size_t hperm_u32(int row, int col, int Kdim) {
    const int mt = row >> 7, kt = col >> 5;
    const int s = (col >> 4) & 1, ma = (row >> 4) & 7;
    const int rr = row & 15, cc = col & 15;
    const int lane = (rr & 7) * 4 + ((cc >> 1) & 3);
    const int reg = (rr >> 3) + 2 * ((cc >> 3) & 1);
    return ((size_t)(mt * (Kdim >> 5) + kt) * 2048) + (((s * 8 + ma) * 32 + lane) << 2) + reg;
}

// ==================== weight permute (fp16 B-frag, coalesced uint4 writes) ====
__global__ void permute_w(const float* __restrict__ W, uint32_t* __restrict__ Wp,
                          int N, int K) {
    const int u = blockIdx.x * 256 + threadIdx.x;        // uint4 index
    const int chunk = u >> 10, o = u & 1023;
    const int ktn = K >> 5;
    const int nt = chunk / ktn, kt = chunk % ktn;
    const int lane = o & 31, pair = (o >> 5) & 15, s = o >> 9;
    const int n_lo = nt * 256 + pair * 16 + (lane >> 2);
    const int kb = kt * 32 + s * 16 + (lane & 3) * 2;
    float2 a0 = *(const float2*)(W + (size_t)n_lo * K + kb);
    float2 a1 = *(const float2*)(W + (size_t)n_lo * K + kb + 8);
    float2 a2 = *(const float2*)(W + (size_t)(n_lo + 8) * K + kb);
    float2 a3 = *(const float2*)(W + (size_t)(n_lo + 8) * K + kb + 8);
    uint4 r;
    r.x = h2u(a0.x, a0.y);
    r.y = h2u(a1.x, a1.y);
    r.z = h2u(a2.x, a2.y);
    r.w = h2u(a3.x, a3.y);
    ((uint4*)Wp)[u] = r;
}

// ==================== cp.async fp16 GEMM, BK=64, 2 stages ====================
// C[M,N] = A[M,K] @ W[N,K]^T. CTA 128x256, 8 warps (2m x 4n), warp 64x64.
// Stage (BK=64): A 4096 u32 (16KB) + B 8192 u32 (32KB) = 48KB. 2 stages = 96KB.
#define STAGE_U32 12288
#define GEMMCP_SMEM (2 * STAGE_U32 * 4)   // 98304

// EPI: 0 none, 1 GELU, 2 residual. PERMC: write C in fp16 A-perm layout.
template <int EPI, bool PERMC>
__device__ __forceinline__ void gemm_cp_body(
    const uint32_t* __restrict__ Ap, const uint32_t* __restrict__ Wp,
    const float* __restrict__ R, void* __restrict__ Cv,
    int N, int K, int mt, int nt, uint32_t* sm) {
    const uint32_t sb = smem_u32(sm);
    const int tid = threadIdx.x, lane = tid & 31, wid = tid >> 5;
    const int wm = wid >> 2, wn = wid & 3;
    const int NT32 = K >> 5;
    const int NT64 = K >> 6;
    const uint4* Agc = (const uint4*)Ap + (size_t)mt * NT32 * 512;
    const uint4* Bgc = (const uint4*)Wp + (size_t)nt * NT32 * 1024;

    float acc[4][8][4];
    #pragma unroll
    for (int i = 0; i < 4; i++)
        #pragma unroll
        for (int j = 0; j < 8; j++)
            #pragma unroll
            for (int r = 0; r < 4; r++) acc[i][j][r] = 0.f;

    auto issue = [&](int kt) {
        const int st = kt & 1;
        const uint32_t sa = sb + st * STAGE_U32 * 4;
        const uint4* ag = Agc + (size_t)kt * 1024;
        const uint4* bg = Bgc + (size_t)kt * 2048;
        #pragma unroll
        for (int i = 0; i < 4; i++)
            cp16(sa + (tid + 256 * i) * 16, ag + tid + 256 * i);
        const uint32_t sbb = sa + 4096 * 4;
        #pragma unroll
        for (int i = 0; i < 8; i++)
            cp16(sbb + (tid + 256 * i) * 16, bg + tid + 256 * i);
        asm volatile("cp.async.commit_group;" ::: "memory");
    };

    issue(0);

    for (int kt = 0; kt < NT64; kt++) {
        asm volatile("cp.async.wait_group 0;" ::: "memory");
        __syncthreads();          // all threads done reading the stage we overwrite next
        if (kt + 1 < NT64) issue(kt + 1);

        const uint32_t* smA = sm + (kt & 1) * STAGE_U32;
        const uint32_t* smB = smA + 4096;

        uint32_t af[2][4][4], bf[2][4][4];
        auto ldfrag = [&](int s4, int buf) {
            const int chunk = s4 >> 1, s = s4 & 1;
            const uint32_t* A = smA + chunk * 2048;
            const uint32_t* Bp = smB + chunk * 4096;
            #pragma unroll
            for (int i = 0; i < 4; i++)
                *(uint4*)af[buf][i] = *(const uint4*)(A + (((s * 8 + wm * 4 + i) * 32 + lane) << 2));
            #pragma unroll
            for (int j = 0; j < 4; j++)
                *(uint4*)bf[buf][j] = *(const uint4*)(Bp + (((s * 16 + wn * 4 + j) * 32 + lane) << 2));
        };

        ldfrag(0, 0);
        #pragma unroll
        for (int s4 = 0; s4 < 4; s4++) {
            if (s4 < 3) ldfrag(s4 + 1, (s4 + 1) & 1);
            const int cb = s4 & 1;
            #pragma unroll
            for (int i = 0; i < 4; i++)
                #pragma unroll
                for (int jj = 0; jj < 4; jj++) {
                    mma_f16(acc[i][2 * jj],     af[cb][i], bf[cb][jj]);
                    mma_f16(acc[i][2 * jj + 1], af[cb][i], bf[cb][jj] + 2);
                }
        }
    }

    const int gid = lane >> 2, tig = lane & 3;
    #pragma unroll
    for (int i = 0; i < 4; i++) {
        #pragma unroll
        for (int j = 0; j < 8; j++) {
            const int row0 = mt * 128 + wm * 64 + i * 16 + gid;
            const int col  = nt * 256 + wn * 64 + j * 8 + tig * 2;
            float2 v0 = {acc[i][j][0], acc[i][j][1]};
            float2 v1 = {acc[i][j][2], acc[i][j][3]};
            if (EPI == 2) {
                float2 q0 = *(const float2*)(R + (size_t)row0 * N + col);
                float2 q1 = *(const float2*)(R + (size_t)(row0 + 8) * N + col);
                v0.x += q0.x; v0.y += q0.y;
                v1.x += q1.x; v1.y += q1.y;
            }
            if (EPI == 1) {
                v0.x = gelu_exact(v0.x); v0.y = gelu_exact(v0.y);
                v1.x = gelu_exact(v1.x); v1.y = gelu_exact(v1.y);
            }
            if (PERMC) {
                uint32_t* Ch = (uint32_t*)Cv;
                Ch[hperm_u32(row0, col, N)]     = h2u(v0.x, v0.y);
                Ch[hperm_u32(row0 + 8, col, N)] = h2u(v1.x, v1.y);
            } else {
                float* C = (float*)Cv;
                *(float2*)(C + (size_t)row0 * N + col) = v0;
                *(float2*)(C + (size_t)(row0 + 8) * N + col) = v1;
            }
        }
    }
}

template <int EPI, bool PERMC>
__global__ void __launch_bounds__(256, 1)
gemm_cp(const uint32_t* __restrict__ Ap, const uint32_t* __restrict__ Wp,
        const float* __restrict__ R, void* __restrict__ C, int N, int K) {
    extern __shared__ uint32_t smu[];
    gemm_cp_body<EPI, PERMC>(Ap, Wp, R, C, N, K, blockIdx.x, blockIdx.y, smu);
}

// Fused QKV. grid.y = 24: which = y>>3, nt = y&7.
__global__ void __launch_bounds__(256, 1)
qkv_cp(const uint32_t* __restrict__ Ap,
       const uint32_t* __restrict__ wqp, const uint32_t* __restrict__ wkp,
       const uint32_t* __restrict__ wvp,
       float* __restrict__ q, float* __restrict__ k, float* __restrict__ v) {
    extern __shared__ uint32_t smu[];
    const int which = blockIdx.y >> 3;
    const uint32_t* Wp = (which == 0) ? wqp : (which == 1) ? wkp : wvp;
    float* C = (which == 0) ? q : (which == 1) ? k : v;
    gemm_cp_body<0, false>(Ap, Wp, nullptr, C, D_SZ, D_SZ, blockIdx.x, blockIdx.y & 7, smu);
}

// ---------------- fused hypersphere norm + fp16 A-permute ----------------
__global__ void hnorm_perm(const float* __restrict__ x, const float* __restrict__ g,
                           uint32_t* __restrict__ Ap) {
    const int row = blockIdx.x;
    const float* xr = x + (size_t)row * D_SZ;
    float ss = 0.f;
    for (int i = threadIdx.x; i < D_SZ; i += blockDim.x) {
        float v = xr[i];
        ss += v * v;
    }
    __shared__ float red[32];
    #pragma unroll
    for (int o = 16; o; o >>= 1) ss += __shfl_xor_sync(0xffffffffu, ss, o);
    if ((threadIdx.x & 31) == 0) red[threadIdx.x >> 5] = ss;
    __syncthreads();
    if (threadIdx.x < 32) {
        float v = (threadIdx.x < (blockDim.x >> 5)) ? red[threadIdx.x] : 0.f;
        #pragma unroll
        for (int o = 16; o; o >>= 1) v += __shfl_xor_sync(0xffffffffu, v, o);
        if (threadIdx.x == 0) red[0] = v;
    }
    __syncthreads();
    const float n = sqrtf(red[0]);
    const float scale = 45.254833995939045f / (n + 1e-6f);  // sqrt(2048)
    #pragma unroll
    for (int i = 0; i < 4; i++) {
        const int col = (threadIdx.x + 256 * i) * 2;
        float2 xv = *(const float2*)(xr + col);
        float2 gv = *(const float2*)(g + col);
        Ap[hperm_u32(row, col, D_SZ)] = h2u(xv.x * scale * gv.x, xv.y * scale * gv.y);
    }
}

// ==================== Flash attention via mma.sync fp16 (unchanged R13) ====
#define FL_SQ  0
#define FL_SK  8192
#define FL_SVT 12288
#define FL_SP  16384
#define FLASH_SMEM (20480 * 4)

__global__ void __launch_bounds__(256, 1)
flash_mma(const float* __restrict__ Q, const float* __restrict__ K,
          const float* __restrict__ V, const float* __restrict__ scale_p,
          uint32_t* __restrict__ O) {
    extern __shared__ uint32_t fsu[];
    uint32_t* sQ  = fsu + FL_SQ;
    uint32_t* sK  = fsu + FL_SK;
    uint32_t* sVt = fsu + FL_SVT;
    uint32_t* sP  = fsu + FL_SP;

    const int qt = gridDim.x - 1 - blockIdx.x;
    const int bh = blockIdx.y;
    const int b = bh >> 4, h = bh & 15;
    const float scale = *scale_p;
    const int tid = threadIdx.x;
    const int lane = tid & 31;
    const int wid = tid >> 5;

    const size_t base = (size_t)b * S_SZ * D_SZ + (size_t)h * HD;

    {
        const int r = tid >> 1;
        const int ma = r >> 4, rr = r & 15;
        const float* qrow = Q + base + (size_t)(qt * 128 + r) * D_SZ;
        float ssq = 0.f;
        #pragma unroll
        for (int i = 0; i < 16; i++) {
            const int c4 = (tid & 1) * 16 + i;
            float4 v = *(const float4*)(qrow + c4 * 4);
            ssq += v.x * v.x + v.y * v.y + v.z * v.z + v.w * v.w;
        }
        ssq += __shfl_xor_sync(0xffffffffu, ssq, 1);
        const float qs = scale / (sqrtf(ssq) + 1e-6f);
        #pragma unroll
        for (int i = 0; i < 16; i++) {
            const int c4 = (tid & 1) * 16 + i;
            float4 v = *(const float4*)(qrow + c4 * 4);
            const int chunk = c4 >> 2;
            const int lq = (rr & 7) * 4 + 2 * (c4 & 1);
            const int reg = (rr >> 3) + 2 * ((c4 >> 1) & 1);
            uint32_t* dst = sQ + (((chunk * 8 + ma) * 32 + lq) << 2) + reg;
            dst[0] = h2u(v.x * qs, v.y * qs);
            dst[4] = h2u(v.z * qs, v.w * qs);
        }
    }

    float o[16][4];
    #pragma unroll
    for (int i = 0; i < 16; i++)
        #pragma unroll
        for (int r = 0; r < 4; r++) o[i][r] = 0.f;
    float m_run[2] = {-INFINITY, -INFINITY};
    float l_run[2] = {0.f, 0.f};

    const int NKT = 2 * qt + 2;
    for (int kt = 0; kt < NKT; kt++) {
        __syncthreads();
        {
            const int n0 = tid >> 2;
            const float* krow = K + base + (size_t)(kt * 64 + n0) * D_SZ;
            const float* vrow = V + base + (size_t)(kt * 64 + n0) * D_SZ;
            float ssk = 0.f;
            #pragma unroll
            for (int i = 0; i < 8; i++) {
                const int c4i = (tid & 3) + 4 * i;
                float4 kv = *(const float4*)(krow + c4i * 4);
                ssk += kv.x * kv.x + kv.y * kv.y + kv.z * kv.z + kv.w * kv.w;
            }
            ssk += __shfl_xor_sync(0xffffffffu, ssk, 1);
            ssk += __shfl_xor_sync(0xffffffffu, ssk, 2);
            const float ks = 1.f / (sqrtf(ssk) + 1e-6f);
            __half* sVtH = (__half*)sVt;
            #pragma unroll
            for (int i = 0; i < 8; i++) {
                const int c4i = (tid & 3) + 4 * i;
                const int d0 = c4i * 4;
                float4 kv = *(const float4*)(krow + d0);
                {
                    const int chunk = c4i >> 2;
                    const int pair = n0 >> 4;
                    const int lk = (n0 & 7) * 4 + ((d0 & 7) >> 1);
                    const int reg = ((n0 >> 3) & 1) * 2 + ((c4i >> 1) & 1);
                    uint32_t* dk = sK + (((chunk * 4 + pair) * 32 + lk) << 2) + reg;
                    dk[0] = h2u(kv.x * ks, kv.y * ks);
                    dk[4] = h2u(kv.z * ks, kv.w * ks);
                }
                float4 vv = *(const float4*)(vrow + d0);
                {
                    const int chunk = n0 >> 4;
                    const int pair = d0 >> 4;
                    const int regv = (((d0 >> 3) & 1) << 1) + ((n0 >> 3) & 1);
                    const int lbase = (d0 & 7) * 4 + ((n0 & 7) >> 1);
                    const int hbit = n0 & 1;
                    float ve[4] = {vv.x, vv.y, vv.z, vv.w};
                    #pragma unroll
                    for (int e = 0; e < 4; e++) {
                        const uint32_t u = (((chunk * 8 + pair) * 32 + lbase + e * 4) << 2) + regv;
                        sVtH[u * 2 + hbit] = __float2half_rn(ve[e]);
                    }
                }
            }
        }
        __syncthreads();

        float sacc[8][4];
        #pragma unroll
        for (int j = 0; j < 8; j++)
            #pragma unroll
            for (int r = 0; r < 4; r++) sacc[j][r] = 0.f;
        #pragma unroll
        for (int c = 0; c < 8; c++) {
            uint32_t af[4];
            *(uint4*)af = *(const uint4*)(sQ + (((c * 8 + wid) * 32 + lane) << 2));
            #pragma unroll
            for (int j2 = 0; j2 < 4; j2++) {
                uint32_t bf[4];
                *(uint4*)bf = *(const uint4*)(sK + (((c * 4 + j2) * 32 + lane) << 2));
                mma_f16(sacc[2 * j2],     af, bf);
                mma_f16(sacc[2 * j2 + 1], af, bf + 2);
            }
        }

        if (kt >= 2 * qt) {
            const int rbase = qt * 128 + wid * 16 + (lane >> 2);
            const int cbase = kt * 64 + 2 * (lane & 3);
            #pragma unroll
            for (int j = 0; j < 8; j++)
                #pragma unroll
                for (int r = 0; r < 4; r++) {
                    const int row = rbase + ((r >> 1) << 3);
                    const int col = cbase + j * 8 + (r & 1);
                    if (col > row) sacc[j][r] = -INFINITY;
                }
        }

        #pragma unroll
        for (int hh = 0; hh < 2; hh++) {
            float mt = -INFINITY;
            #pragma unroll
            for (int j = 0; j < 8; j++)
                mt = fmaxf(mt, fmaxf(sacc[j][2 * hh], sacc[j][2 * hh + 1]));
            mt = fmaxf(mt, __shfl_xor_sync(0xffffffffu, mt, 1));
            mt = fmaxf(mt, __shfl_xor_sync(0xffffffffu, mt, 2));
            const bool skip = (mt == -INFINITY);
            const float mold = m_run[hh];
            const float mnew = skip ? mold : fmaxf(mold, mt);
            const float msafe = (mnew == -INFINITY) ? 0.f : mnew;
            const float alpha = skip ? 1.f : __expf(mold - mnew);
            float sum = 0.f;
            #pragma unroll
            for (int j = 0; j < 8; j++) {
                float p0 = __expf(sacc[j][2 * hh]     - msafe);
                float p1 = __expf(sacc[j][2 * hh + 1] - msafe);
                sacc[j][2 * hh]     = p0;
                sacc[j][2 * hh + 1] = p1;
                sum += p0 + p1;
            }
            sum += __shfl_xor_sync(0xffffffffu, sum, 1);
            sum += __shfl_xor_sync(0xffffffffu, sum, 2);
            l_run[hh] = l_run[hh] * alpha + sum;
            m_run[hh] = mnew;
            #pragma unroll
            for (int j = 0; j < 16; j++) {
                o[j][2 * hh]     *= alpha;
                o[j][2 * hh + 1] *= alpha;
            }
        }

        __syncwarp();
        {
            const int rlow = lane >> 2, qq = lane & 3;
            #pragma unroll
            for (int j = 0; j < 8; j++) {
                #pragma unroll
                for (int hh = 0; hh < 2; hh++) {
                    const int lt = rlow * 4 + qq;
                    const int rt = hh + 2 * (j & 1);
                    sP[((((j >> 1) * 8 + wid) * 32 + lt) << 2) + rt] =
                        h2u(sacc[j][2 * hh], sacc[j][2 * hh + 1]);
                }
            }
        }
        __syncwarp();

        #pragma unroll
        for (int c = 0; c < 4; c++) {
            uint32_t af[4];
            *(uint4*)af = *(const uint4*)(sP + (((c * 8 + wid) * 32 + lane) << 2));
            #pragma unroll
            for (int j2 = 0; j2 < 8; j2++) {
                uint32_t bf[4];
                *(uint4*)bf = *(const uint4*)(sVt + (((c * 8 + j2) * 32 + lane) << 2));
                mma_f16(o[2 * j2],     af, bf);
                mma_f16(o[2 * j2 + 1], af, bf + 2);
            }
        }
    }

    const float il0 = 1.f / l_run[0];
    const float il1 = 1.f / l_run[1];
    const int grow = b * S_SZ + qt * 128 + wid * 16 + (lane >> 2);
    #pragma unroll
    for (int j = 0; j < 16; j++) {
        const int col = h * HD + j * 8 + 2 * (lane & 3);
        O[hperm_u32(grow, col, D_SZ)]     = h2u(o[j][0] * il0, o[j][1] * il0);
        O[hperm_u32(grow + 8, col, D_SZ)] = h2u(o[j][2] * il1, o[j][3] * il1);
    }
}

// ---------------- driver ----------------
extern "C" void kernel_launch(void* const* d_in, const int* in_sizes, int n_in,
                              void* d_out, int out_size) {
    const float* hs    = (const float*)d_in[0];
    const float* Wq    = (const float*)d_in[1];
    const float* Wk    = (const float*)d_in[2];
    const float* Wv    = (const float*)d_in[3];
    const float* Wo    = (const float*)d_in[4];
    const float* Win   = (const float*)d_in[5];
    const float* Wout  = (const float*)d_in[6];
    const float* qkf   = (const float*)d_in[7];
    const float* gattn = (const float*)d_in[8];
    const float* gmlp  = (const float*)d_in[9];
    float* out = (float*)d_out;

    uint32_t *xnp, *attnp, *mlpp, *wqp, *wkp, *wvp, *wop, *winp, *woutp;
    float *q, *k, *v, *h;
    cudaGetSymbolAddress((void**)&xnp,   g_xnp);
    cudaGetSymbolAddress((void**)&q,     g_q);
    cudaGetSymbolAddress((void**)&k,     g_k);
    cudaGetSymbolAddress((void**)&v,     g_v);
    cudaGetSymbolAddress((void**)&attnp, g_attnp);
    cudaGetSymbolAddress((void**)&h,     g_h);
    cudaGetSymbolAddress((void**)&mlpp,  g_mlpp);
    cudaGetSymbolAddress((void**)&wqp,   g_wqp);
    cudaGetSymbolAddress((void**)&wkp,   g_wkp);
    cudaGetSymbolAddress((void**)&wvp,   g_wvp);
    cudaGetSymbolAddress((void**)&wop,   g_wop);
    cudaGetSymbolAddress((void**)&winp,  g_winp);
    cudaGetSymbolAddress((void**)&woutp, g_woutp);

    cudaFuncSetAttribute(flash_mma, cudaFuncAttributeMaxDynamicSharedMemorySize, FLASH_SMEM);
    cudaFuncSetAttribute(qkv_cp, cudaFuncAttributeMaxDynamicSharedMemorySize, GEMMCP_SMEM);
    cudaFuncSetAttribute(gemm_cp<1, true>,  cudaFuncAttributeMaxDynamicSharedMemorySize, GEMMCP_SMEM);
    cudaFuncSetAttribute(gemm_cp<2, false>, cudaFuncAttributeMaxDynamicSharedMemorySize, GEMMCP_SMEM);

    // 0) permute weights to fp16 fragment order
    permute_w<<<D_SZ * D_SZ / 8 / 256, 256>>>(Wq, wqp, D_SZ, D_SZ);
    permute_w<<<D_SZ * D_SZ / 8 / 256, 256>>>(Wk, wkp, D_SZ, D_SZ);
    permute_w<<<D_SZ * D_SZ / 8 / 256, 256>>>(Wv, wvp, D_SZ, D_SZ);
    permute_w<<<D_SZ * D_SZ / 8 / 256, 256>>>(Wo, wop, D_SZ, D_SZ);
    permute_w<<<F_SZ * D_SZ / 8 / 256, 256>>>(Win, winp, F_SZ, D_SZ);
    permute_w<<<F_SZ * D_SZ / 8 / 256, 256>>>(Wout, woutp, D_SZ, F_SZ);

    // 1) pre-attn hypersphere norm fused with fp16 A-permute
    hnorm_perm<<<MROWS, 256>>>(hs, gattn, xnp);

    // 2) fused QKV projection
    qkv_cp<<<dim3(MROWS / 128, 24), 256, GEMMCP_SMEM>>>(xnp, wqp, wkp, wvp, q, k, v);

    // 3) causal attention -> attn in fp16 A-perm layout
    flash_mma<<<dim3(S_SZ / 128, B_SZ * H_SZ), 256, FLASH_SMEM>>>(q, k, v, qkf, attnp);

    // 4) output projection + residual -> h (f32)
    gemm_cp<2, false><<<dim3(32, 8), 256, GEMMCP_SMEM>>>(attnp, wop, hs, h, D_SZ, D_SZ);

    // 5) pre-MLP hypersphere norm fused with fp16 A-permute
    hnorm_perm<<<MROWS, 256>>>(h, gmlp, xnp);

    // 6) MLP in + GELU -> mlp in fp16 A-perm layout
    gemm_cp<1, true><<<dim3(32, 32), 256, GEMMCP_SMEM>>>(xnp, winp, nullptr, mlpp, F_SZ, D_SZ);

    // 7) MLP out + residual -> d_out (f32)
    gemm_cp<2, false><<<dim3(32, 8), 256, GEMMCP_SMEM>>>(mlpp, woutp, h, out, D_SZ, F_SZ);
}

// round 15
// speedup vs baseline: 8.2092x; 1.0423x over previous
#include <cuda_runtime.h>
#include <cuda_fp16.h>
#include <math.h>
#include <stdint.h>

#define B_SZ 2
#define S_SZ 2048
#define D_SZ 2048
#define F_SZ 8192
#define H_SZ 16
#define HD   128
#define MROWS (B_SZ * S_SZ)   // 4096

// ---------------- scratch (device globals; no allocation) ----------------
__device__ uint32_t g_xnp [MROWS * D_SZ / 2];
__device__ uint32_t g_q   [MROWS * D_SZ / 2];
__device__ uint32_t g_k   [MROWS * D_SZ / 2];
__device__ uint32_t g_v   [MROWS * D_SZ / 2];
__device__ uint32_t g_attnp[MROWS * D_SZ / 2];
__device__ float    g_h   [MROWS * D_SZ];
__device__ uint32_t g_mlpp[(size_t)MROWS * F_SZ / 2];
__device__ uint32_t g_wqp [D_SZ * D_SZ / 2];
__device__ uint32_t g_wkp [D_SZ * D_SZ / 2];
__device__ uint32_t g_wvp [D_SZ * D_SZ / 2];
__device__ uint32_t g_wop [D_SZ * D_SZ / 2];
__device__ uint32_t g_winp[(size_t)F_SZ * D_SZ / 2];
__device__ uint32_t g_woutp[(size_t)D_SZ * F_SZ / 2];

// ==================== helpers ====================
__device__ __forceinline__ uint32_t h2u(float lo, float hi) {
    __half2 h = __floats2half2_rn(lo, hi);
    return *(uint32_t*)&h;
}
__device__ __forceinline__ float2 u2f(uint32_t u) {
    return __half22float2(*(__half2*)&u);
}
__device__ __forceinline__ uint32_t smem_u32(const void* p) {
    uint32_t a;
    asm("{ .reg .u64 t; cvta.to.shared.u64 t, %1; cvt.u32.u64 %0, t; }" : "=r"(a) : "l"(p));
    return a;
}
__device__ __forceinline__ void cp16(uint32_t saddr, const void* g) {
    asm volatile("cp.async.cg.shared.global [%0], [%1], 16;" :: "r"(saddr), "l"(g) : "memory");
}
__device__ __forceinline__ void mma_f16(float* d, const uint32_t* a, const uint32_t* b) {
    asm volatile(
        "mma.sync.aligned.m16n8k16.row.col.f32.f16.f16.f32 "
        "{%0,%1,%2,%3}, {%4,%5,%6,%7}, {%8,%9}, {%0,%1,%2,%3};"
        : "+f"(d[0]), "+f"(d[1]), "+f"(d[2]), "+f"(d[3])
        : "r"(a[0]), "r"(a[1]), "r"(a[2]), "r"(a[3]), "r"(b[0]), "r"(b[1]));
}
__device__ __forceinline__ float gelu_exact(float x) {
    return 0.5f * x * (1.f + erff(x * 0.7071067811865476f));
}

// fp16 A-perm u32 index for the half2 pair (col even) of element (row, col).
// Chunk (mt, kt) = 2048 u32: [s(2)][ma(8)][lane(32)][reg(4)].
__device__ __forceinline__ size_t hperm_u32(int row, int col, int Kdim) {
    const int mt = row >> 7, kt = col >> 5;
    const int s = (col >> 4) & 1, ma = (row >> 4) & 7;
    const int rr = row & 15, cc = col & 15;
    const int lane = (rr & 7) * 4 + ((cc >> 1) & 3);
    const int reg = (rr >> 3) + 2 * ((cc >> 3) & 1);
    return ((size_t)(mt * (Kdim >> 5) + kt) * 2048) + (((s * 8 + ma) * 32 + lane) << 2) + reg;
}

// ==================== weight permute (fp16 B-frag, coalesced uint4 writes) ====
__global__ void permute_w(const float* __restrict__ W, uint32_t* __restrict__ Wp,
                          int N, int K) {
    const int u = blockIdx.x * 256 + threadIdx.x;        // uint4 index
    const int chunk = u >> 10, o = u & 1023;
    const int ktn = K >> 5;
    const int nt = chunk / ktn, kt = chunk % ktn;
    const int lane = o & 31, pair = (o >> 5) & 15, s = o >> 9;
    const int n_lo = nt * 256 + pair * 16 + (lane >> 2);
    const int kb = kt * 32 + s * 16 + (lane & 3) * 2;
    float2 a0 = *(const float2*)(W + (size_t)n_lo * K + kb);
    float2 a1 = *(const float2*)(W + (size_t)n_lo * K + kb + 8);
    float2 a2 = *(const float2*)(W + (size_t)(n_lo + 8) * K + kb);
    float2 a3 = *(const float2*)(W + (size_t)(n_lo + 8) * K + kb + 8);
    uint4 r;
    r.x = h2u(a0.x, a0.y);
    r.y = h2u(a1.x, a1.y);
    r.z = h2u(a2.x, a2.y);
    r.w = h2u(a3.x, a3.y);
    ((uint4*)Wp)[u] = r;
}

// ==================== cp.async fp16 GEMM, BK=128, 2 stages ====================
// C[M,N] = A[M,K] @ W[N,K]^T. CTA 128x256, 8 warps (2m x 4n), warp 64x64.
// Stage (BK=128): A 8192 u32 (32KB) + B 16384 u32 (64KB) = 96KB. 2 stages = 192KB.
#define STAGE_U32 24576
#define GEMMCP_SMEM (2 * STAGE_U32 * 4)   // 196608

// EPI: 0 none, 1 GELU, 2 residual.
// OUT: 0 f32 row-major, 1 fp16 A-perm, 2 fp16 row-major (half2 packed).
template <int EPI, int OUT>
__device__ __forceinline__ void gemm_cp_body(
    const uint32_t* __restrict__ Ap, const uint32_t* __restrict__ Wp,
    const float* __restrict__ R, void* __restrict__ Cv,
    int N, int K, int mt, int nt, uint32_t* sm) {
    const uint32_t sb = smem_u32(sm);
    const int tid = threadIdx.x, lane = tid & 31, wid = tid >> 5;
    const int wm = wid >> 2, wn = wid & 3;
    const int NT32 = K >> 5;
    const int NT128 = K >> 7;
    const uint4* Agc = (const uint4*)Ap + (size_t)mt * NT32 * 512;
    const uint4* Bgc = (const uint4*)Wp + (size_t)nt * NT32 * 1024;

    float acc[4][8][4];
    #pragma unroll
    for (int i = 0; i < 4; i++)
        #pragma unroll
        for (int j = 0; j < 8; j++)
            #pragma unroll
            for (int r = 0; r < 4; r++) acc[i][j][r] = 0.f;

    auto issue = [&](int kt) {
        const int st = kt & 1;
        const uint32_t sa = sb + st * STAGE_U32 * 4;
        const uint4* ag = Agc + (size_t)kt * 2048;
        const uint4* bg = Bgc + (size_t)kt * 4096;
        #pragma unroll
        for (int i = 0; i < 8; i++)
            cp16(sa + (tid + 256 * i) * 16, ag + tid + 256 * i);
        const uint32_t sbb = sa + 8192 * 4;
        #pragma unroll
        for (int i = 0; i < 16; i++)
            cp16(sbb + (tid + 256 * i) * 16, bg + tid + 256 * i);
        asm volatile("cp.async.commit_group;" ::: "memory");
    };

    issue(0);

    for (int kt = 0; kt < NT128; kt++) {
        asm volatile("cp.async.wait_group 0;" ::: "memory");
        __syncthreads();
        if (kt + 1 < NT128) issue(kt + 1);

        const uint32_t* smA = sm + (kt & 1) * STAGE_U32;
        const uint32_t* smB = smA + 8192;

        uint32_t af[2][4][4], bf[2][4][4];
        auto ldfrag = [&](int s4, int buf) {
            const int chunk = s4 >> 1, s = s4 & 1;
            const uint32_t* A = smA + chunk * 2048;
            const uint32_t* Bp = smB + chunk * 4096;
            #pragma unroll
            for (int i = 0; i < 4; i++)
                *(uint4*)af[buf][i] = *(const uint4*)(A + (((s * 8 + wm * 4 + i) * 32 + lane) << 2));
            #pragma unroll
            for (int j = 0; j < 4; j++)
                *(uint4*)bf[buf][j] = *(const uint4*)(Bp + (((s * 16 + wn * 4 + j) * 32 + lane) << 2));
        };

        ldfrag(0, 0);
        #pragma unroll
        for (int s4 = 0; s4 < 8; s4++) {
            if (s4 < 7) ldfrag(s4 + 1, (s4 + 1) & 1);
            const int cb = s4 & 1;
            #pragma unroll
            for (int i = 0; i < 4; i++)
                #pragma unroll
                for (int jj = 0; jj < 4; jj++) {
                    mma_f16(acc[i][2 * jj],     af[cb][i], bf[cb][jj]);
                    mma_f16(acc[i][2 * jj + 1], af[cb][i], bf[cb][jj] + 2);
                }
        }
    }

    const int gid = lane >> 2, tig = lane & 3;
    #pragma unroll
    for (int i = 0; i < 4; i++) {
        #pragma unroll
        for (int j = 0; j < 8; j++) {
            const int row0 = mt * 128 + wm * 64 + i * 16 + gid;
            const int col  = nt * 256 + wn * 64 + j * 8 + tig * 2;
            float2 v0 = {acc[i][j][0], acc[i][j][1]};
            float2 v1 = {acc[i][j][2], acc[i][j][3]};
            if (EPI == 2) {
                float2 q0 = *(const float2*)(R + (size_t)row0 * N + col);
                float2 q1 = *(const float2*)(R + (size_t)(row0 + 8) * N + col);
                v0.x += q0.x; v0.y += q0.y;
                v1.x += q1.x; v1.y += q1.y;
            }
            if (EPI == 1) {
                v0.x = gelu_exact(v0.x); v0.y = gelu_exact(v0.y);
                v1.x = gelu_exact(v1.x); v1.y = gelu_exact(v1.y);
            }
            if (OUT == 1) {
                uint32_t* Ch = (uint32_t*)Cv;
                Ch[hperm_u32(row0, col, N)]     = h2u(v0.x, v0.y);
                Ch[hperm_u32(row0 + 8, col, N)] = h2u(v1.x, v1.y);
            } else if (OUT == 2) {
                uint32_t* Ch = (uint32_t*)Cv;
                Ch[(size_t)row0 * (N >> 1) + (col >> 1)]       = h2u(v0.x, v0.y);
                Ch[(size_t)(row0 + 8) * (N >> 1) + (col >> 1)] = h2u(v1.x, v1.y);
            } else {
                float* C = (float*)Cv;
                *(float2*)(C + (size_t)row0 * N + col) = v0;
                *(float2*)(C + (size_t)(row0 + 8) * N + col) = v1;
            }
        }
    }
}

template <int EPI, int OUT>
__global__ void __launch_bounds__(256, 1)
gemm_cp(const uint32_t* __restrict__ Ap, const uint32_t* __restrict__ Wp,
        const float* __restrict__ R, void* __restrict__ C, int N, int K) {
    extern __shared__ uint32_t smu[];
    gemm_cp_body<EPI, OUT>(Ap, Wp, R, C, N, K, blockIdx.x, blockIdx.y, smu);
}

// Fused QKV -> fp16 row-major outputs. grid.y = 24: which = y>>3, nt = y&7.
__global__ void __launch_bounds__(256, 1)
qkv_cp(const uint32_t* __restrict__ Ap,
       const uint32_t* __restrict__ wqp, const uint32_t* __restrict__ wkp,
       const uint32_t* __restrict__ wvp,
       uint32_t* __restrict__ q, uint32_t* __restrict__ k, uint32_t* __restrict__ v) {
    extern __shared__ uint32_t smu[];
    const int which = blockIdx.y >> 3;
    const uint32_t* Wp = (which == 0) ? wqp : (which == 1) ? wkp : wvp;
    uint32_t* C = (which == 0) ? q : (which == 1) ? k : v;
    gemm_cp_body<0, 2>(Ap, Wp, nullptr, C, D_SZ, D_SZ, blockIdx.x, blockIdx.y & 7, smu);
}

// ---------------- fused hypersphere norm + fp16 A-permute ----------------
__global__ void hnorm_perm(const float* __restrict__ x, const float* __restrict__ g,
                           uint32_t* __restrict__ Ap) {
    const int row = blockIdx.x;
    const float* xr = x + (size_t)row * D_SZ;
    float ss = 0.f;
    for (int i = threadIdx.x; i < D_SZ; i += blockDim.x) {
        float v = xr[i];
        ss += v * v;
    }
    __shared__ float red[32];
    #pragma unroll
    for (int o = 16; o; o >>= 1) ss += __shfl_xor_sync(0xffffffffu, ss, o);
    if ((threadIdx.x & 31) == 0) red[threadIdx.x >> 5] = ss;
    __syncthreads();
    if (threadIdx.x < 32) {
        float v = (threadIdx.x < (blockDim.x >> 5)) ? red[threadIdx.x] : 0.f;
        #pragma unroll
        for (int o = 16; o; o >>= 1) v += __shfl_xor_sync(0xffffffffu, v, o);
        if (threadIdx.x == 0) red[0] = v;
    }
    __syncthreads();
    const float n = sqrtf(red[0]);
    const float scale = 45.254833995939045f / (n + 1e-6f);  // sqrt(2048)
    #pragma unroll
    for (int i = 0; i < 4; i++) {
        const int col = (threadIdx.x + 256 * i) * 2;
        float2 xv = *(const float2*)(xr + col);
        float2 gv = *(const float2*)(g + col);
        Ap[hperm_u32(row, col, D_SZ)] = h2u(xv.x * scale * gv.x, xv.y * scale * gv.y);
    }
}

// ==================== Flash attention, fp16 q/k/v inputs ====================
#define FL_SQ  0
#define FL_SK  8192
#define FL_SVT 12288
#define FL_SP  16384
#define FLASH_SMEM (20480 * 4)

__global__ void __launch_bounds__(256, 1)
flash_mma(const uint32_t* __restrict__ Q, const uint32_t* __restrict__ K,
          const uint32_t* __restrict__ V, const float* __restrict__ scale_p,
          uint32_t* __restrict__ O) {
    extern __shared__ uint32_t fsu[];
    uint32_t* sQ  = fsu + FL_SQ;
    uint32_t* sK  = fsu + FL_SK;
    uint32_t* sVt = fsu + FL_SVT;
    uint32_t* sP  = fsu + FL_SP;

    const int qt = gridDim.x - 1 - blockIdx.x;
    const int bh = blockIdx.y;
    const int b = bh >> 4, h = bh & 15;
    const float scale = *scale_p;
    const int tid = threadIdx.x;
    const int lane = tid & 31;
    const int wid = tid >> 5;

    const size_t base2 = (size_t)b * S_SZ * (D_SZ / 2) + (size_t)h * (HD / 2);

    // ---- stage Q: fused row-norm (2 lanes/row) + qk scale, fp16 A-frag ----
    {
        const int r = tid >> 1;
        const int ma = r >> 4, rr = r & 15;
        const uint4* qrow4 = (const uint4*)(Q + base2 + (size_t)(qt * 128 + r) * (D_SZ / 2));
        float ssq = 0.f;
        #pragma unroll
        for (int i = 0; i < 8; i++) {
            uint4 w = qrow4[(tid & 1) * 8 + i];
            float2 f0 = u2f(w.x), f1 = u2f(w.y), f2 = u2f(w.z), f3 = u2f(w.w);
            ssq += f0.x * f0.x + f0.y * f0.y + f1.x * f1.x + f1.y * f1.y
                 + f2.x * f2.x + f2.y * f2.y + f3.x * f3.x + f3.y * f3.y;
        }
        ssq += __shfl_xor_sync(0xffffffffu, ssq, 1);
        const float qs = scale / (sqrtf(ssq) + 1e-6f);
        #pragma unroll
        for (int i = 0; i < 8; i++) {
            uint4 w = qrow4[(tid & 1) * 8 + i];
            const int cb = (tid & 1) * 64 + 8 * i;      // element col base (cb%8==0)
            const int chunk = cb >> 4;
            const int reg = (rr >> 3) + 2 * ((cb >> 3) & 1);
            uint32_t* dst = sQ + (((chunk * 8 + ma) * 32 + (rr & 7) * 4) << 2) + reg;
            float2 f0 = u2f(w.x), f1 = u2f(w.y), f2 = u2f(w.z), f3 = u2f(w.w);
            dst[0]  = h2u(f0.x * qs, f0.y * qs);
            dst[4]  = h2u(f1.x * qs, f1.y * qs);
            dst[8]  = h2u(f2.x * qs, f2.y * qs);
            dst[12] = h2u(f3.x * qs, f3.y * qs);
        }
    }

    float o[16][4];
    #pragma unroll
    for (int i = 0; i < 16; i++)
        #pragma unroll
        for (int r = 0; r < 4; r++) o[i][r] = 0.f;
    float m_run[2] = {-INFINITY, -INFINITY};
    float l_run[2] = {0.f, 0.f};

    const int NKT = 2 * qt + 2;
    for (int kt = 0; kt < NKT; kt++) {
        __syncthreads();
        // ---- stage K (fused row-norm, 4 lanes/row) and V^T ----
        {
            const int n0 = tid >> 2;
            const uint4* krow4 = (const uint4*)(K + base2 + (size_t)(kt * 64 + n0) * (D_SZ / 2));
            const uint4* vrow4 = (const uint4*)(V + base2 + (size_t)(kt * 64 + n0) * (D_SZ / 2));
            float ssk = 0.f;
            #pragma unroll
            for (int i = 0; i < 4; i++) {
                uint4 w = krow4[(tid & 3) + 4 * i];
                float2 f0 = u2f(w.x), f1 = u2f(w.y), f2 = u2f(w.z), f3 = u2f(w.w);
                ssk += f0.x * f0.x + f0.y * f0.y + f1.x * f1.x + f1.y * f1.y
                     + f2.x * f2.x + f2.y * f2.y + f3.x * f3.x + f3.y * f3.y;
            }
            ssk += __shfl_xor_sync(0xffffffffu, ssk, 1);
            ssk += __shfl_xor_sync(0xffffffffu, ssk, 2);
            const float ks = 1.f / (sqrtf(ssk) + 1e-6f);
            __half* sVtH = (__half*)sVt;
            const int vchunk = n0 >> 4, hbit = n0 & 1, lb0 = (n0 & 7) >> 1;
            #pragma unroll
            for (int i = 0; i < 4; i++) {
                const int u = (tid & 3) + 4 * i;        // uint4 idx within row (0..15)
                // K fragment (B-frag)
                {
                    uint4 w = krow4[u];
                    const int chunk = u >> 1;
                    const int pair = n0 >> 4;
                    const int reg = ((n0 >> 3) & 1) * 2 + (u & 1);
                    uint32_t* dk = sK + (((chunk * 4 + pair) * 32 + (n0 & 7) * 4) << 2) + reg;
                    float2 f0 = u2f(w.x), f1 = u2f(w.y), f2 = u2f(w.z), f3 = u2f(w.w);
                    dk[0]  = h2u(f0.x * ks, f0.y * ks);
                    dk[4]  = h2u(f1.x * ks, f1.y * ks);
                    dk[8]  = h2u(f2.x * ks, f2.y * ks);
                    dk[12] = h2u(f3.x * ks, f3.y * ks);
                }
                // V^T fragment (B-frag, halves copied bit-exact)
                {
                    uint4 w = vrow4[u];
                    const __half* wh = (const __half*)&w;
                    const int pair = u >> 1;
                    const int regv = (u & 1) * 2 + ((n0 >> 3) & 1);
                    const uint32_t ub = (((vchunk * 8 + pair) * 32 + lb0) << 2) + regv;
                    #pragma unroll
                    for (int e = 0; e < 8; e++)
                        sVtH[(ub + e * 16) * 2 + hbit] = wh[e];
                }
            }
        }
        __syncthreads();

        // ---- S = Q @ K^T ----
        float sacc[8][4];
        #pragma unroll
        for (int j = 0; j < 8; j++)
            #pragma unroll
            for (int r = 0; r < 4; r++) sacc[j][r] = 0.f;
        #pragma unroll
        for (int c = 0; c < 8; c++) {
            uint32_t af[4];
            *(uint4*)af = *(const uint4*)(sQ + (((c * 8 + wid) * 32 + lane) << 2));
            #pragma unroll
            for (int j2 = 0; j2 < 4; j2++) {
                uint32_t bf[4];
                *(uint4*)bf = *(const uint4*)(sK + (((c * 4 + j2) * 32 + lane) << 2));
                mma_f16(sacc[2 * j2],     af, bf);
                mma_f16(sacc[2 * j2 + 1], af, bf + 2);
            }
        }

        if (kt >= 2 * qt) {
            const int rbase = qt * 128 + wid * 16 + (lane >> 2);
            const int cbase = kt * 64 + 2 * (lane & 3);
            #pragma unroll
            for (int j = 0; j < 8; j++)
                #pragma unroll
                for (int r = 0; r < 4; r++) {
                    const int row = rbase + ((r >> 1) << 3);
                    const int col = cbase + j * 8 + (r & 1);
                    if (col > row) sacc[j][r] = -INFINITY;
                }
        }

        #pragma unroll
        for (int hh = 0; hh < 2; hh++) {
            float mt = -INFINITY;
            #pragma unroll
            for (int j = 0; j < 8; j++)
                mt = fmaxf(mt, fmaxf(sacc[j][2 * hh], sacc[j][2 * hh + 1]));
            mt = fmaxf(mt, __shfl_xor_sync(0xffffffffu, mt, 1));
            mt = fmaxf(mt, __shfl_xor_sync(0xffffffffu, mt, 2));
            const bool skip = (mt == -INFINITY);
            const float mold = m_run[hh];
            const float mnew = skip ? mold : fmaxf(mold, mt);
            const float msafe = (mnew == -INFINITY) ? 0.f : mnew;
            const float alpha = skip ? 1.f : __expf(mold - mnew);
            float sum = 0.f;
            #pragma unroll
            for (int j = 0; j < 8; j++) {
                float p0 = __expf(sacc[j][2 * hh]     - msafe);
                float p1 = __expf(sacc[j][2 * hh + 1] - msafe);
                sacc[j][2 * hh]     = p0;
                sacc[j][2 * hh + 1] = p1;
                sum += p0 + p1;
            }
            sum += __shfl_xor_sync(0xffffffffu, sum, 1);
            sum += __shfl_xor_sync(0xffffffffu, sum, 2);
            l_run[hh] = l_run[hh] * alpha + sum;
            m_run[hh] = mnew;
            #pragma unroll
            for (int j = 0; j < 16; j++) {
                o[j][2 * hh]     *= alpha;
                o[j][2 * hh + 1] *= alpha;
            }
        }

        __syncwarp();
        {
            const int rlow = lane >> 2, qq = lane & 3;
            #pragma unroll
            for (int j = 0; j < 8; j++) {
                #pragma unroll
                for (int hh = 0; hh < 2; hh++) {
                    const int lt = rlow * 4 + qq;
                    const int rt = hh + 2 * (j & 1);
                    sP[((((j >> 1) * 8 + wid) * 32 + lt) << 2) + rt] =
                        h2u(sacc[j][2 * hh], sacc[j][2 * hh + 1]);
                }
            }
        }
        __syncwarp();

        #pragma unroll
        for (int c = 0; c < 4; c++) {
            uint32_t af[4];
            *(uint4*)af = *(const uint4*)(sP + (((c * 8 + wid) * 32 + lane) << 2));
            #pragma unroll
            for (int j2 = 0; j2 < 8; j2++) {
                uint32_t bf[4];
                *(uint4*)bf = *(const uint4*)(sVt + (((c * 8 + j2) * 32 + lane) << 2));
                mma_f16(o[2 * j2],     af, bf);
                mma_f16(o[2 * j2 + 1], af, bf + 2);
            }
        }
    }

    const float il0 = 1.f / l_run[0];
    const float il1 = 1.f / l_run[1];
    const int grow = b * S_SZ + qt * 128 + wid * 16 + (lane >> 2);
    #pragma unroll
    for (int j = 0; j < 16; j++) {
        const int col = h * HD + j * 8 + 2 * (lane & 3);
        O[hperm_u32(grow, col, D_SZ)]     = h2u(o[j][0] * il0, o[j][1] * il0);
        O[hperm_u32(grow + 8, col, D_SZ)] = h2u(o[j][2] * il1, o[j][3] * il1);
    }
}

// ---------------- driver ----------------
extern "C" void kernel_launch(void* const* d_in, const int* in_sizes, int n_in,
                              void* d_out, int out_size) {
    const float* hs    = (const float*)d_in[0];
    const float* Wq    = (const float*)d_in[1];
    const float* Wk    = (const float*)d_in[2];
    const float* Wv    = (const float*)d_in[3];
    const float* Wo    = (const float*)d_in[4];
    const float* Win   = (const float*)d_in[5];
    const float* Wout  = (const float*)d_in[6];
    const float* qkf   = (const float*)d_in[7];
    const float* gattn = (const float*)d_in[8];
    const float* gmlp  = (const float*)d_in[9];
    float* out = (float*)d_out;

    uint32_t *xnp, *q, *k, *v, *attnp, *mlpp, *wqp, *wkp, *wvp, *wop, *winp, *woutp;
    float *h;
    cudaGetSymbolAddress((void**)&xnp,   g_xnp);
    cudaGetSymbolAddress((void**)&q,     g_q);
    cudaGetSymbolAddress((void**)&k,     g_k);
    cudaGetSymbolAddress((void**)&v,     g_v);
    cudaGetSymbolAddress((void**)&attnp, g_attnp);
    cudaGetSymbolAddress((void**)&h,     g_h);
    cudaGetSymbolAddress((void**)&mlpp,  g_mlpp);
    cudaGetSymbolAddress((void**)&wqp,   g_wqp);
    cudaGetSymbolAddress((void**)&wkp,   g_wkp);
    cudaGetSymbolAddress((void**)&wvp,   g_wvp);
    cudaGetSymbolAddress((void**)&wop,   g_wop);
    cudaGetSymbolAddress((void**)&winp,  g_winp);
    cudaGetSymbolAddress((void**)&woutp, g_woutp);

    cudaFuncSetAttribute(flash_mma, cudaFuncAttributeMaxDynamicSharedMemorySize, FLASH_SMEM);
    cudaFuncSetAttribute(qkv_cp, cudaFuncAttributeMaxDynamicSharedMemorySize, GEMMCP_SMEM);
    cudaFuncSetAttribute(gemm_cp<1, 1>, cudaFuncAttributeMaxDynamicSharedMemorySize, GEMMCP_SMEM);
    cudaFuncSetAttribute(gemm_cp<2, 0>, cudaFuncAttributeMaxDynamicSharedMemorySize, GEMMCP_SMEM);

    // 0) permute weights to fp16 fragment order
    permute_w<<<D_SZ * D_SZ / 8 / 256, 256>>>(Wq, wqp, D_SZ, D_SZ);
    permute_w<<<D_SZ * D_SZ / 8 / 256, 256>>>(Wk, wkp, D_SZ, D_SZ);
    permute_w<<<D_SZ * D_SZ / 8 / 256, 256>>>(Wv, wvp, D_SZ, D_SZ);
    permute_w<<<D_SZ * D_SZ / 8 / 256, 256>>>(Wo, wop, D_SZ, D_SZ);
    permute_w<<<F_SZ * D_SZ / 8 / 256, 256>>>(Win, winp, F_SZ, D_SZ);
    permute_w<<<F_SZ * D_SZ / 8 / 256, 256>>>(Wout, woutp, D_SZ, F_SZ);

    // 1) pre-attn hypersphere norm fused with fp16 A-permute
    hnorm_perm<<<MROWS, 256>>>(hs, gattn, xnp);

    // 2) fused QKV projection -> fp16 row-major q/k/v
    qkv_cp<<<dim3(MROWS / 128, 24), 256, GEMMCP_SMEM>>>(xnp, wqp, wkp, wvp, q, k, v);

    // 3) causal attention -> attn in fp16 A-perm layout
    flash_mma<<<dim3(S_SZ / 128, B_SZ * H_SZ), 256, FLASH_SMEM>>>(q, k, v, qkf, attnp);

    // 4) output projection + residual -> h (f32)
    gemm_cp<2, 0><<<dim3(32, 8), 256, GEMMCP_SMEM>>>(attnp, wop, hs, h, D_SZ, D_SZ);

    // 5) pre-MLP hypersphere norm fused with fp16 A-permute
    hnorm_perm<<<MROWS, 256>>>(h, gmlp, xnp);

    // 6) MLP in + GELU -> mlp in fp16 A-perm layout
    gemm_cp<1, 1><<<dim3(32, 32), 256, GEMMCP_SMEM>>>(xnp, winp, nullptr, mlpp, F_SZ, D_SZ);

    // 7) MLP out + residual -> d_out (f32)
    gemm_cp<2, 0><<<dim3(32, 8), 256, GEMMCP_SMEM>>>(mlpp, woutp, h, out, D_SZ, F_SZ);
}

// round 16
// speedup vs baseline: 8.3923x; 1.0223x over previous
#include <cuda_runtime.h>
#include <cuda_fp16.h>
#include <math.h>
#include <stdint.h>

#define B_SZ 2
#define S_SZ 2048
#define D_SZ 2048
#define F_SZ 8192
#define H_SZ 16
#define HD   128
#define MROWS (B_SZ * S_SZ)   // 4096

// ---------------- scratch (device globals; no allocation) ----------------
__device__ uint32_t g_xnp [MROWS * D_SZ / 2];
__device__ uint32_t g_q   [MROWS * D_SZ / 2];
__device__ uint32_t g_k   [MROWS * D_SZ / 2];
__device__ uint32_t g_v   [MROWS * D_SZ / 2];
__device__ uint32_t g_attnp[MROWS * D_SZ / 2];
__device__ float    g_h   [MROWS * D_SZ];
__device__ uint32_t g_mlpp[(size_t)MROWS * F_SZ / 2];
__device__ uint32_t g_wqp [D_SZ * D_SZ / 2];
__device__ uint32_t g_wkp [D_SZ * D_SZ / 2];
__device__ uint32_t g_wvp [D_SZ * D_SZ / 2];
__device__ uint32_t g_wop [D_SZ * D_SZ / 2];
__device__ uint32_t g_winp[(size_t)F_SZ * D_SZ / 2];
__device__ uint32_t g_woutp[(size_t)D_SZ * F_SZ / 2];

// ==================== helpers ====================
__device__ __forceinline__ uint32_t h2u(float lo, float hi) {
    __half2 h = __floats2half2_rn(lo, hi);
    return *(uint32_t*)&h;
}
__device__ __forceinline__ float2 u2f(uint32_t u) {
    return __half22float2(*(__half2*)&u);
}
__device__ __forceinline__ uint32_t smem_u32(const void* p) {
    uint32_t a;
    asm("{ .reg .u64 t; cvta.to.shared.u64 t, %1; cvt.u32.u64 %0, t; }" : "=r"(a) : "l"(p));
    return a;
}
__device__ __forceinline__ void cp16(uint32_t saddr, const void* g) {
    asm volatile("cp.async.cg.shared.global [%0], [%1], 16;" :: "r"(saddr), "l"(g) : "memory");
}
__device__ __forceinline__ void mma_f16(float* d, const uint32_t* a, const uint32_t* b) {
    asm volatile(
        "mma.sync.aligned.m16n8k16.row.col.f32.f16.f16.f32 "
        "{%0,%1,%2,%3}, {%4,%5,%6,%7}, {%8,%9}, {%0,%1,%2,%3};"
        : "+f"(d[0]), "+f"(d[1]), "+f"(d[2]), "+f"(d[3])
        : "r"(a[0]), "r"(a[1]), "r"(a[2]), "r"(a[3]), "r"(b[0]), "r"(b[1]));
}
__device__ __forceinline__ float gelu_exact(float x) {
    return 0.5f * x * (1.f + erff(x * 0.7071067811865476f));
}

// fp16 A-perm u32 index for the half2 pair (col even) of element (row, col).
// Chunk (mt, kt) = 2048 u32: [s(2)][ma(8)][lane(32)][reg(4)].
__device__ __forceinline__ size_t hperm_u32(int row, int col, int Kdim) {
    const int mt = row >> 7, kt = col >> 5;
    const int s = (col >> 4) & 1, ma = (row >> 4) & 7;
    const int rr = row & 15, cc = col & 15;
    const int lane = (rr & 7) * 4 + ((cc >> 1) & 3);
    const int reg = (rr >> 3) + 2 * ((cc >> 3) & 1);
    return ((size_t)(mt * (Kdim >> 5) + kt) * 2048) + (((s * 8 + ma) * 32 + lane) << 2) + reg;
}

// ==================== fused weight permute (all 6 weights, one launch) ====
// block ranges: [0,2048)x4 for Wq/Wk/Wv/Wo (D*D), [8192,16384) Win (F*D),
// [16384,24576) Wout (D*F).
__global__ void permute_all(
    const float* __restrict__ Wq, const float* __restrict__ Wk,
    const float* __restrict__ Wv, const float* __restrict__ Wo,
    const float* __restrict__ Win, const float* __restrict__ Wout,
    uint32_t* __restrict__ wqp, uint32_t* __restrict__ wkp,
    uint32_t* __restrict__ wvp, uint32_t* __restrict__ wop,
    uint32_t* __restrict__ winp, uint32_t* __restrict__ woutp) {
    const int bid = blockIdx.x;
    const float* W; uint32_t* Wp; int K, b0;
    if (bid < 8192) {
        const int sel = bid >> 11;
        b0 = sel << 11;
        K = D_SZ;
        W  = (sel == 0) ? Wq  : (sel == 1) ? Wk  : (sel == 2) ? Wv  : Wo;
        Wp = (sel == 0) ? wqp : (sel == 1) ? wkp : (sel == 2) ? wvp : wop;
    } else if (bid < 16384) {
        b0 = 8192;  K = D_SZ; W = Win;  Wp = winp;
    } else {
        b0 = 16384; K = F_SZ; W = Wout; Wp = woutp;
    }
    const int u = (bid - b0) * 256 + threadIdx.x;        // uint4 index
    const int chunk = u >> 10, o = u & 1023;
    const int ktn = K >> 5;
    const int nt = chunk / ktn, kt = chunk % ktn;
    const int lane = o & 31, pair = (o >> 5) & 15, s = o >> 9;
    const int n_lo = nt * 256 + pair * 16 + (lane >> 2);
    const int kb = kt * 32 + s * 16 + (lane & 3) * 2;
    float2 a0 = *(const float2*)(W + (size_t)n_lo * K + kb);
    float2 a1 = *(const float2*)(W + (size_t)n_lo * K + kb + 8);
    float2 a2 = *(const float2*)(W + (size_t)(n_lo + 8) * K + kb);
    float2 a3 = *(const float2*)(W + (size_t)(n_lo + 8) * K + kb + 8);
    uint4 r;
    r.x = h2u(a0.x, a0.y);
    r.y = h2u(a1.x, a1.y);
    r.z = h2u(a2.x, a2.y);
    r.w = h2u(a3.x, a3.y);
    ((uint4*)Wp)[u] = r;
}

// ==================== cp.async fp16 GEMM, BK=128, 2 stages (unchanged) ====
#define STAGE_U32 24576
#define GEMMCP_SMEM (2 * STAGE_U32 * 4)   // 196608

// EPI: 0 none, 1 GELU, 2 residual.
// OUT: 0 f32 row-major, 1 fp16 A-perm, 2 fp16 row-major (half2 packed).
template <int EPI, int OUT>
__device__ __forceinline__ void gemm_cp_body(
    const uint32_t* __restrict__ Ap, const uint32_t* __restrict__ Wp,
    const float* __restrict__ R, void* __restrict__ Cv,
    int N, int K, int mt, int nt, uint32_t* sm) {
    const uint32_t sb = smem_u32(sm);
    const int tid = threadIdx.x, lane = tid & 31, wid = tid >> 5;
    const int wm = wid >> 2, wn = wid & 3;
    const int NT32 = K >> 5;
    const int NT128 = K >> 7;
    const uint4* Agc = (const uint4*)Ap + (size_t)mt * NT32 * 512;
    const uint4* Bgc = (const uint4*)Wp + (size_t)nt * NT32 * 1024;

    float acc[4][8][4];
    #pragma unroll
    for (int i = 0; i < 4; i++)
        #pragma unroll
        for (int j = 0; j < 8; j++)
            #pragma unroll
            for (int r = 0; r < 4; r++) acc[i][j][r] = 0.f;

    auto issue = [&](int kt) {
        const int st = kt & 1;
        const uint32_t sa = sb + st * STAGE_U32 * 4;
        const uint4* ag = Agc + (size_t)kt * 2048;
        const uint4* bg = Bgc + (size_t)kt * 4096;
        #pragma unroll
        for (int i = 0; i < 8; i++)
            cp16(sa + (tid + 256 * i) * 16, ag + tid + 256 * i);
        const uint32_t sbb = sa + 8192 * 4;
        #pragma unroll
        for (int i = 0; i < 16; i++)
            cp16(sbb + (tid + 256 * i) * 16, bg + tid + 256 * i);
        asm volatile("cp.async.commit_group;" ::: "memory");
    };

    issue(0);

    for (int kt = 0; kt < NT128; kt++) {
        asm volatile("cp.async.wait_group 0;" ::: "memory");
        __syncthreads();
        if (kt + 1 < NT128) issue(kt + 1);

        const uint32_t* smA = sm + (kt & 1) * STAGE_U32;
        const uint32_t* smB = smA + 8192;

        uint32_t af[2][4][4], bf[2][4][4];
        auto ldfrag = [&](int s4, int buf) {
            const int chunk = s4 >> 1, s = s4 & 1;
            const uint32_t* A = smA + chunk * 2048;
            const uint32_t* Bp = smB + chunk * 4096;
            #pragma unroll
            for (int i = 0; i < 4; i++)
                *(uint4*)af[buf][i] = *(const uint4*)(A + (((s * 8 + wm * 4 + i) * 32 + lane) << 2));
            #pragma unroll
            for (int j = 0; j < 4; j++)
                *(uint4*)bf[buf][j] = *(const uint4*)(Bp + (((s * 16 + wn * 4 + j) * 32 + lane) << 2));
        };

        ldfrag(0, 0);
        #pragma unroll
        for (int s4 = 0; s4 < 8; s4++) {
            if (s4 < 7) ldfrag(s4 + 1, (s4 + 1) & 1);
            const int cb = s4 & 1;
            #pragma unroll
            for (int i = 0; i < 4; i++)
                #pragma unroll
                for (int jj = 0; jj < 4; jj++) {
                    mma_f16(acc[i][2 * jj],     af[cb][i], bf[cb][jj]);
                    mma_f16(acc[i][2 * jj + 1], af[cb][i], bf[cb][jj] + 2);
                }
        }
    }

    const int gid = lane >> 2, tig = lane & 3;
    #pragma unroll
    for (int i = 0; i < 4; i++) {
        #pragma unroll
        for (int j = 0; j < 8; j++) {
            const int row0 = mt * 128 + wm * 64 + i * 16 + gid;
            const int col  = nt * 256 + wn * 64 + j * 8 + tig * 2;
            float2 v0 = {acc[i][j][0], acc[i][j][1]};
            float2 v1 = {acc[i][j][2], acc[i][j][3]};
            if (EPI == 2) {
                float2 q0 = *(const float2*)(R + (size_t)row0 * N + col);
                float2 q1 = *(const float2*)(R + (size_t)(row0 + 8) * N + col);
                v0.x += q0.x; v0.y += q0.y;
                v1.x += q1.x; v1.y += q1.y;
            }
            if (EPI == 1) {
                v0.x = gelu_exact(v0.x); v0.y = gelu_exact(v0.y);
                v1.x = gelu_exact(v1.x); v1.y = gelu_exact(v1.y);
            }
            if (OUT == 1) {
                uint32_t* Ch = (uint32_t*)Cv;
                Ch[hperm_u32(row0, col, N)]     = h2u(v0.x, v0.y);
                Ch[hperm_u32(row0 + 8, col, N)] = h2u(v1.x, v1.y);
            } else if (OUT == 2) {
                uint32_t* Ch = (uint32_t*)Cv;
                Ch[(size_t)row0 * (N >> 1) + (col >> 1)]       = h2u(v0.x, v0.y);
                Ch[(size_t)(row0 + 8) * (N >> 1) + (col >> 1)] = h2u(v1.x, v1.y);
            } else {
                float* C = (float*)Cv;
                *(float2*)(C + (size_t)row0 * N + col) = v0;
                *(float2*)(C + (size_t)(row0 + 8) * N + col) = v1;
            }
        }
    }
}

template <int EPI, int OUT>
__global__ void __launch_bounds__(256, 1)
gemm_cp(const uint32_t* __restrict__ Ap, const uint32_t* __restrict__ Wp,
        const float* __restrict__ R, void* __restrict__ C, int N, int K) {
    extern __shared__ uint32_t smu[];
    gemm_cp_body<EPI, OUT>(Ap, Wp, R, C, N, K, blockIdx.x, blockIdx.y, smu);
}

// Fused QKV -> fp16 row-major outputs. grid.y = 24: which = y>>3, nt = y&7.
__global__ void __launch_bounds__(256, 1)
qkv_cp(const uint32_t* __restrict__ Ap,
       const uint32_t* __restrict__ wqp, const uint32_t* __restrict__ wkp,
       const uint32_t* __restrict__ wvp,
       uint32_t* __restrict__ q, uint32_t* __restrict__ k, uint32_t* __restrict__ v) {
    extern __shared__ uint32_t smu[];
    const int which = blockIdx.y >> 3;
    const uint32_t* Wp = (which == 0) ? wqp : (which == 1) ? wkp : wvp;
    uint32_t* C = (which == 0) ? q : (which == 1) ? k : v;
    gemm_cp_body<0, 2>(Ap, Wp, nullptr, C, D_SZ, D_SZ, blockIdx.x, blockIdx.y & 7, smu);
}

// ---------------- fused hypersphere norm + fp16 A-permute ----------------
__global__ void hnorm_perm(const float* __restrict__ x, const float* __restrict__ g,
                           uint32_t* __restrict__ Ap) {
    const int row = blockIdx.x;
    const float* xr = x + (size_t)row * D_SZ;
    float ss = 0.f;
    for (int i = threadIdx.x; i < D_SZ; i += blockDim.x) {
        float v = xr[i];
        ss += v * v;
    }
    __shared__ float red[32];
    #pragma unroll
    for (int o = 16; o; o >>= 1) ss += __shfl_xor_sync(0xffffffffu, ss, o);
    if ((threadIdx.x & 31) == 0) red[threadIdx.x >> 5] = ss;
    __syncthreads();
    if (threadIdx.x < 32) {
        float v = (threadIdx.x < (blockDim.x >> 5)) ? red[threadIdx.x] : 0.f;
        #pragma unroll
        for (int o = 16; o; o >>= 1) v += __shfl_xor_sync(0xffffffffu, v, o);
        if (threadIdx.x == 0) red[0] = v;
    }
    __syncthreads();
    const float n = sqrtf(red[0]);
    const float scale = 45.254833995939045f / (n + 1e-6f);  // sqrt(2048)
    #pragma unroll
    for (int i = 0; i < 4; i++) {
        const int col = (threadIdx.x + 256 * i) * 2;
        float2 xv = *(const float2*)(xr + col);
        float2 gv = *(const float2*)(g + col);
        Ap[hperm_u32(row, col, D_SZ)] = h2u(xv.x * scale * gv.x, xv.y * scale * gv.y);
    }
}

// ==================== Flash attention, fp16 q/k/v, gmem prefetch ====================
#define FL_SQ  0
#define FL_SK  8192
#define FL_SVT 12288
#define FL_SP  16384
#define FLASH_SMEM (20480 * 4)

__global__ void __launch_bounds__(256, 1)
flash_mma(const uint32_t* __restrict__ Q, const uint32_t* __restrict__ K,
          const uint32_t* __restrict__ V, const float* __restrict__ scale_p,
          uint32_t* __restrict__ O) {
    extern __shared__ uint32_t fsu[];
    uint32_t* sQ  = fsu + FL_SQ;
    uint32_t* sK  = fsu + FL_SK;
    uint32_t* sVt = fsu + FL_SVT;
    uint32_t* sP  = fsu + FL_SP;

    const int qt = gridDim.x - 1 - blockIdx.x;
    const int bh = blockIdx.y;
    const int b = bh >> 4, h = bh & 15;
    const float scale = *scale_p;
    const int tid = threadIdx.x;
    const int lane = tid & 31;
    const int wid = tid >> 5;

    const size_t base2 = (size_t)b * S_SZ * (D_SZ / 2) + (size_t)h * (HD / 2);

    // ---- stage Q: fused row-norm (2 lanes/row) + qk scale, fp16 A-frag ----
    {
        const int r = tid >> 1;
        const int ma = r >> 4, rr = r & 15;
        const uint4* qrow4 = (const uint4*)(Q + base2 + (size_t)(qt * 128 + r) * (D_SZ / 2));
        float ssq = 0.f;
        #pragma unroll
        for (int i = 0; i < 8; i++) {
            uint4 w = qrow4[(tid & 1) * 8 + i];
            float2 f0 = u2f(w.x), f1 = u2f(w.y), f2 = u2f(w.z), f3 = u2f(w.w);
            ssq += f0.x * f0.x + f0.y * f0.y + f1.x * f1.x + f1.y * f1.y
                 + f2.x * f2.x + f2.y * f2.y + f3.x * f3.x + f3.y * f3.y;
        }
        ssq += __shfl_xor_sync(0xffffffffu, ssq, 1);
        const float qs = scale / (sqrtf(ssq) + 1e-6f);
        #pragma unroll
        for (int i = 0; i < 8; i++) {
            uint4 w = qrow4[(tid & 1) * 8 + i];
            const int cb = (tid & 1) * 64 + 8 * i;
            const int chunk = cb >> 4;
            const int reg = (rr >> 3) + 2 * ((cb >> 3) & 1);
            uint32_t* dst = sQ + (((chunk * 8 + ma) * 32 + (rr & 7) * 4) << 2) + reg;
            float2 f0 = u2f(w.x), f1 = u2f(w.y), f2 = u2f(w.z), f3 = u2f(w.w);
            dst[0]  = h2u(f0.x * qs, f0.y * qs);
            dst[4]  = h2u(f1.x * qs, f1.y * qs);
            dst[8]  = h2u(f2.x * qs, f2.y * qs);
            dst[12] = h2u(f3.x * qs, f3.y * qs);
        }
    }

    float o[16][4];
    #pragma unroll
    for (int i = 0; i < 16; i++)
        #pragma unroll
        for (int r = 0; r < 4; r++) o[i][r] = 0.f;
    float m_run[2] = {-INFINITY, -INFINITY};
    float l_run[2] = {0.f, 0.f};

    const int n0 = tid >> 2;
    uint4 kreg[4], vreg[4];
    auto ldkv = [&](int kt) {
        const uint4* kr = (const uint4*)(K + base2 + (size_t)(kt * 64 + n0) * (D_SZ / 2));
        const uint4* vr = (const uint4*)(V + base2 + (size_t)(kt * 64 + n0) * (D_SZ / 2));
        #pragma unroll
        for (int i = 0; i < 4; i++) {
            kreg[i] = kr[(tid & 3) + 4 * i];
            vreg[i] = vr[(tid & 3) + 4 * i];
        }
    };

    const int NKT = 2 * qt + 2;
    ldkv(0);
    for (int kt = 0; kt < NKT; kt++) {
        __syncthreads();   // previous iteration done reading sK/sVt
        // ---- stage K (fused row-norm from regs) and V^T ----
        {
            float ssk = 0.f;
            #pragma unroll
            for (int i = 0; i < 4; i++) {
                float2 f0 = u2f(kreg[i].x), f1 = u2f(kreg[i].y),
                       f2 = u2f(kreg[i].z), f3 = u2f(kreg[i].w);
                ssk += f0.x * f0.x + f0.y * f0.y + f1.x * f1.x + f1.y * f1.y
                     + f2.x * f2.x + f2.y * f2.y + f3.x * f3.x + f3.y * f3.y;
            }
            ssk += __shfl_xor_sync(0xffffffffu, ssk, 1);
            ssk += __shfl_xor_sync(0xffffffffu, ssk, 2);
            const float ks = 1.f / (sqrtf(ssk) + 1e-6f);
            __half* sVtH = (__half*)sVt;
            const int vchunk = n0 >> 4, hbit = n0 & 1, lb0 = (n0 & 7) >> 1;
            #pragma unroll
            for (int i = 0; i < 4; i++) {
                const int u = (tid & 3) + 4 * i;
                {
                    uint4 w = kreg[i];
                    const int chunk = u >> 1;
                    const int pair = n0 >> 4;
                    const int reg = ((n0 >> 3) & 1) * 2 + (u & 1);
                    uint32_t* dk = sK + (((chunk * 4 + pair) * 32 + (n0 & 7) * 4) << 2) + reg;
                    float2 f0 = u2f(w.x), f1 = u2f(w.y), f2 = u2f(w.z), f3 = u2f(w.w);
                    dk[0]  = h2u(f0.x * ks, f0.y * ks);
                    dk[4]  = h2u(f1.x * ks, f1.y * ks);
                    dk[8]  = h2u(f2.x * ks, f2.y * ks);
                    dk[12] = h2u(f3.x * ks, f3.y * ks);
                }
                {
                    uint4 w = vreg[i];
                    const __half* wh = (const __half*)&w;
                    const int pair = u >> 1;
                    const int regv = (u & 1) * 2 + ((n0 >> 3) & 1);
                    const uint32_t ub = (((vchunk * 8 + pair) * 32 + lb0) << 2) + regv;
                    #pragma unroll
                    for (int e = 0; e < 8; e++)
                        sVtH[(ub + e * 16) * 2 + hbit] = wh[e];
                }
            }
        }
        // prefetch next tile's K/V (latency hides behind mma below)
        if (kt + 1 < NKT) ldkv(kt + 1);
        __syncthreads();

        // ---- S = Q @ K^T ----
        float sacc[8][4];
        #pragma unroll
        for (int j = 0; j < 8; j++)
            #pragma unroll
            for (int r = 0; r < 4; r++) sacc[j][r] = 0.f;
        #pragma unroll
        for (int c = 0; c < 8; c++) {
            uint32_t af[4];
            *(uint4*)af = *(const uint4*)(sQ + (((c * 8 + wid) * 32 + lane) << 2));
            #pragma unroll
            for (int j2 = 0; j2 < 4; j2++) {
                uint32_t bf[4];
                *(uint4*)bf = *(const uint4*)(sK + (((c * 4 + j2) * 32 + lane) << 2));
                mma_f16(sacc[2 * j2],     af, bf);
                mma_f16(sacc[2 * j2 + 1], af, bf + 2);
            }
        }

        if (kt >= 2 * qt) {
            const int rbase = qt * 128 + wid * 16 + (lane >> 2);
            const int cbase = kt * 64 + 2 * (lane & 3);
            #pragma unroll
            for (int j = 0; j < 8; j++)
                #pragma unroll
                for (int r = 0; r < 4; r++) {
                    const int row = rbase + ((r >> 1) << 3);
                    const int col = cbase + j * 8 + (r & 1);
                    if (col > row) sacc[j][r] = -INFINITY;
                }
        }

        #pragma unroll
        for (int hh = 0; hh < 2; hh++) {
            float mt = -INFINITY;
            #pragma unroll
            for (int j = 0; j < 8; j++)
                mt = fmaxf(mt, fmaxf(sacc[j][2 * hh], sacc[j][2 * hh + 1]));
            mt = fmaxf(mt, __shfl_xor_sync(0xffffffffu, mt, 1));
            mt = fmaxf(mt, __shfl_xor_sync(0xffffffffu, mt, 2));
            const bool skip = (mt == -INFINITY);
            const float mold = m_run[hh];
            const float mnew = skip ? mold : fmaxf(mold, mt);
            const float msafe = (mnew == -INFINITY) ? 0.f : mnew;
            const float alpha = skip ? 1.f : __expf(mold - mnew);
            float sum = 0.f;
            #pragma unroll
            for (int j = 0; j < 8; j++) {
                float p0 = __expf(sacc[j][2 * hh]     - msafe);
                float p1 = __expf(sacc[j][2 * hh + 1] - msafe);
                sacc[j][2 * hh]     = p0;
                sacc[j][2 * hh + 1] = p1;
                sum += p0 + p1;
            }
            sum += __shfl_xor_sync(0xffffffffu, sum, 1);
            sum += __shfl_xor_sync(0xffffffffu, sum, 2);
            l_run[hh] = l_run[hh] * alpha + sum;
            m_run[hh] = mnew;
            #pragma unroll
            for (int j = 0; j < 16; j++) {
                o[j][2 * hh]     *= alpha;
                o[j][2 * hh + 1] *= alpha;
            }
        }

        __syncwarp();
        {
            const int rlow = lane >> 2, qq = lane & 3;
            #pragma unroll
            for (int j = 0; j < 8; j++) {
                #pragma unroll
                for (int hh = 0; hh < 2; hh++) {
                    const int lt = rlow * 4 + qq;
                    const int rt = hh + 2 * (j & 1);
                    sP[((((j >> 1) * 8 + wid) * 32 + lt) << 2) + rt] =
                        h2u(sacc[j][2 * hh], sacc[j][2 * hh + 1]);
                }
            }
        }
        __syncwarp();

        #pragma unroll
        for (int c = 0; c < 4; c++) {
            uint32_t af[4];
            *(uint4*)af = *(const uint4*)(sP + (((c * 8 + wid) * 32 + lane) << 2));
            #pragma unroll
            for (int j2 = 0; j2 < 8; j2++) {
                uint32_t bf[4];
                *(uint4*)bf = *(const uint4*)(sVt + (((c * 8 + j2) * 32 + lane) << 2));
                mma_f16(o[2 * j2],     af, bf);
                mma_f16(o[2 * j2 + 1], af, bf + 2);
            }
        }
    }

    const float il0 = 1.f / l_run[0];
    const float il1 = 1.f / l_run[1];
    const int grow = b * S_SZ + qt * 128 + wid * 16 + (lane >> 2);
    #pragma unroll
    for (int j = 0; j < 16; j++) {
        const int col = h * HD + j * 8 + 2 * (lane & 3);
        O[hperm_u32(grow, col, D_SZ)]     = h2u(o[j][0] * il0, o[j][1] * il0);
        O[hperm_u32(grow + 8, col, D_SZ)] = h2u(o[j][2] * il1, o[j][3] * il1);
    }
}

// ---------------- driver ----------------
extern "C" void kernel_launch(void* const* d_in, const int* in_sizes, int n_in,
                              void* d_out, int out_size) {
    const float* hs    = (const float*)d_in[0];
    const float* Wq    = (const float*)d_in[1];
    const float* Wk    = (const float*)d_in[2];
    const float* Wv    = (const float*)d_in[3];
    const float* Wo    = (const float*)d_in[4];
    const float* Win   = (const float*)d_in[5];
    const float* Wout  = (const float*)d_in[6];
    const float* qkf   = (const float*)d_in[7];
    const float* gattn = (const float*)d_in[8];
    const float* gmlp  = (const float*)d_in[9];
    float* out = (float*)d_out;

    uint32_t *xnp, *q, *k, *v, *attnp, *mlpp, *wqp, *wkp, *wvp, *wop, *winp, *woutp;
    float *h;
    cudaGetSymbolAddress((void**)&xnp,   g_xnp);
    cudaGetSymbolAddress((void**)&q,     g_q);
    cudaGetSymbolAddress((void**)&k,     g_k);
    cudaGetSymbolAddress((void**)&v,     g_v);
    cudaGetSymbolAddress((void**)&attnp, g_attnp);
    cudaGetSymbolAddress((void**)&h,     g_h);
    cudaGetSymbolAddress((void**)&mlpp,  g_mlpp);
    cudaGetSymbolAddress((void**)&wqp,   g_wqp);
    cudaGetSymbolAddress((void**)&wkp,   g_wkp);
    cudaGetSymbolAddress((void**)&wvp,   g_wvp);
    cudaGetSymbolAddress((void**)&wop,   g_wop);
    cudaGetSymbolAddress((void**)&winp,  g_winp);
    cudaGetSymbolAddress((void**)&woutp, g_woutp);

    cudaFuncSetAttribute(flash_mma, cudaFuncAttributeMaxDynamicSharedMemorySize, FLASH_SMEM);
    cudaFuncSetAttribute(qkv_cp, cudaFuncAttributeMaxDynamicSharedMemorySize, GEMMCP_SMEM);
    cudaFuncSetAttribute(gemm_cp<1, 1>, cudaFuncAttributeMaxDynamicSharedMemorySize, GEMMCP_SMEM);
    cudaFuncSetAttribute(gemm_cp<2, 0>, cudaFuncAttributeMaxDynamicSharedMemorySize, GEMMCP_SMEM);

    // 0) permute all weights to fp16 fragment order (one launch)
    permute_all<<<24576, 256>>>(Wq, Wk, Wv, Wo, Win, Wout,
                                wqp, wkp, wvp, wop, winp, woutp);

    // 1) pre-attn hypersphere norm fused with fp16 A-permute
    hnorm_perm<<<MROWS, 256>>>(hs, gattn, xnp);

    // 2) fused QKV projection -> fp16 row-major q/k/v
    qkv_cp<<<dim3(MROWS / 128, 24), 256, GEMMCP_SMEM>>>(xnp, wqp, wkp, wvp, q, k, v);

    // 3) causal attention -> attn in fp16 A-perm layout
    flash_mma<<<dim3(S_SZ / 128, B_SZ * H_SZ), 256, FLASH_SMEM>>>(q, k, v, qkf, attnp);

    // 4) output projection + residual -> h (f32)
    gemm_cp<2, 0><<<dim3(32, 8), 256, GEMMCP_SMEM>>>(attnp, wop, hs, h, D_SZ, D_SZ);

    // 5) pre-MLP hypersphere norm fused with fp16 A-permute
    hnorm_perm<<<MROWS, 256>>>(h, gmlp, xnp);

    // 6) MLP in + GELU -> mlp in fp16 A-perm layout
    gemm_cp<1, 1><<<dim3(32, 32), 256, GEMMCP_SMEM>>>(xnp, winp, nullptr, mlpp, F_SZ, D_SZ);

    // 7) MLP out + residual -> d_out (f32)
    gemm_cp<2, 0><<<dim3(32, 8), 256, GEMMCP_SMEM>>>(mlpp, woutp, h, out, D_SZ, F_SZ);
}

// round 17
// speedup vs baseline: 8.5311x; 1.0165x over previous
#include <cuda_runtime.h>
#include <cuda_fp16.h>
#include <math.h>
#include <stdint.h>

#define B_SZ 2
#define S_SZ 2048
#define D_SZ 2048
#define F_SZ 8192
#define H_SZ 16
#define HD   128
#define MROWS (B_SZ * S_SZ)   // 4096

// ---------------- scratch (device globals; no allocation) ----------------
__device__ uint32_t g_xnp [MROWS * D_SZ / 2];
__device__ uint32_t g_q   [MROWS * D_SZ / 2];
__device__ uint32_t g_k   [MROWS * D_SZ / 2];
__device__ uint32_t g_v   [MROWS * D_SZ / 2];
__device__ uint32_t g_attnp[MROWS * D_SZ / 2];
__device__ float    g_h   [MROWS * D_SZ];
__device__ uint32_t g_mlpp[(size_t)MROWS * F_SZ / 2];
__device__ uint32_t g_wqp [D_SZ * D_SZ / 2];
__device__ uint32_t g_wkp [D_SZ * D_SZ / 2];
__device__ uint32_t g_wvp [D_SZ * D_SZ / 2];
__device__ uint32_t g_wop [D_SZ * D_SZ / 2];
__device__ uint32_t g_winp[(size_t)F_SZ * D_SZ / 2];
__device__ uint32_t g_woutp[(size_t)D_SZ * F_SZ / 2];

// ==================== helpers ====================
__device__ __forceinline__ uint32_t h2u(float lo, float hi) {
    __half2 h = __floats2half2_rn(lo, hi);
    return *(uint32_t*)&h;
}
__device__ __forceinline__ float2 u2f(uint32_t u) {
    return __half22float2(*(__half2*)&u);
}
__device__ __forceinline__ uint32_t smem_u32(const void* p) {
    uint32_t a;
    asm("{ .reg .u64 t; cvta.to.shared.u64 t, %1; cvt.u32.u64 %0, t; }" : "=r"(a) : "l"(p));
    return a;
}
__device__ __forceinline__ void cp16(uint32_t saddr, const void* g) {
    asm volatile("cp.async.cg.shared.global [%0], [%1], 16;" :: "r"(saddr), "l"(g) : "memory");
}
__device__ __forceinline__ void mma_f16(float* d, const uint32_t* a, const uint32_t* b) {
    asm volatile(
        "mma.sync.aligned.m16n8k16.row.col.f32.f16.f16.f32 "
        "{%0,%1,%2,%3}, {%4,%5,%6,%7}, {%8,%9}, {%0,%1,%2,%3};"
        : "+f"(d[0]), "+f"(d[1]), "+f"(d[2]), "+f"(d[3])
        : "r"(a[0]), "r"(a[1]), "r"(a[2]), "r"(a[3]), "r"(b[0]), "r"(b[1]));
}
__device__ __forceinline__ void ldsm_t4(uint32_t* r, uint32_t a) {
    asm volatile("ldmatrix.sync.aligned.m8n8.x4.trans.shared.b16 {%0,%1,%2,%3}, [%4];"
        : "=r"(r[0]), "=r"(r[1]), "=r"(r[2]), "=r"(r[3]) : "r"(a));
}
__device__ __forceinline__ float gelu_exact(float x) {
    return 0.5f * x * (1.f + erff(x * 0.7071067811865476f));
}

// fp16 A-perm u32 index for the half2 pair (col even) of element (row, col).
// Chunk (mt, kt) = 2048 u32: [s(2)][ma(8)][lane(32)][reg(4)].
__device__ __forceinline__ size_t hperm_u32(int row, int col, int Kdim) {
    const int mt = row >> 7, kt = col >> 5;
    const int s = (col >> 4) & 1, ma = (row >> 4) & 7;
    const int rr = row & 15, cc = col & 15;
    const int lane = (rr & 7) * 4 + ((cc >> 1) & 3);
    const int reg = (rr >> 3) + 2 * ((cc >> 3) & 1);
    return ((size_t)(mt * (Kdim >> 5) + kt) * 2048) + (((s * 8 + ma) * 32 + lane) << 2) + reg;
}

// ==================== fused weight permute (all 6 weights, one launch) ====
__global__ void permute_all(
    const float* __restrict__ Wq, const float* __restrict__ Wk,
    const float* __restrict__ Wv, const float* __restrict__ Wo,
    const float* __restrict__ Win, const float* __restrict__ Wout,
    uint32_t* __restrict__ wqp, uint32_t* __restrict__ wkp,
    uint32_t* __restrict__ wvp, uint32_t* __restrict__ wop,
    uint32_t* __restrict__ winp, uint32_t* __restrict__ woutp) {
    const int bid = blockIdx.x;
    const float* W; uint32_t* Wp; int K, b0;
    if (bid < 8192) {
        const int sel = bid >> 11;
        b0 = sel << 11;
        K = D_SZ;
        W  = (sel == 0) ? Wq  : (sel == 1) ? Wk  : (sel == 2) ? Wv  : Wo;
        Wp = (sel == 0) ? wqp : (sel == 1) ? wkp : (sel == 2) ? wvp : wop;
    } else if (bid < 16384) {
        b0 = 8192;  K = D_SZ; W = Win;  Wp = winp;
    } else {
        b0 = 16384; K = F_SZ; W = Wout; Wp = woutp;
    }
    const int u = (bid - b0) * 256 + threadIdx.x;
    const int chunk = u >> 10, o = u & 1023;
    const int ktn = K >> 5;
    const int nt = chunk / ktn, kt = chunk % ktn;
    const int lane = o & 31, pair = (o >> 5) & 15, s = o >> 9;
    const int n_lo = nt * 256 + pair * 16 + (lane >> 2);
    const int kb = kt * 32 + s * 16 + (lane & 3) * 2;
    float2 a0 = *(const float2*)(W + (size_t)n_lo * K + kb);
    float2 a1 = *(const float2*)(W + (size_t)n_lo * K + kb + 8);
    float2 a2 = *(const float2*)(W + (size_t)(n_lo + 8) * K + kb);
    float2 a3 = *(const float2*)(W + (size_t)(n_lo + 8) * K + kb + 8);
    uint4 r;
    r.x = h2u(a0.x, a0.y);
    r.y = h2u(a1.x, a1.y);
    r.z = h2u(a2.x, a2.y);
    r.w = h2u(a3.x, a3.y);
    ((uint4*)Wp)[u] = r;
}

// ==================== cp.async fp16 GEMM, BK=128, 2 stages (unchanged) ====
#define STAGE_U32 24576
#define GEMMCP_SMEM (2 * STAGE_U32 * 4)   // 196608

template <int EPI, int OUT>
__device__ __forceinline__ void gemm_cp_body(
    const uint32_t* __restrict__ Ap, const uint32_t* __restrict__ Wp,
    const float* __restrict__ R, void* __restrict__ Cv,
    int N, int K, int mt, int nt, uint32_t* sm) {
    const uint32_t sb = smem_u32(sm);
    const int tid = threadIdx.x, lane = tid & 31, wid = tid >> 5;
    const int wm = wid >> 2, wn = wid & 3;
    const int NT32 = K >> 5;
    const int NT128 = K >> 7;
    const uint4* Agc = (const uint4*)Ap + (size_t)mt * NT32 * 512;
    const uint4* Bgc = (const uint4*)Wp + (size_t)nt * NT32 * 1024;

    float acc[4][8][4];
    #pragma unroll
    for (int i = 0; i < 4; i++)
        #pragma unroll
        for (int j = 0; j < 8; j++)
            #pragma unroll
            for (int r = 0; r < 4; r++) acc[i][j][r] = 0.f;

    auto issue = [&](int kt) {
        const int st = kt & 1;
        const uint32_t sa = sb + st * STAGE_U32 * 4;
        const uint4* ag = Agc + (size_t)kt * 2048;
        const uint4* bg = Bgc + (size_t)kt * 4096;
        #pragma unroll
        for (int i = 0; i < 8; i++)
            cp16(sa + (tid + 256 * i) * 16, ag + tid + 256 * i);
        const uint32_t sbb = sa + 8192 * 4;
        #pragma unroll
        for (int i = 0; i < 16; i++)
            cp16(sbb + (tid + 256 * i) * 16, bg + tid + 256 * i);
        asm volatile("cp.async.commit_group;" ::: "memory");
    };

    issue(0);

    for (int kt = 0; kt < NT128; kt++) {
        asm volatile("cp.async.wait_group 0;" ::: "memory");
        __syncthreads();
        if (kt + 1 < NT128) issue(kt + 1);

        const uint32_t* smA = sm + (kt & 1) * STAGE_U32;
        const uint32_t* smB = smA + 8192;

        uint32_t af[2][4][4], bf[2][4][4];
        auto ldfrag = [&](int s4, int buf) {
            const int chunk = s4 >> 1, s = s4 & 1;
            const uint32_t* A = smA + chunk * 2048;
            const uint32_t* Bp = smB + chunk * 4096;
            #pragma unroll
            for (int i = 0; i < 4; i++)
                *(uint4*)af[buf][i] = *(const uint4*)(A + (((s * 8 + wm * 4 + i) * 32 + lane) << 2));
            #pragma unroll
            for (int j = 0; j < 4; j++)
                *(uint4*)bf[buf][j] = *(const uint4*)(Bp + (((s * 16 + wn * 4 + j) * 32 + lane) << 2));
        };

        ldfrag(0, 0);
        #pragma unroll
        for (int s4 = 0; s4 < 8; s4++) {
            if (s4 < 7) ldfrag(s4 + 1, (s4 + 1) & 1);
            const int cb = s4 & 1;
            #pragma unroll
            for (int i = 0; i < 4; i++)
                #pragma unroll
                for (int jj = 0; jj < 4; jj++) {
                    mma_f16(acc[i][2 * jj],     af[cb][i], bf[cb][jj]);
                    mma_f16(acc[i][2 * jj + 1], af[cb][i], bf[cb][jj] + 2);
                }
        }
    }

    const int gid = lane >> 2, tig = lane & 3;
    #pragma unroll
    for (int i = 0; i < 4; i++) {
        #pragma unroll
        for (int j = 0; j < 8; j++) {
            const int row0 = mt * 128 + wm * 64 + i * 16 + gid;
            const int col  = nt * 256 + wn * 64 + j * 8 + tig * 2;
            float2 v0 = {acc[i][j][0], acc[i][j][1]};
            float2 v1 = {acc[i][j][2], acc[i][j][3]};
            if (EPI == 2) {
                float2 q0 = *(const float2*)(R + (size_t)row0 * N + col);
                float2 q1 = *(const float2*)(R + (size_t)(row0 + 8) * N + col);
                v0.x += q0.x; v0.y += q0.y;
                v1.x += q1.x; v1.y += q1.y;
            }
            if (EPI == 1) {
                v0.x = gelu_exact(v0.x); v0.y = gelu_exact(v0.y);
                v1.x = gelu_exact(v1.x); v1.y = gelu_exact(v1.y);
            }
            if (OUT == 1) {
                uint32_t* Ch = (uint32_t*)Cv;
                Ch[hperm_u32(row0, col, N)]     = h2u(v0.x, v0.y);
                Ch[hperm_u32(row0 + 8, col, N)] = h2u(v1.x, v1.y);
            } else if (OUT == 2) {
                uint32_t* Ch = (uint32_t*)Cv;
                Ch[(size_t)row0 * (N >> 1) + (col >> 1)]       = h2u(v0.x, v0.y);
                Ch[(size_t)(row0 + 8) * (N >> 1) + (col >> 1)] = h2u(v1.x, v1.y);
            } else {
                float* C = (float*)Cv;
                *(float2*)(C + (size_t)row0 * N + col) = v0;
                *(float2*)(C + (size_t)(row0 + 8) * N + col) = v1;
            }
        }
    }
}

template <int EPI, int OUT>
__global__ void __launch_bounds__(256, 1)
gemm_cp(const uint32_t* __restrict__ Ap, const uint32_t* __restrict__ Wp,
        const float* __restrict__ R, void* __restrict__ C, int N, int K) {
    extern __shared__ uint32_t smu[];
    gemm_cp_body<EPI, OUT>(Ap, Wp, R, C, N, K, blockIdx.x, blockIdx.y, smu);
}

__global__ void __launch_bounds__(256, 1)
qkv_cp(const uint32_t* __restrict__ Ap,
       const uint32_t* __restrict__ wqp, const uint32_t* __restrict__ wkp,
       const uint32_t* __restrict__ wvp,
       uint32_t* __restrict__ q, uint32_t* __restrict__ k, uint32_t* __restrict__ v) {
    extern __shared__ uint32_t smu[];
    const int which = blockIdx.y >> 3;
    const uint32_t* Wp = (which == 0) ? wqp : (which == 1) ? wkp : wvp;
    uint32_t* C = (which == 0) ? q : (which == 1) ? k : v;
    gemm_cp_body<0, 2>(Ap, Wp, nullptr, C, D_SZ, D_SZ, blockIdx.x, blockIdx.y & 7, smu);
}

// ---------------- fused hypersphere norm + fp16 A-permute ----------------
__global__ void hnorm_perm(const float* __restrict__ x, const float* __restrict__ g,
                           uint32_t* __restrict__ Ap) {
    const int row = blockIdx.x;
    const float* xr = x + (size_t)row * D_SZ;
    float ss = 0.f;
    for (int i = threadIdx.x; i < D_SZ; i += blockDim.x) {
        float v = xr[i];
        ss += v * v;
    }
    __shared__ float red[32];
    #pragma unroll
    for (int o = 16; o; o >>= 1) ss += __shfl_xor_sync(0xffffffffu, ss, o);
    if ((threadIdx.x & 31) == 0) red[threadIdx.x >> 5] = ss;
    __syncthreads();
    if (threadIdx.x < 32) {
        float v = (threadIdx.x < (blockDim.x >> 5)) ? red[threadIdx.x] : 0.f;
        #pragma unroll
        for (int o = 16; o; o >>= 1) v += __shfl_xor_sync(0xffffffffu, v, o);
        if (threadIdx.x == 0) red[0] = v;
    }
    __syncthreads();
    const float n = sqrtf(red[0]);
    const float scale = 45.254833995939045f / (n + 1e-6f);  // sqrt(2048)
    #pragma unroll
    for (int i = 0; i < 4; i++) {
        const int col = (threadIdx.x + 256 * i) * 2;
        float2 xv = *(const float2*)(xr + col);
        float2 gv = *(const float2*)(g + col);
        Ap[hperm_u32(row, col, D_SZ)] = h2u(xv.x * scale * gv.x, xv.y * scale * gv.y);
    }
}

// ==================== Flash attention, fp16, V via ldmatrix.trans ====================
// smem (u32): sQ 8192, sK 4096, sV (row-major, 64 rows x 68 u32) 4352, sP 4096.
#define FL_SQ  0
#define FL_SK  8192
#define FL_SV  12288
#define FL_SP  16640
#define FLASH_SMEM (20736 * 4)   // 82944
#define VROW 68                  // u32 row stride (17 x 16B -> ldmatrix conflict-free)

__global__ void __launch_bounds__(256, 1)
flash_mma(const uint32_t* __restrict__ Q, const uint32_t* __restrict__ K,
          const uint32_t* __restrict__ V, const float* __restrict__ scale_p,
          uint32_t* __restrict__ O) {
    extern __shared__ uint32_t fsu[];
    uint32_t* sQ = fsu + FL_SQ;
    uint32_t* sK = fsu + FL_SK;
    uint32_t* sV = fsu + FL_SV;
    uint32_t* sP = fsu + FL_SP;

    const int qt = gridDim.x - 1 - blockIdx.x;
    const int bh = blockIdx.y;
    const int b = bh >> 4, h = bh & 15;
    const float scale = *scale_p;
    const int tid = threadIdx.x;
    const int lane = tid & 31;
    const int wid = tid >> 5;

    const size_t base2 = (size_t)b * S_SZ * (D_SZ / 2) + (size_t)h * (HD / 2);

    // ---- stage Q: fused row-norm (2 lanes/row) + qk scale, fp16 A-frag ----
    {
        const int r = tid >> 1;
        const int ma = r >> 4, rr = r & 15;
        const uint4* qrow4 = (const uint4*)(Q + base2 + (size_t)(qt * 128 + r) * (D_SZ / 2));
        float ssq = 0.f;
        #pragma unroll
        for (int i = 0; i < 8; i++) {
            uint4 w = qrow4[(tid & 1) * 8 + i];
            float2 f0 = u2f(w.x), f1 = u2f(w.y), f2 = u2f(w.z), f3 = u2f(w.w);
            ssq += f0.x * f0.x + f0.y * f0.y + f1.x * f1.x + f1.y * f1.y
                 + f2.x * f2.x + f2.y * f2.y + f3.x * f3.x + f3.y * f3.y;
        }
        ssq += __shfl_xor_sync(0xffffffffu, ssq, 1);
        const float qs = scale / (sqrtf(ssq) + 1e-6f);
        #pragma unroll
        for (int i = 0; i < 8; i++) {
            uint4 w = qrow4[(tid & 1) * 8 + i];
            const int cb = (tid & 1) * 64 + 8 * i;
            const int chunk = cb >> 4;
            const int reg = (rr >> 3) + 2 * ((cb >> 3) & 1);
            uint32_t* dst = sQ + (((chunk * 8 + ma) * 32 + (rr & 7) * 4) << 2) + reg;
            float2 f0 = u2f(w.x), f1 = u2f(w.y), f2 = u2f(w.z), f3 = u2f(w.w);
            dst[0]  = h2u(f0.x * qs, f0.y * qs);
            dst[4]  = h2u(f1.x * qs, f1.y * qs);
            dst[8]  = h2u(f2.x * qs, f2.y * qs);
            dst[12] = h2u(f3.x * qs, f3.y * qs);
        }
    }

    float o[16][4];
    #pragma unroll
    for (int i = 0; i < 16; i++)
        #pragma unroll
        for (int r = 0; r < 4; r++) o[i][r] = 0.f;
    float m_run[2] = {-INFINITY, -INFINITY};
    float l_run[2] = {0.f, 0.f};

    const int n0 = tid >> 2;
    uint4 kreg[4], vreg[4];
    auto ldkv = [&](int kt) {
        const uint4* kr = (const uint4*)(K + base2 + (size_t)(kt * 64 + n0) * (D_SZ / 2));
        const uint4* vr = (const uint4*)(V + base2 + (size_t)(kt * 64 + n0) * (D_SZ / 2));
        #pragma unroll
        for (int i = 0; i < 4; i++) {
            kreg[i] = kr[(tid & 3) + 4 * i];
            vreg[i] = vr[(tid & 3) + 4 * i];
        }
    };

    // ldmatrix per-lane address component (row-within-16 and d-half select)
    const uint32_t svb = smem_u32(sV);
    const int rb16 = ((lane >> 3) & 1) * 8 + (lane & 7);   // row within 16-key block
    const int dclu = (lane >> 4) * 4;                      // +8 d (=4 u32) for hi half

    const int NKT = 2 * qt + 2;
    ldkv(0);
    for (int kt = 0; kt < NKT; kt++) {
        __syncthreads();   // previous iteration done reading sK/sV
        // ---- stage K (fused row-norm from regs) and V (row-major) ----
        {
            float ssk = 0.f;
            #pragma unroll
            for (int i = 0; i < 4; i++) {
                float2 f0 = u2f(kreg[i].x), f1 = u2f(kreg[i].y),
                       f2 = u2f(kreg[i].z), f3 = u2f(kreg[i].w);
                ssk += f0.x * f0.x + f0.y * f0.y + f1.x * f1.x + f1.y * f1.y
                     + f2.x * f2.x + f2.y * f2.y + f3.x * f3.x + f3.y * f3.y;
            }
            ssk += __shfl_xor_sync(0xffffffffu, ssk, 1);
            ssk += __shfl_xor_sync(0xffffffffu, ssk, 2);
            const float ks = 1.f / (sqrtf(ssk) + 1e-6f);
            #pragma unroll
            for (int i = 0; i < 4; i++) {
                const int u = (tid & 3) + 4 * i;
                {
                    uint4 w = kreg[i];
                    const int chunk = u >> 1;
                    const int pair = n0 >> 4;
                    const int reg = ((n0 >> 3) & 1) * 2 + (u & 1);
                    uint32_t* dk = sK + (((chunk * 4 + pair) * 32 + (n0 & 7) * 4) << 2) + reg;
                    float2 f0 = u2f(w.x), f1 = u2f(w.y), f2 = u2f(w.z), f3 = u2f(w.w);
                    dk[0]  = h2u(f0.x * ks, f0.y * ks);
                    dk[4]  = h2u(f1.x * ks, f1.y * ks);
                    dk[8]  = h2u(f2.x * ks, f2.y * ks);
                    dk[12] = h2u(f3.x * ks, f3.y * ks);
                }
                *(uint4*)(sV + n0 * VROW + u * 4) = vreg[i];
            }
        }
        // prefetch next tile's K/V (latency hides behind mma below)
        if (kt + 1 < NKT) ldkv(kt + 1);
        __syncthreads();

        // ---- S = Q @ K^T ----
        float sacc[8][4];
        #pragma unroll
        for (int j = 0; j < 8; j++)
            #pragma unroll
            for (int r = 0; r < 4; r++) sacc[j][r] = 0.f;
        #pragma unroll
        for (int c = 0; c < 8; c++) {
            uint32_t af[4];
            *(uint4*)af = *(const uint4*)(sQ + (((c * 8 + wid) * 32 + lane) << 2));
            #pragma unroll
            for (int j2 = 0; j2 < 4; j2++) {
                uint32_t bf[4];
                *(uint4*)bf = *(const uint4*)(sK + (((c * 4 + j2) * 32 + lane) << 2));
                mma_f16(sacc[2 * j2],     af, bf);
                mma_f16(sacc[2 * j2 + 1], af, bf + 2);
            }
        }

        if (kt >= 2 * qt) {
            const int rbase = qt * 128 + wid * 16 + (lane >> 2);
            const int cbase = kt * 64 + 2 * (lane & 3);
            #pragma unroll
            for (int j = 0; j < 8; j++)
                #pragma unroll
                for (int r = 0; r < 4; r++) {
                    const int row = rbase + ((r >> 1) << 3);
                    const int col = cbase + j * 8 + (r & 1);
                    if (col > row) sacc[j][r] = -INFINITY;
                }
        }

        #pragma unroll
        for (int hh = 0; hh < 2; hh++) {
            float mt = -INFINITY;
            #pragma unroll
            for (int j = 0; j < 8; j++)
                mt = fmaxf(mt, fmaxf(sacc[j][2 * hh], sacc[j][2 * hh + 1]));
            mt = fmaxf(mt, __shfl_xor_sync(0xffffffffu, mt, 1));
            mt = fmaxf(mt, __shfl_xor_sync(0xffffffffu, mt, 2));
            const bool skip = (mt == -INFINITY);
            const float mold = m_run[hh];
            const float mnew = skip ? mold : fmaxf(mold, mt);
            const float msafe = (mnew == -INFINITY) ? 0.f : mnew;
            const float alpha = skip ? 1.f : __expf(mold - mnew);
            float sum = 0.f;
            #pragma unroll
            for (int j = 0; j < 8; j++) {
                float p0 = __expf(sacc[j][2 * hh]     - msafe);
                float p1 = __expf(sacc[j][2 * hh + 1] - msafe);
                sacc[j][2 * hh]     = p0;
                sacc[j][2 * hh + 1] = p1;
                sum += p0 + p1;
            }
            sum += __shfl_xor_sync(0xffffffffu, sum, 1);
            sum += __shfl_xor_sync(0xffffffffu, sum, 2);
            l_run[hh] = l_run[hh] * alpha + sum;
            m_run[hh] = mnew;
            #pragma unroll
            for (int j = 0; j < 16; j++) {
                o[j][2 * hh]     *= alpha;
                o[j][2 * hh + 1] *= alpha;
            }
        }

        __syncwarp();
        {
            const int rlow = lane >> 2, qq = lane & 3;
            #pragma unroll
            for (int j = 0; j < 8; j++) {
                #pragma unroll
                for (int hh = 0; hh < 2; hh++) {
                    const int lt = rlow * 4 + qq;
                    const int rt = hh + 2 * (j & 1);
                    sP[((((j >> 1) * 8 + wid) * 32 + lt) << 2) + rt] =
                        h2u(sacc[j][2 * hh], sacc[j][2 * hh + 1]);
                }
            }
        }
        __syncwarp();

        // ---- O += P @ V  (V fragments via ldmatrix.trans) ----
        #pragma unroll
        for (int c = 0; c < 4; c++) {
            uint32_t af[4];
            *(uint4*)af = *(const uint4*)(sP + (((c * 8 + wid) * 32 + lane) << 2));
            #pragma unroll
            for (int jp = 0; jp < 8; jp++) {
                uint32_t m[4];
                ldsm_t4(m, svb + (((16 * c + rb16) * VROW) + 8 * jp + dclu) * 4);
                mma_f16(o[2 * jp],     af, m);
                mma_f16(o[2 * jp + 1], af, m + 2);
            }
        }
    }

    const float il0 = 1.f / l_run[0];
    const float il1 = 1.f / l_run[1];
    const int grow = b * S_SZ + qt * 128 + wid * 16 + (lane >> 2);
    #pragma unroll
    for (int j = 0; j < 16; j++) {
        const int col = h * HD + j * 8 + 2 * (lane & 3);
        O[hperm_u32(grow, col, D_SZ)]     = h2u(o[j][0] * il0, o[j][1] * il0);
        O[hperm_u32(grow + 8, col, D_SZ)] = h2u(o[j][2] * il1, o[j][3] * il1);
    }
}

// ---------------- driver ----------------
extern "C" void kernel_launch(void* const* d_in, const int* in_sizes, int n_in,
                              void* d_out, int out_size) {
    const float* hs    = (const float*)d_in[0];
    const float* Wq    = (const float*)d_in[1];
    const float* Wk    = (const float*)d_in[2];
    const float* Wv    = (const float*)d_in[3];
    const float* Wo    = (const float*)d_in[4];
    const float* Win   = (const float*)d_in[5];
    const float* Wout  = (const float*)d_in[6];
    const float* qkf   = (const float*)d_in[7];
    const float* gattn = (const float*)d_in[8];
    const float* gmlp  = (const float*)d_in[9];
    float* out = (float*)d_out;

    uint32_t *xnp, *q, *k, *v, *attnp, *mlpp, *wqp, *wkp, *wvp, *wop, *winp, *woutp;
    float *h;
    cudaGetSymbolAddress((void**)&xnp,   g_xnp);
    cudaGetSymbolAddress((void**)&q,     g_q);
    cudaGetSymbolAddress((void**)&k,     g_k);
    cudaGetSymbolAddress((void**)&v,     g_v);
    cudaGetSymbolAddress((void**)&attnp, g_attnp);
    cudaGetSymbolAddress((void**)&h,     g_h);
    cudaGetSymbolAddress((void**)&mlpp,  g_mlpp);
    cudaGetSymbolAddress((void**)&wqp,   g_wqp);
    cudaGetSymbolAddress((void**)&wkp,   g_wkp);
    cudaGetSymbolAddress((void**)&wvp,   g_wvp);
    cudaGetSymbolAddress((void**)&wop,   g_wop);
    cudaGetSymbolAddress((void**)&winp,  g_winp);
    cudaGetSymbolAddress((void**)&woutp, g_woutp);

    cudaFuncSetAttribute(flash_mma, cudaFuncAttributeMaxDynamicSharedMemorySize, FLASH_SMEM);
    cudaFuncSetAttribute(qkv_cp, cudaFuncAttributeMaxDynamicSharedMemorySize, GEMMCP_SMEM);
    cudaFuncSetAttribute(gemm_cp<1, 1>, cudaFuncAttributeMaxDynamicSharedMemorySize, GEMMCP_SMEM);
    cudaFuncSetAttribute(gemm_cp<2, 0>, cudaFuncAttributeMaxDynamicSharedMemorySize, GEMMCP_SMEM);

    // 0) permute all weights to fp16 fragment order (one launch)
    permute_all<<<24576, 256>>>(Wq, Wk, Wv, Wo, Win, Wout,
                                wqp, wkp, wvp, wop, winp, woutp);

    // 1) pre-attn hypersphere norm fused with fp16 A-permute
    hnorm_perm<<<MROWS, 256>>>(hs, gattn, xnp);

    // 2) fused QKV projection -> fp16 row-major q/k/v
    qkv_cp<<<dim3(MROWS / 128, 24), 256, GEMMCP_SMEM>>>(xnp, wqp, wkp, wvp, q, k, v);

    // 3) causal attention -> attn in fp16 A-perm layout
    flash_mma<<<dim3(S_SZ / 128, B_SZ * H_SZ), 256, FLASH_SMEM>>>(q, k, v, qkf, attnp);

    // 4) output projection + residual -> h (f32)
    gemm_cp<2, 0><<<dim3(32, 8), 256, GEMMCP_SMEM>>>(attnp, wop, hs, h, D_SZ, D_SZ);

    // 5) pre-MLP hypersphere norm fused with fp16 A-permute
    hnorm_perm<<<MROWS, 256>>>(h, gmlp, xnp);

    // 6) MLP in + GELU -> mlp in fp16 A-perm layout
    gemm_cp<1, 1><<<dim3(32, 32), 256, GEMMCP_SMEM>>>(xnp, winp, nullptr, mlpp, F_SZ, D_SZ);

    // 7) MLP out + residual -> d_out (f32)
    gemm_cp<2, 0><<<dim3(32, 8), 256, GEMMCP_SMEM>>>(mlpp, woutp, h, out, D_SZ, F_SZ);
}